// round 11
// baseline (speedup 1.0000x reference)
#include <cuda_runtime.h>
#include <cuda_bf16.h>
#include <cstdint>

#define B_SZ   2
#define T_SZ   2048
#define DIM_   2048
#define NHEAD  16
#define KVHEAD 4
#define HDIM   128
#define MROWS  (B_SZ * T_SZ)        // 4096
#define KVDIM  (KVHEAD * HDIM)      // 512
#define GK     2048

// ================= scratch (device globals; no allocations allowed) =========
__device__ float g_q[(size_t)MROWS * DIM_];
__device__ float g_k[(size_t)MROWS * KVDIM];
__device__ float g_v[(size_t)MROWS * KVDIM];
__device__ float g_att[(size_t)MROWS * DIM_];

__device__ __align__(16) __nv_bfloat16 g_xh[(size_t)MROWS * DIM_];
__device__ __align__(16) __nv_bfloat16 g_xl[(size_t)MROWS * DIM_];
__device__ __align__(16) __nv_bfloat16 g_wqth[(size_t)DIM_ * DIM_];   // [N,K]
__device__ __align__(16) __nv_bfloat16 g_wqtl[(size_t)DIM_ * DIM_];
__device__ __align__(16) __nv_bfloat16 g_wkth[(size_t)KVDIM * DIM_];
__device__ __align__(16) __nv_bfloat16 g_wktl[(size_t)KVDIM * DIM_];
__device__ __align__(16) __nv_bfloat16 g_wvth[(size_t)KVDIM * DIM_];
__device__ __align__(16) __nv_bfloat16 g_wvtl[(size_t)KVDIM * DIM_];
__device__ __align__(16) __nv_bfloat16 g_woth[(size_t)DIM_ * DIM_];
__device__ __align__(16) __nv_bfloat16 g_wotl[(size_t)DIM_ * DIM_];
__device__ __align__(16) __nv_bfloat16 g_ath[(size_t)MROWS * DIM_];
__device__ __align__(16) __nv_bfloat16 g_atl[(size_t)MROWS * DIM_];
// flash inputs (bf16 hi/lo)
__device__ __align__(16) __nv_bfloat16 g_qh[(size_t)MROWS * DIM_];
__device__ __align__(16) __nv_bfloat16 g_ql[(size_t)MROWS * DIM_];
__device__ __align__(16) __nv_bfloat16 g_kh[(size_t)MROWS * KVDIM];
__device__ __align__(16) __nv_bfloat16 g_kl[(size_t)MROWS * KVDIM];
__device__ __align__(16) __nv_bfloat16 g_vth[(size_t)B_SZ * KVDIM * T_SZ]; // [b*512+c][t]
__device__ __align__(16) __nv_bfloat16 g_vtl[(size_t)B_SZ * KVDIM * T_SZ];

// ================= helpers ===================================================
__device__ __forceinline__ uint32_t smem_u32(const void* p) {
    uint32_t a;
    asm("{ .reg .u64 t; cvta.to.shared.u64 t, %1; cvt.u32.u64 %0, t; }" : "=r"(a) : "l"(p));
    return a;
}
__device__ __forceinline__ void ldsm4(uint32_t (&r)[4], uint32_t addr) {
    asm volatile("ldmatrix.sync.aligned.m8n8.x4.shared.b16 {%0,%1,%2,%3}, [%4];"
                 : "=r"(r[0]), "=r"(r[1]), "=r"(r[2]), "=r"(r[3]) : "r"(addr));
}
__device__ __forceinline__ void mma16816(float (&d)[4], const uint32_t (&a)[4],
                                         uint32_t b0, uint32_t b1) {
    asm volatile("mma.sync.aligned.m16n8k16.row.col.f32.bf16.bf16.f32 "
                 "{%0,%1,%2,%3}, {%4,%5,%6,%7}, {%8,%9}, {%0,%1,%2,%3};"
                 : "+f"(d[0]), "+f"(d[1]), "+f"(d[2]), "+f"(d[3])
                 : "r"(a[0]), "r"(a[1]), "r"(a[2]), "r"(a[3]), "r"(b0), "r"(b1));
}
#define CP_ASYNC16(sm, gm) \
    asm volatile("cp.async.cg.shared.global [%0], [%1], 16;" :: "r"(sm), "l"(gm) : "memory")
#define CP_COMMIT() asm volatile("cp.async.commit_group;" ::: "memory")
#define CP_WAIT(n)  asm volatile("cp.async.wait_group %0;" :: "n"(n) : "memory")

__device__ __forceinline__ void split2(float a, float b, uint32_t& h, uint32_t& l) {
    __nv_bfloat16 ha = __float2bfloat16(a), hb = __float2bfloat16(b);
    float ra = a - __bfloat162float(ha), rb = b - __bfloat162float(hb);
    __nv_bfloat162 hp; hp.x = ha; hp.y = hb;
    __nv_bfloat162 lp; lp.x = __float2bfloat16(ra); lp.y = __float2bfloat16(rb);
    h = *reinterpret_cast<uint32_t*>(&hp);
    l = *reinterpret_cast<uint32_t*>(&lp);
}

// ================= split / transpose-split conversion kernels ================
__global__ void split_kernel(const float* __restrict__ in, __nv_bfloat16* __restrict__ hi,
                             __nv_bfloat16* __restrict__ lo, int n4, float scale)
{
    int i = blockIdx.x * 256 + threadIdx.x;
    if (i >= n4) return;
    float4 v = ((const float4*)in)[i];
    float f[4] = {v.x * scale, v.y * scale, v.z * scale, v.w * scale};
    uint32_t h0, l0, h1, l1;
    split2(f[0], f[1], h0, l0);
    split2(f[2], f[3], h1, l1);
    ((uint32_t*)hi)[2 * i]     = h0;
    ((uint32_t*)hi)[2 * i + 1] = h1;
    ((uint32_t*)lo)[2 * i]     = l0;
    ((uint32_t*)lo)[2 * i + 1] = l1;
}

// in: [R,C] fp32 row-major  ->  out hi/lo: [C,R] bf16 row-major (transposed)
__global__ void tsplit_kernel(const float* __restrict__ in, __nv_bfloat16* __restrict__ hi,
                              __nv_bfloat16* __restrict__ lo, int R, int C)
{
    __shared__ float tile[32][33];
    const int bx = blockIdx.x << 5;
    const int by = blockIdx.y << 5;
    const int tx = threadIdx.x & 31, ty = threadIdx.x >> 5;
    #pragma unroll
    for (int r = ty; r < 32; r += 8)
        tile[r][tx] = in[(size_t)(by + r) * C + bx + tx];
    __syncthreads();
    #pragma unroll
    for (int r = ty; r < 32; r += 8) {
        float v = tile[tx][r];
        __nv_bfloat16 h = __float2bfloat16(v);
        __nv_bfloat16 l = __float2bfloat16(v - __bfloat162float(h));
        size_t o = (size_t)(bx + r) * R + by + tx;
        hi[o] = h; lo[o] = l;
    }
}

// g_v [b*T + t][c] fp32 -> g_vt[(b*512 + c)][t] bf16 hi/lo (per-batch transpose)
__global__ void vtsplit_kernel(const float* __restrict__ in, __nv_bfloat16* __restrict__ hi,
                               __nv_bfloat16* __restrict__ lo)
{
    __shared__ float tile[32][33];
    const int t0 = blockIdx.x << 5;
    const int c0 = blockIdx.y << 5;
    const int b  = blockIdx.z;
    const int tx = threadIdx.x & 31, ty = threadIdx.x >> 5;
    #pragma unroll
    for (int r = ty; r < 32; r += 8)
        tile[r][tx] = in[(size_t)(b * T_SZ + t0 + r) * KVDIM + c0 + tx];
    __syncthreads();
    #pragma unroll
    for (int r = ty; r < 32; r += 8) {
        float v = tile[tx][r];
        __nv_bfloat16 h = __float2bfloat16(v);
        __nv_bfloat16 l = __float2bfloat16(v - __bfloat162float(h));
        size_t o = (size_t)(b * KVDIM + c0 + r) * T_SZ + t0 + tx;
        hi[o] = h; lo[o] = l;
    }
}

// ================= split-bf16 HMMA GEMM (unchanged from R8-passing) ==========
#define BK        32
#define NKB       (GK / BK)
#define TPITCH    80
#define TILE_BY   (128 * TPITCH)
#define SOFF_AH   0
#define SOFF_AL   (1 * TILE_BY)
#define SOFF_BH   (2 * TILE_BY)
#define SOFF_BL   (3 * TILE_BY)
#define STAGE_BY  (4 * TILE_BY)
#define GEMM_SMEM (2 * STAGE_BY)

__device__ __forceinline__ void load_stage(
    const __nv_bfloat16* __restrict__ Abh, const __nv_bfloat16* __restrict__ Abl,
    const __nv_bfloat16* __restrict__ Bbh, const __nv_bfloat16* __restrict__ Bbl,
    int kof, uint32_t sbuf, int tid)
{
    #pragma unroll
    for (int i = 0; i < 2; i++) {
        const int c   = tid + (i << 8);
        const int row = c >> 2, q = c & 3;
        const size_t   go = (size_t)row * GK + kof + q * 8;
        const uint32_t so = row * TPITCH + q * 16;
        CP_ASYNC16(sbuf + SOFF_AH + so, Abh + go);
        CP_ASYNC16(sbuf + SOFF_AL + so, Abl + go);
        CP_ASYNC16(sbuf + SOFF_BH + so, Bbh + go);
        CP_ASYNC16(sbuf + SOFF_BL + so, Bbl + go);
    }
}

template<bool ROPE>
__global__ __launch_bounds__(256, 1)
void mma_gemm_kernel(const __nv_bfloat16* __restrict__ Ah, const __nv_bfloat16* __restrict__ Al,
                     const __nv_bfloat16* __restrict__ Bh, const __nv_bfloat16* __restrict__ Bl,
                     float* __restrict__ C, int N,
                     const float* __restrict__ fc, const float* __restrict__ fs)
{
    extern __shared__ char smem[];
    const uint32_t sbase = smem_u32(smem);
    const int tid  = threadIdx.x;
    const int lane = tid & 31, wid = tid >> 5;
    const int wm   = wid & 3,  wn  = wid >> 2;
    const int row0 = blockIdx.y << 7, col0 = blockIdx.x << 7;

    const __nv_bfloat16* Abh = Ah + (size_t)row0 * GK;
    const __nv_bfloat16* Abl = Al + (size_t)row0 * GK;
    const __nv_bfloat16* Bbh = Bh + (size_t)col0 * GK;
    const __nv_bfloat16* Bbl = Bl + (size_t)col0 * GK;

    float acc[2][8][4];
    #pragma unroll
    for (int mi = 0; mi < 2; mi++)
        #pragma unroll
        for (int ni = 0; ni < 8; ni++)
            #pragma unroll
            for (int e = 0; e < 4; e++) acc[mi][ni][e] = 0.f;

    const uint32_t a_row = wm * 32 + (lane & 15);
    const uint32_t a_col = (lane >> 4) << 4;
    const uint32_t b_rowb = wn * 64 + (lane & 7) + ((lane >> 4) << 3);
    const uint32_t b_col  = ((lane >> 3) & 1) << 4;

    load_stage(Abh, Abl, Bbh, Bbl, 0, sbase, tid);
    CP_COMMIT();

    for (int blk = 0; blk < NKB; blk++) {
        const uint32_t buf = sbase + (uint32_t)(blk & 1) * STAGE_BY;
        if (blk + 1 < NKB) {
            load_stage(Abh, Abl, Bbh, Bbl, (blk + 1) * BK,
                       sbase + (uint32_t)((blk + 1) & 1) * STAGE_BY, tid);
            CP_COMMIT();
            CP_WAIT(1);
        } else {
            CP_WAIT(0);
        }
        __syncthreads();

        #pragma unroll
        for (int ks = 0; ks < 2; ks++) {
            const uint32_t koff = ks * 32;
            uint32_t ah[2][4], al[2][4];
            #pragma unroll
            for (int mi = 0; mi < 2; mi++) {
                const uint32_t aaddr = buf + SOFF_AH + (a_row + mi * 16) * TPITCH + koff + a_col;
                ldsm4(ah[mi], aaddr);
                ldsm4(al[mi], aaddr + (SOFF_AL - SOFF_AH));
            }
            uint32_t bh[4][4], bl[4][4];
            #pragma unroll
            for (int nq = 0; nq < 4; nq++) {
                const uint32_t baddr = buf + SOFF_BH + (b_rowb + nq * 16) * TPITCH + koff + b_col;
                ldsm4(bh[nq], baddr);
                ldsm4(bl[nq], baddr + (SOFF_BL - SOFF_BH));
            }
            #pragma unroll
            for (int mi = 0; mi < 2; mi++)
                #pragma unroll
                for (int nq = 0; nq < 4; nq++)
                    #pragma unroll
                    for (int hf = 0; hf < 2; hf++) {
                        const int ni = nq * 2 + hf;
                        const uint32_t b0h = bh[nq][hf * 2], b1h = bh[nq][hf * 2 + 1];
                        const uint32_t b0l = bl[nq][hf * 2], b1l = bl[nq][hf * 2 + 1];
                        mma16816(acc[mi][ni], ah[mi], b0h, b1h);
                        mma16816(acc[mi][ni], ah[mi], b0l, b1l);
                        mma16816(acc[mi][ni], al[mi], b0h, b1h);
                    }
        }
        __syncthreads();
    }

    const int lr = lane >> 2;
    const int lc = (lane & 3) << 1;
    #pragma unroll
    for (int mi = 0; mi < 2; mi++) {
        #pragma unroll
        for (int ni = 0; ni < 8; ni++) {
            float* d = acc[mi][ni];
            const int r0  = row0 + wm * 32 + mi * 16 + lr;
            const int r1  = r0 + 8;
            const int col = col0 + wn * 64 + ni * 8 + lc;
            if (ROPE) {
                const int p = (col & (HDIM - 1)) >> 1;
                {
                    const int t = r0 & (T_SZ - 1);
                    const float cz = fc[t * (HDIM / 2) + p];
                    const float sz = fs[t * (HDIM / 2) + p];
                    const float xr = d[0], xi = d[1];
                    d[0] = xr * cz - xi * sz;
                    d[1] = xr * sz + xi * cz;
                }
                {
                    const int t = r1 & (T_SZ - 1);
                    const float cz = fc[t * (HDIM / 2) + p];
                    const float sz = fs[t * (HDIM / 2) + p];
                    const float xr = d[2], xi = d[3];
                    d[2] = xr * cz - xi * sz;
                    d[3] = xr * sz + xi * cz;
                }
            }
            *(float2*)(C + (size_t)r0 * N + col) = make_float2(d[0], d[1]);
            *(float2*)(C + (size_t)r1 * N + col) = make_float2(d[2], d[3]);
        }
    }
}

// ================= tensor-core flash attention ===============================
// q-tile 128 (8 warps x 16 rows), k-tile 64, 3-pass hi/lo mma for S and PV.
// Per-row softmax stats entirely in registers (row owned by one warp).
#define QPITCH 272                    // 128 bf16 = 256B + 16 pad
#define VPITCH 144                    // 64 bf16 = 128B + 16 pad
#define SM_QH  0
#define SM_QL  (128 * QPITCH)         // 34816
#define SM_KV  (2 * 128 * QPITCH)     // 69632
#define OFF_KH 0
#define OFF_KL (64 * QPITCH)          // 17408
#define OFF_VH (2 * 64 * QPITCH)      // 34816
#define OFF_VL (OFF_VH + 128 * VPITCH) // 53248
#define KVBUF  (OFF_VL + 128 * VPITCH) // 71680
#define FLASH2_SMEM (SM_KV + 2 * KVBUF) // 212992

__device__ __forceinline__ void flash_load_kv(
    const __nv_bfloat16* __restrict__ Kh, const __nv_bfloat16* __restrict__ Kl,
    const __nv_bfloat16* __restrict__ Vth, const __nv_bfloat16* __restrict__ Vtl,
    int b, int kvh, int kt, uint32_t buf, int tid)
{
    const char* gkh = (const char*)(Kh + (size_t)(b * T_SZ + kt * 64) * KVDIM + kvh * HDIM);
    const char* gkl = (const char*)(Kl + (size_t)(b * T_SZ + kt * 64) * KVDIM + kvh * HDIM);
    #pragma unroll
    for (int s = 0; s < 4; s++) {
        const int u = tid + s * 256;           // 0..1023
        const int r = u >> 4, c = (u & 15) << 4;
        CP_ASYNC16(buf + OFF_KH + r * QPITCH + c, gkh + (size_t)r * (KVDIM * 2) + c);
        CP_ASYNC16(buf + OFF_KL + r * QPITCH + c, gkl + (size_t)r * (KVDIM * 2) + c);
    }
    const char* gvh = (const char*)(Vth + ((size_t)(b * KVHEAD + kvh) * HDIM) * T_SZ + kt * 64);
    const char* gvl = (const char*)(Vtl + ((size_t)(b * KVHEAD + kvh) * HDIM) * T_SZ + kt * 64);
    #pragma unroll
    for (int s = 0; s < 4; s++) {
        const int u = tid + s * 256;
        const int r = u >> 3, c = (u & 7) << 4;
        CP_ASYNC16(buf + OFF_VH + r * VPITCH + c, gvh + (size_t)r * (T_SZ * 2) + c);
        CP_ASYNC16(buf + OFF_VL + r * VPITCH + c, gvl + (size_t)r * (T_SZ * 2) + c);
    }
}

__global__ __launch_bounds__(256, 1)
void flash_mma_kernel(const __nv_bfloat16* __restrict__ Qh, const __nv_bfloat16* __restrict__ Ql,
                      const __nv_bfloat16* __restrict__ Kh, const __nv_bfloat16* __restrict__ Kl,
                      const __nv_bfloat16* __restrict__ Vth, const __nv_bfloat16* __restrict__ Vtl,
                      float* __restrict__ Og)
{
    extern __shared__ char smem[];
    const uint32_t sbase = smem_u32(smem);
    const int tid = threadIdx.x, lane = tid & 31, w = tid >> 5;
    const int qt = (int)gridDim.x - 1 - (int)blockIdx.x;   // heavy tiles first
    const int bh = blockIdx.y, b = bh >> 4, h = bh & 15, kvh = h >> 2;
    const int qrow0 = b * T_SZ + qt * 128;
    const int nkt = 2 * qt + 2;

    // prologue: stage Q (hi/lo) + KV tile 0
    {
        const char* gqh = (const char*)(Qh + (size_t)qrow0 * DIM_ + h * HDIM);
        const char* gql = (const char*)(Ql + (size_t)qrow0 * DIM_ + h * HDIM);
        #pragma unroll
        for (int s = 0; s < 8; s++) {
            const int u = tid + s * 256;       // 0..2047
            const int r = u >> 4, c = (u & 15) << 4;
            CP_ASYNC16(sbase + SM_QH + r * QPITCH + c, gqh + (size_t)r * (DIM_ * 2) + c);
            CP_ASYNC16(sbase + SM_QL + r * QPITCH + c, gql + (size_t)r * (DIM_ * 2) + c);
        }
    }
    flash_load_kv(Kh, Kl, Vth, Vtl, b, kvh, 0, sbase + SM_KV, tid);
    CP_COMMIT();

    float sm0 = -1e30f, sm1 = -1e30f, sl0 = 0.f, sl1 = 0.f;
    float vacc[16][4];
    #pragma unroll
    for (int ni = 0; ni < 16; ni++)
        #pragma unroll
        for (int e = 0; e < 4; e++) vacc[ni][e] = 0.f;

    const int r0l = w * 16 + (lane >> 2);
    const int r1l = r0l + 8;
    const uint32_t a_addr0 = sbase + SM_QH + (w * 16 + (lane & 15)) * QPITCH + ((lane >> 4) << 4);
    const uint32_t b_roff  = ((lane & 7) + ((lane >> 4) << 3));
    const uint32_t b_coff  = ((lane >> 3) & 1) << 4;

    CP_WAIT(0);
    __syncthreads();

    for (int kt = 0; kt < nkt; kt++) {
        const uint32_t buf = sbase + SM_KV + (uint32_t)(kt & 1) * KVBUF;
        if (kt + 1 < nkt) {
            flash_load_kv(Kh, Kl, Vth, Vtl, b, kvh, kt + 1,
                          sbase + SM_KV + (uint32_t)((kt + 1) & 1) * KVBUF, tid);
            CP_COMMIT();
        }

        // ---- S = Q K^T  (3-pass split) ----
        float sacc[8][4];
        #pragma unroll
        for (int nj = 0; nj < 8; nj++)
            #pragma unroll
            for (int e = 0; e < 4; e++) sacc[nj][e] = 0.f;

        #pragma unroll
        for (int ks = 0; ks < 8; ks++) {
            uint32_t qh4[4], ql4[4];
            const uint32_t aaddr = a_addr0 + ks * 32;
            ldsm4(qh4, aaddr);
            ldsm4(ql4, aaddr + (SM_QL - SM_QH));
            #pragma unroll
            for (int nq = 0; nq < 4; nq++) {
                uint32_t kh4[4], kl4[4];
                const uint32_t baddr = buf + OFF_KH + (nq * 16 + b_roff) * QPITCH + ks * 32 + b_coff;
                ldsm4(kh4, baddr);
                ldsm4(kl4, baddr + (OFF_KL - OFF_KH));
                mma16816(sacc[nq * 2],     qh4, kh4[0], kh4[1]);
                mma16816(sacc[nq * 2 + 1], qh4, kh4[2], kh4[3]);
                mma16816(sacc[nq * 2],     qh4, kl4[0], kl4[1]);
                mma16816(sacc[nq * 2 + 1], qh4, kl4[2], kl4[3]);
                mma16816(sacc[nq * 2],     ql4, kh4[0], kh4[1]);
                mma16816(sacc[nq * 2 + 1], ql4, kh4[2], kh4[3]);
            }
        }

        // ---- causal mask (diagonal k-tiles only) ----
        if (kt >= 2 * qt) {
            const int coff = kt * 64 - qt * 128;
            #pragma unroll
            for (int nj = 0; nj < 8; nj++) {
                const int c0 = coff + nj * 8 + (lane & 3) * 2;
                if (c0     > r0l) sacc[nj][0] = -1e30f;
                if (c0 + 1 > r0l) sacc[nj][1] = -1e30f;
                if (c0     > r1l) sacc[nj][2] = -1e30f;
                if (c0 + 1 > r1l) sacc[nj][3] = -1e30f;
            }
        }

        // ---- online softmax (row stats in registers, bfly over lane&3) ----
        float mx0 = -1e30f, mx1 = -1e30f;
        #pragma unroll
        for (int nj = 0; nj < 8; nj++) {
            mx0 = fmaxf(mx0, fmaxf(sacc[nj][0], sacc[nj][1]));
            mx1 = fmaxf(mx1, fmaxf(sacc[nj][2], sacc[nj][3]));
        }
        mx0 = fmaxf(mx0, __shfl_xor_sync(0xFFFFFFFFu, mx0, 1));
        mx0 = fmaxf(mx0, __shfl_xor_sync(0xFFFFFFFFu, mx0, 2));
        mx1 = fmaxf(mx1, __shfl_xor_sync(0xFFFFFFFFu, mx1, 1));
        mx1 = fmaxf(mx1, __shfl_xor_sync(0xFFFFFFFFu, mx1, 2));
        const float mn0 = fmaxf(sm0, mx0), mn1 = fmaxf(sm1, mx1);
        const float al0 = __expf(sm0 - mn0), al1 = __expf(sm1 - mn1);
        sm0 = mn0; sm1 = mn1;

        // P = exp(S - m), pack to hi/lo A fragments, accumulate row sums
        uint32_t pah[4][4], pal[4][4];
        float ls0 = 0.f, ls1 = 0.f;
        #pragma unroll
        for (int j = 0; j < 4; j++) {
            #pragma unroll
            for (int t = 0; t < 2; t++) {
                const int nj = 2 * j + t;
                const float p0 = __expf(sacc[nj][0] - mn0);
                const float p1 = __expf(sacc[nj][1] - mn0);
                const float p2 = __expf(sacc[nj][2] - mn1);
                const float p3 = __expf(sacc[nj][3] - mn1);
                ls0 += p0 + p1;
                ls1 += p2 + p3;
                split2(p0, p1, pah[j][t * 2],     pal[j][t * 2]);
                split2(p2, p3, pah[j][t * 2 + 1], pal[j][t * 2 + 1]);
            }
        }
        ls0 += __shfl_xor_sync(0xFFFFFFFFu, ls0, 1);
        ls0 += __shfl_xor_sync(0xFFFFFFFFu, ls0, 2);
        ls1 += __shfl_xor_sync(0xFFFFFFFFu, ls1, 1);
        ls1 += __shfl_xor_sync(0xFFFFFFFFu, ls1, 2);
        sl0 = sl0 * al0 + ls0;
        sl1 = sl1 * al1 + ls1;

        // rescale O
        #pragma unroll
        for (int ni = 0; ni < 16; ni++) {
            vacc[ni][0] *= al0; vacc[ni][1] *= al0;
            vacc[ni][2] *= al1; vacc[ni][3] *= al1;
        }

        // ---- O += P V  (3-pass split; B = V^T [d][t]) ----
        #pragma unroll
        for (int j = 0; j < 4; j++) {
            #pragma unroll
            for (int nq = 0; nq < 8; nq++) {
                uint32_t vh4[4], vl4[4];
                const uint32_t vaddr = buf + OFF_VH + (nq * 16 + b_roff) * VPITCH + j * 32 + b_coff;
                ldsm4(vh4, vaddr);
                ldsm4(vl4, vaddr + (OFF_VL - OFF_VH));
                mma16816(vacc[nq * 2],     pah[j], vh4[0], vh4[1]);
                mma16816(vacc[nq * 2 + 1], pah[j], vh4[2], vh4[3]);
                mma16816(vacc[nq * 2],     pah[j], vl4[0], vl4[1]);
                mma16816(vacc[nq * 2 + 1], pah[j], vl4[2], vl4[3]);
                mma16816(vacc[nq * 2],     pal[j], vh4[0], vh4[1]);
                mma16816(vacc[nq * 2 + 1], pal[j], vh4[2], vh4[3]);
            }
        }

        if (kt + 1 < nkt) CP_WAIT(0);
        __syncthreads();
    }

    // ---- epilogue ----
    const float inv0 = 1.f / sl0, inv1 = 1.f / sl1;
    float* o0 = Og + (size_t)(qrow0 + r0l) * DIM_ + h * HDIM;
    float* o1 = Og + (size_t)(qrow0 + r1l) * DIM_ + h * HDIM;
    #pragma unroll
    for (int ni = 0; ni < 16; ni++) {
        const int col = ni * 8 + (lane & 3) * 2;
        *(float2*)(o0 + col) = make_float2(vacc[ni][0] * inv0, vacc[ni][1] * inv0);
        *(float2*)(o1 + col) = make_float2(vacc[ni][2] * inv1, vacc[ni][3] * inv1);
    }
}

// ================= launch ====================================================
extern "C" void kernel_launch(void* const* d_in, const int* in_sizes, int n_in,
                              void* d_out, int out_size)
{
    const float* x  = (const float*)d_in[0];
    const float* fc = (const float*)d_in[1];
    const float* fs = (const float*)d_in[2];
    const float* wq = (const float*)d_in[3];
    const float* wk = (const float*)d_in[4];
    const float* wv = (const float*)d_in[5];
    const float* wo = (const float*)d_in[6];
    float* out = (float*)d_out;

    float *q, *k, *v, *att;
    cudaGetSymbolAddress((void**)&q,   g_q);
    cudaGetSymbolAddress((void**)&k,   g_k);
    cudaGetSymbolAddress((void**)&v,   g_v);
    cudaGetSymbolAddress((void**)&att, g_att);
    __nv_bfloat16 *xh, *xl, *wqth, *wqtl, *wkth, *wktl, *wvth, *wvtl, *woth, *wotl, *ath, *atl;
    __nv_bfloat16 *qh, *ql, *kh, *kl, *vth, *vtl;
    cudaGetSymbolAddress((void**)&xh,   g_xh);   cudaGetSymbolAddress((void**)&xl,   g_xl);
    cudaGetSymbolAddress((void**)&wqth, g_wqth); cudaGetSymbolAddress((void**)&wqtl, g_wqtl);
    cudaGetSymbolAddress((void**)&wkth, g_wkth); cudaGetSymbolAddress((void**)&wktl, g_wktl);
    cudaGetSymbolAddress((void**)&wvth, g_wvth); cudaGetSymbolAddress((void**)&wvtl, g_wvtl);
    cudaGetSymbolAddress((void**)&woth, g_woth); cudaGetSymbolAddress((void**)&wotl, g_wotl);
    cudaGetSymbolAddress((void**)&ath,  g_ath);  cudaGetSymbolAddress((void**)&atl,  g_atl);
    cudaGetSymbolAddress((void**)&qh,   g_qh);   cudaGetSymbolAddress((void**)&ql,   g_ql);
    cudaGetSymbolAddress((void**)&kh,   g_kh);   cudaGetSymbolAddress((void**)&kl,   g_kl);
    cudaGetSymbolAddress((void**)&vth,  g_vth);  cudaGetSymbolAddress((void**)&vtl,  g_vtl);

    cudaFuncSetAttribute(mma_gemm_kernel<true>,  cudaFuncAttributeMaxDynamicSharedMemorySize,
                         GEMM_SMEM);
    cudaFuncSetAttribute(mma_gemm_kernel<false>, cudaFuncAttributeMaxDynamicSharedMemorySize,
                         GEMM_SMEM);
    cudaFuncSetAttribute(flash_mma_kernel, cudaFuncAttributeMaxDynamicSharedMemorySize,
                         FLASH2_SMEM);

    const int n4x = MROWS * DIM_ / 4;          // 2M
    const int n4k = MROWS * KVDIM / 4;         // 512K
    const float qscale = 0.08838834764831845f; // 1/sqrt(128)

    split_kernel<<<n4x / 256, 256>>>(x, xh, xl, n4x, 1.f);
    tsplit_kernel<<<dim3(DIM_  / 32, DIM_ / 32), 256>>>(wq, wqth, wqtl, DIM_, DIM_);
    tsplit_kernel<<<dim3(KVDIM / 32, DIM_ / 32), 256>>>(wk, wkth, wktl, DIM_, KVDIM);
    tsplit_kernel<<<dim3(KVDIM / 32, DIM_ / 32), 256>>>(wv, wvth, wvtl, DIM_, KVDIM);
    tsplit_kernel<<<dim3(DIM_  / 32, DIM_ / 32), 256>>>(wo, woth, wotl, DIM_, DIM_);

    mma_gemm_kernel<true ><<<dim3(DIM_  / 128, MROWS / 128), 256, GEMM_SMEM>>>(
        xh, xl, wqth, wqtl, q, DIM_,  fc, fs);
    mma_gemm_kernel<true ><<<dim3(KVDIM / 128, MROWS / 128), 256, GEMM_SMEM>>>(
        xh, xl, wkth, wktl, k, KVDIM, fc, fs);
    mma_gemm_kernel<false><<<dim3(KVDIM / 128, MROWS / 128), 256, GEMM_SMEM>>>(
        xh, xl, wvth, wvtl, v, KVDIM, nullptr, nullptr);

    // convert flash inputs: Q (scale folded), K, V^T
    split_kernel<<<n4x / 256, 256>>>(q, qh, ql, n4x, qscale);
    split_kernel<<<n4k / 256, 256>>>(k, kh, kl, n4k, 1.f);
    vtsplit_kernel<<<dim3(T_SZ / 32, KVDIM / 32, B_SZ), 256>>>(v, vth, vtl);

    flash_mma_kernel<<<dim3(T_SZ / 128, B_SZ * NHEAD), 256, FLASH2_SMEM>>>(
        qh, ql, kh, kl, vth, vtl, att);

    split_kernel<<<n4x / 256, 256>>>(att, ath, atl, n4x, 1.f);
    mma_gemm_kernel<false><<<dim3(DIM_ / 128, MROWS / 128), 256, GEMM_SMEM>>>(
        ath, atl, woth, wotl, out, DIM_, nullptr, nullptr);
}

// round 12
// speedup vs baseline: 1.0007x; 1.0007x over previous
#include <cuda_runtime.h>
#include <cuda_bf16.h>
#include <cstdint>

#define B_SZ   2
#define T_SZ   2048
#define DIM_   2048
#define NHEAD  16
#define KVHEAD 4
#define HDIM   128
#define MROWS  (B_SZ * T_SZ)        // 4096
#define KVDIM  (KVHEAD * HDIM)      // 512
#define GK     2048

// ================= scratch (device globals; no allocations allowed) =========
__device__ float g_q[(size_t)MROWS * DIM_];
__device__ float g_k[(size_t)MROWS * KVDIM];
__device__ float g_v[(size_t)MROWS * KVDIM];
__device__ float g_att[(size_t)MROWS * DIM_];

__device__ __align__(16) __nv_bfloat16 g_xh[(size_t)MROWS * DIM_];
__device__ __align__(16) __nv_bfloat16 g_xl[(size_t)MROWS * DIM_];
__device__ __align__(16) __nv_bfloat16 g_wqth[(size_t)DIM_ * DIM_];   // [N,K]
__device__ __align__(16) __nv_bfloat16 g_wqtl[(size_t)DIM_ * DIM_];
__device__ __align__(16) __nv_bfloat16 g_wkth[(size_t)KVDIM * DIM_];
__device__ __align__(16) __nv_bfloat16 g_wktl[(size_t)KVDIM * DIM_];
__device__ __align__(16) __nv_bfloat16 g_wvth[(size_t)KVDIM * DIM_];
__device__ __align__(16) __nv_bfloat16 g_wvtl[(size_t)KVDIM * DIM_];
__device__ __align__(16) __nv_bfloat16 g_woth[(size_t)DIM_ * DIM_];
__device__ __align__(16) __nv_bfloat16 g_wotl[(size_t)DIM_ * DIM_];
__device__ __align__(16) __nv_bfloat16 g_ath[(size_t)MROWS * DIM_];
__device__ __align__(16) __nv_bfloat16 g_atl[(size_t)MROWS * DIM_];
// flash inputs (bf16 hi/lo)
__device__ __align__(16) __nv_bfloat16 g_qh[(size_t)MROWS * DIM_];
__device__ __align__(16) __nv_bfloat16 g_ql[(size_t)MROWS * DIM_];
__device__ __align__(16) __nv_bfloat16 g_kh[(size_t)MROWS * KVDIM];
__device__ __align__(16) __nv_bfloat16 g_kl[(size_t)MROWS * KVDIM];
__device__ __align__(16) __nv_bfloat16 g_vth[(size_t)B_SZ * KVDIM * T_SZ]; // [b*512+c][t]
__device__ __align__(16) __nv_bfloat16 g_vtl[(size_t)B_SZ * KVDIM * T_SZ];

// ================= helpers ===================================================
__device__ __forceinline__ uint32_t smem_u32(const void* p) {
    uint32_t a;
    asm("{ .reg .u64 t; cvta.to.shared.u64 t, %1; cvt.u32.u64 %0, t; }" : "=r"(a) : "l"(p));
    return a;
}
__device__ __forceinline__ void ldsm4(uint32_t (&r)[4], uint32_t addr) {
    asm volatile("ldmatrix.sync.aligned.m8n8.x4.shared.b16 {%0,%1,%2,%3}, [%4];"
                 : "=r"(r[0]), "=r"(r[1]), "=r"(r[2]), "=r"(r[3]) : "r"(addr));
}
__device__ __forceinline__ void mma16816(float (&d)[4], const uint32_t (&a)[4],
                                         uint32_t b0, uint32_t b1) {
    asm volatile("mma.sync.aligned.m16n8k16.row.col.f32.bf16.bf16.f32 "
                 "{%0,%1,%2,%3}, {%4,%5,%6,%7}, {%8,%9}, {%0,%1,%2,%3};"
                 : "+f"(d[0]), "+f"(d[1]), "+f"(d[2]), "+f"(d[3])
                 : "r"(a[0]), "r"(a[1]), "r"(a[2]), "r"(a[3]), "r"(b0), "r"(b1));
}
#define CP_ASYNC16(sm, gm) \
    asm volatile("cp.async.cg.shared.global [%0], [%1], 16;" :: "r"(sm), "l"(gm) : "memory")
#define CP_COMMIT() asm volatile("cp.async.commit_group;" ::: "memory")
#define CP_WAIT(n)  asm volatile("cp.async.wait_group %0;" :: "n"(n) : "memory")

__device__ __forceinline__ void split2(float a, float b, uint32_t& h, uint32_t& l) {
    __nv_bfloat16 ha = __float2bfloat16(a), hb = __float2bfloat16(b);
    float ra = a - __bfloat162float(ha), rb = b - __bfloat162float(hb);
    __nv_bfloat162 hp; hp.x = ha; hp.y = hb;
    __nv_bfloat162 lp; lp.x = __float2bfloat16(ra); lp.y = __float2bfloat16(rb);
    h = *reinterpret_cast<uint32_t*>(&hp);
    l = *reinterpret_cast<uint32_t*>(&lp);
}

// ================= split / transpose-split conversion kernels ================
__global__ void split_kernel(const float* __restrict__ in, __nv_bfloat16* __restrict__ hi,
                             __nv_bfloat16* __restrict__ lo, int n4, float scale)
{
    int i = blockIdx.x * 256 + threadIdx.x;
    if (i >= n4) return;
    float4 v = ((const float4*)in)[i];
    float f[4] = {v.x * scale, v.y * scale, v.z * scale, v.w * scale};
    uint32_t h0, l0, h1, l1;
    split2(f[0], f[1], h0, l0);
    split2(f[2], f[3], h1, l1);
    ((uint32_t*)hi)[2 * i]     = h0;
    ((uint32_t*)hi)[2 * i + 1] = h1;
    ((uint32_t*)lo)[2 * i]     = l0;
    ((uint32_t*)lo)[2 * i + 1] = l1;
}

// in: [R,C] fp32 row-major  ->  out hi/lo: [C,R] bf16 row-major (transposed)
__global__ void tsplit_kernel(const float* __restrict__ in, __nv_bfloat16* __restrict__ hi,
                              __nv_bfloat16* __restrict__ lo, int R, int C)
{
    __shared__ float tile[32][33];
    const int bx = blockIdx.x << 5;
    const int by = blockIdx.y << 5;
    const int tx = threadIdx.x & 31, ty = threadIdx.x >> 5;
    #pragma unroll
    for (int r = ty; r < 32; r += 8)
        tile[r][tx] = in[(size_t)(by + r) * C + bx + tx];
    __syncthreads();
    #pragma unroll
    for (int r = ty; r < 32; r += 8) {
        float v = tile[tx][r];
        __nv_bfloat16 h = __float2bfloat16(v);
        __nv_bfloat16 l = __float2bfloat16(v - __bfloat162float(h));
        size_t o = (size_t)(bx + r) * R + by + tx;
        hi[o] = h; lo[o] = l;
    }
}

// g_v [b*T + t][c] fp32 -> g_vt[(b*512 + c)][t] bf16 hi/lo (per-batch transpose)
__global__ void vtsplit_kernel(const float* __restrict__ in, __nv_bfloat16* __restrict__ hi,
                               __nv_bfloat16* __restrict__ lo)
{
    __shared__ float tile[32][33];
    const int t0 = blockIdx.x << 5;
    const int c0 = blockIdx.y << 5;
    const int b  = blockIdx.z;
    const int tx = threadIdx.x & 31, ty = threadIdx.x >> 5;
    #pragma unroll
    for (int r = ty; r < 32; r += 8)
        tile[r][tx] = in[(size_t)(b * T_SZ + t0 + r) * KVDIM + c0 + tx];
    __syncthreads();
    #pragma unroll
    for (int r = ty; r < 32; r += 8) {
        float v = tile[tx][r];
        __nv_bfloat16 h = __float2bfloat16(v);
        __nv_bfloat16 l = __float2bfloat16(v - __bfloat162float(h));
        size_t o = (size_t)(b * KVDIM + c0 + r) * T_SZ + t0 + tx;
        hi[o] = h; lo[o] = l;
    }
}

// ================= split-bf16 HMMA GEMM (unchanged from R8-passing) ==========
#define BK        32
#define NKB       (GK / BK)
#define TPITCH    80
#define TILE_BY   (128 * TPITCH)
#define SOFF_AH   0
#define SOFF_AL   (1 * TILE_BY)
#define SOFF_BH   (2 * TILE_BY)
#define SOFF_BL   (3 * TILE_BY)
#define STAGE_BY  (4 * TILE_BY)
#define GEMM_SMEM (2 * STAGE_BY)

__device__ __forceinline__ void load_stage(
    const __nv_bfloat16* __restrict__ Abh, const __nv_bfloat16* __restrict__ Abl,
    const __nv_bfloat16* __restrict__ Bbh, const __nv_bfloat16* __restrict__ Bbl,
    int kof, uint32_t sbuf, int tid)
{
    #pragma unroll
    for (int i = 0; i < 2; i++) {
        const int c   = tid + (i << 8);
        const int row = c >> 2, q = c & 3;
        const size_t   go = (size_t)row * GK + kof + q * 8;
        const uint32_t so = row * TPITCH + q * 16;
        CP_ASYNC16(sbuf + SOFF_AH + so, Abh + go);
        CP_ASYNC16(sbuf + SOFF_AL + so, Abl + go);
        CP_ASYNC16(sbuf + SOFF_BH + so, Bbh + go);
        CP_ASYNC16(sbuf + SOFF_BL + so, Bbl + go);
    }
}

template<bool ROPE>
__global__ __launch_bounds__(256, 1)
void mma_gemm_kernel(const __nv_bfloat16* __restrict__ Ah, const __nv_bfloat16* __restrict__ Al,
                     const __nv_bfloat16* __restrict__ Bh, const __nv_bfloat16* __restrict__ Bl,
                     float* __restrict__ C, int N,
                     const float* __restrict__ fc, const float* __restrict__ fs)
{
    extern __shared__ char smem[];
    const uint32_t sbase = smem_u32(smem);
    const int tid  = threadIdx.x;
    const int lane = tid & 31, wid = tid >> 5;
    const int wm   = wid & 3,  wn  = wid >> 2;
    const int row0 = blockIdx.y << 7, col0 = blockIdx.x << 7;

    const __nv_bfloat16* Abh = Ah + (size_t)row0 * GK;
    const __nv_bfloat16* Abl = Al + (size_t)row0 * GK;
    const __nv_bfloat16* Bbh = Bh + (size_t)col0 * GK;
    const __nv_bfloat16* Bbl = Bl + (size_t)col0 * GK;

    float acc[2][8][4];
    #pragma unroll
    for (int mi = 0; mi < 2; mi++)
        #pragma unroll
        for (int ni = 0; ni < 8; ni++)
            #pragma unroll
            for (int e = 0; e < 4; e++) acc[mi][ni][e] = 0.f;

    const uint32_t a_row = wm * 32 + (lane & 15);
    const uint32_t a_col = (lane >> 4) << 4;
    const uint32_t b_rowb = wn * 64 + (lane & 7) + ((lane >> 4) << 3);
    const uint32_t b_col  = ((lane >> 3) & 1) << 4;

    load_stage(Abh, Abl, Bbh, Bbl, 0, sbase, tid);
    CP_COMMIT();

    for (int blk = 0; blk < NKB; blk++) {
        const uint32_t buf = sbase + (uint32_t)(blk & 1) * STAGE_BY;
        if (blk + 1 < NKB) {
            load_stage(Abh, Abl, Bbh, Bbl, (blk + 1) * BK,
                       sbase + (uint32_t)((blk + 1) & 1) * STAGE_BY, tid);
            CP_COMMIT();
            CP_WAIT(1);
        } else {
            CP_WAIT(0);
        }
        __syncthreads();

        #pragma unroll
        for (int ks = 0; ks < 2; ks++) {
            const uint32_t koff = ks * 32;
            uint32_t ah[2][4], al[2][4];
            #pragma unroll
            for (int mi = 0; mi < 2; mi++) {
                const uint32_t aaddr = buf + SOFF_AH + (a_row + mi * 16) * TPITCH + koff + a_col;
                ldsm4(ah[mi], aaddr);
                ldsm4(al[mi], aaddr + (SOFF_AL - SOFF_AH));
            }
            uint32_t bh[4][4], bl[4][4];
            #pragma unroll
            for (int nq = 0; nq < 4; nq++) {
                const uint32_t baddr = buf + SOFF_BH + (b_rowb + nq * 16) * TPITCH + koff + b_col;
                ldsm4(bh[nq], baddr);
                ldsm4(bl[nq], baddr + (SOFF_BL - SOFF_BH));
            }
            #pragma unroll
            for (int mi = 0; mi < 2; mi++)
                #pragma unroll
                for (int nq = 0; nq < 4; nq++)
                    #pragma unroll
                    for (int hf = 0; hf < 2; hf++) {
                        const int ni = nq * 2 + hf;
                        const uint32_t b0h = bh[nq][hf * 2], b1h = bh[nq][hf * 2 + 1];
                        const uint32_t b0l = bl[nq][hf * 2], b1l = bl[nq][hf * 2 + 1];
                        mma16816(acc[mi][ni], ah[mi], b0h, b1h);
                        mma16816(acc[mi][ni], ah[mi], b0l, b1l);
                        mma16816(acc[mi][ni], al[mi], b0h, b1h);
                    }
        }
        __syncthreads();
    }

    const int lr = lane >> 2;
    const int lc = (lane & 3) << 1;
    #pragma unroll
    for (int mi = 0; mi < 2; mi++) {
        #pragma unroll
        for (int ni = 0; ni < 8; ni++) {
            float* d = acc[mi][ni];
            const int r0  = row0 + wm * 32 + mi * 16 + lr;
            const int r1  = r0 + 8;
            const int col = col0 + wn * 64 + ni * 8 + lc;
            if (ROPE) {
                const int p = (col & (HDIM - 1)) >> 1;
                {
                    const int t = r0 & (T_SZ - 1);
                    const float cz = fc[t * (HDIM / 2) + p];
                    const float sz = fs[t * (HDIM / 2) + p];
                    const float xr = d[0], xi = d[1];
                    d[0] = xr * cz - xi * sz;
                    d[1] = xr * sz + xi * cz;
                }
                {
                    const int t = r1 & (T_SZ - 1);
                    const float cz = fc[t * (HDIM / 2) + p];
                    const float sz = fs[t * (HDIM / 2) + p];
                    const float xr = d[2], xi = d[3];
                    d[2] = xr * cz - xi * sz;
                    d[3] = xr * sz + xi * cz;
                }
            }
            *(float2*)(C + (size_t)r0 * N + col) = make_float2(d[0], d[1]);
            *(float2*)(C + (size_t)r1 * N + col) = make_float2(d[2], d[3]);
        }
    }
}

// ================= tensor-core flash attention ===============================
// q-tile 128 (8 warps x 16 rows), k-tile 64, 3-pass hi/lo mma for S and PV.
// Per-row softmax stats entirely in registers (row owned by one warp).
#define QPITCH 272                    // 128 bf16 = 256B + 16 pad
#define VPITCH 144                    // 64 bf16 = 128B + 16 pad
#define SM_QH  0
#define SM_QL  (128 * QPITCH)         // 34816
#define SM_KV  (2 * 128 * QPITCH)     // 69632
#define OFF_KH 0
#define OFF_KL (64 * QPITCH)          // 17408
#define OFF_VH (2 * 64 * QPITCH)      // 34816
#define OFF_VL (OFF_VH + 128 * VPITCH) // 53248
#define KVBUF  (OFF_VL + 128 * VPITCH) // 71680
#define FLASH2_SMEM (SM_KV + 2 * KVBUF) // 212992

__device__ __forceinline__ void flash_load_kv(
    const __nv_bfloat16* __restrict__ Kh, const __nv_bfloat16* __restrict__ Kl,
    const __nv_bfloat16* __restrict__ Vth, const __nv_bfloat16* __restrict__ Vtl,
    int b, int kvh, int kt, uint32_t buf, int tid)
{
    const char* gkh = (const char*)(Kh + (size_t)(b * T_SZ + kt * 64) * KVDIM + kvh * HDIM);
    const char* gkl = (const char*)(Kl + (size_t)(b * T_SZ + kt * 64) * KVDIM + kvh * HDIM);
    #pragma unroll
    for (int s = 0; s < 4; s++) {
        const int u = tid + s * 256;           // 0..1023
        const int r = u >> 4, c = (u & 15) << 4;
        CP_ASYNC16(buf + OFF_KH + r * QPITCH + c, gkh + (size_t)r * (KVDIM * 2) + c);
        CP_ASYNC16(buf + OFF_KL + r * QPITCH + c, gkl + (size_t)r * (KVDIM * 2) + c);
    }
    const char* gvh = (const char*)(Vth + ((size_t)(b * KVHEAD + kvh) * HDIM) * T_SZ + kt * 64);
    const char* gvl = (const char*)(Vtl + ((size_t)(b * KVHEAD + kvh) * HDIM) * T_SZ + kt * 64);
    #pragma unroll
    for (int s = 0; s < 4; s++) {
        const int u = tid + s * 256;
        const int r = u >> 3, c = (u & 7) << 4;
        CP_ASYNC16(buf + OFF_VH + r * VPITCH + c, gvh + (size_t)r * (T_SZ * 2) + c);
        CP_ASYNC16(buf + OFF_VL + r * VPITCH + c, gvl + (size_t)r * (T_SZ * 2) + c);
    }
}

__global__ __launch_bounds__(256, 1)
void flash_mma_kernel(const __nv_bfloat16* __restrict__ Qh, const __nv_bfloat16* __restrict__ Ql,
                      const __nv_bfloat16* __restrict__ Kh, const __nv_bfloat16* __restrict__ Kl,
                      const __nv_bfloat16* __restrict__ Vth, const __nv_bfloat16* __restrict__ Vtl,
                      float* __restrict__ Og)
{
    extern __shared__ char smem[];
    const uint32_t sbase = smem_u32(smem);
    const int tid = threadIdx.x, lane = tid & 31, w = tid >> 5;
    const int qt = (int)gridDim.x - 1 - (int)blockIdx.x;   // heavy tiles first
    const int bh = blockIdx.y, b = bh >> 4, h = bh & 15, kvh = h >> 2;
    const int qrow0 = b * T_SZ + qt * 128;
    const int nkt = 2 * qt + 2;

    // prologue: stage Q (hi/lo) + KV tile 0
    {
        const char* gqh = (const char*)(Qh + (size_t)qrow0 * DIM_ + h * HDIM);
        const char* gql = (const char*)(Ql + (size_t)qrow0 * DIM_ + h * HDIM);
        #pragma unroll
        for (int s = 0; s < 8; s++) {
            const int u = tid + s * 256;       // 0..2047
            const int r = u >> 4, c = (u & 15) << 4;
            CP_ASYNC16(sbase + SM_QH + r * QPITCH + c, gqh + (size_t)r * (DIM_ * 2) + c);
            CP_ASYNC16(sbase + SM_QL + r * QPITCH + c, gql + (size_t)r * (DIM_ * 2) + c);
        }
    }
    flash_load_kv(Kh, Kl, Vth, Vtl, b, kvh, 0, sbase + SM_KV, tid);
    CP_COMMIT();

    float sm0 = -1e30f, sm1 = -1e30f, sl0 = 0.f, sl1 = 0.f;
    float vacc[16][4];
    #pragma unroll
    for (int ni = 0; ni < 16; ni++)
        #pragma unroll
        for (int e = 0; e < 4; e++) vacc[ni][e] = 0.f;

    const int r0l = w * 16 + (lane >> 2);
    const int r1l = r0l + 8;
    const uint32_t a_addr0 = sbase + SM_QH + (w * 16 + (lane & 15)) * QPITCH + ((lane >> 4) << 4);
    const uint32_t b_roff  = ((lane & 7) + ((lane >> 4) << 3));
    const uint32_t b_coff  = ((lane >> 3) & 1) << 4;

    CP_WAIT(0);
    __syncthreads();

    for (int kt = 0; kt < nkt; kt++) {
        const uint32_t buf = sbase + SM_KV + (uint32_t)(kt & 1) * KVBUF;
        if (kt + 1 < nkt) {
            flash_load_kv(Kh, Kl, Vth, Vtl, b, kvh, kt + 1,
                          sbase + SM_KV + (uint32_t)((kt + 1) & 1) * KVBUF, tid);
            CP_COMMIT();
        }

        // ---- S = Q K^T  (3-pass split) ----
        float sacc[8][4];
        #pragma unroll
        for (int nj = 0; nj < 8; nj++)
            #pragma unroll
            for (int e = 0; e < 4; e++) sacc[nj][e] = 0.f;

        #pragma unroll
        for (int ks = 0; ks < 8; ks++) {
            uint32_t qh4[4], ql4[4];
            const uint32_t aaddr = a_addr0 + ks * 32;
            ldsm4(qh4, aaddr);
            ldsm4(ql4, aaddr + (SM_QL - SM_QH));
            #pragma unroll
            for (int nq = 0; nq < 4; nq++) {
                uint32_t kh4[4], kl4[4];
                const uint32_t baddr = buf + OFF_KH + (nq * 16 + b_roff) * QPITCH + ks * 32 + b_coff;
                ldsm4(kh4, baddr);
                ldsm4(kl4, baddr + (OFF_KL - OFF_KH));
                mma16816(sacc[nq * 2],     qh4, kh4[0], kh4[1]);
                mma16816(sacc[nq * 2 + 1], qh4, kh4[2], kh4[3]);
                mma16816(sacc[nq * 2],     qh4, kl4[0], kl4[1]);
                mma16816(sacc[nq * 2 + 1], qh4, kl4[2], kl4[3]);
                mma16816(sacc[nq * 2],     ql4, kh4[0], kh4[1]);
                mma16816(sacc[nq * 2 + 1], ql4, kh4[2], kh4[3]);
            }
        }

        // ---- causal mask (diagonal k-tiles only) ----
        if (kt >= 2 * qt) {
            const int coff = kt * 64 - qt * 128;
            #pragma unroll
            for (int nj = 0; nj < 8; nj++) {
                const int c0 = coff + nj * 8 + (lane & 3) * 2;
                if (c0     > r0l) sacc[nj][0] = -1e30f;
                if (c0 + 1 > r0l) sacc[nj][1] = -1e30f;
                if (c0     > r1l) sacc[nj][2] = -1e30f;
                if (c0 + 1 > r1l) sacc[nj][3] = -1e30f;
            }
        }

        // ---- online softmax (row stats in registers, bfly over lane&3) ----
        float mx0 = -1e30f, mx1 = -1e30f;
        #pragma unroll
        for (int nj = 0; nj < 8; nj++) {
            mx0 = fmaxf(mx0, fmaxf(sacc[nj][0], sacc[nj][1]));
            mx1 = fmaxf(mx1, fmaxf(sacc[nj][2], sacc[nj][3]));
        }
        mx0 = fmaxf(mx0, __shfl_xor_sync(0xFFFFFFFFu, mx0, 1));
        mx0 = fmaxf(mx0, __shfl_xor_sync(0xFFFFFFFFu, mx0, 2));
        mx1 = fmaxf(mx1, __shfl_xor_sync(0xFFFFFFFFu, mx1, 1));
        mx1 = fmaxf(mx1, __shfl_xor_sync(0xFFFFFFFFu, mx1, 2));
        const float mn0 = fmaxf(sm0, mx0), mn1 = fmaxf(sm1, mx1);
        const float al0 = __expf(sm0 - mn0), al1 = __expf(sm1 - mn1);
        sm0 = mn0; sm1 = mn1;

        // P = exp(S - m), pack to hi/lo A fragments, accumulate row sums
        uint32_t pah[4][4], pal[4][4];
        float ls0 = 0.f, ls1 = 0.f;
        #pragma unroll
        for (int j = 0; j < 4; j++) {
            #pragma unroll
            for (int t = 0; t < 2; t++) {
                const int nj = 2 * j + t;
                const float p0 = __expf(sacc[nj][0] - mn0);
                const float p1 = __expf(sacc[nj][1] - mn0);
                const float p2 = __expf(sacc[nj][2] - mn1);
                const float p3 = __expf(sacc[nj][3] - mn1);
                ls0 += p0 + p1;
                ls1 += p2 + p3;
                split2(p0, p1, pah[j][t * 2],     pal[j][t * 2]);
                split2(p2, p3, pah[j][t * 2 + 1], pal[j][t * 2 + 1]);
            }
        }
        ls0 += __shfl_xor_sync(0xFFFFFFFFu, ls0, 1);
        ls0 += __shfl_xor_sync(0xFFFFFFFFu, ls0, 2);
        ls1 += __shfl_xor_sync(0xFFFFFFFFu, ls1, 1);
        ls1 += __shfl_xor_sync(0xFFFFFFFFu, ls1, 2);
        sl0 = sl0 * al0 + ls0;
        sl1 = sl1 * al1 + ls1;

        // rescale O
        #pragma unroll
        for (int ni = 0; ni < 16; ni++) {
            vacc[ni][0] *= al0; vacc[ni][1] *= al0;
            vacc[ni][2] *= al1; vacc[ni][3] *= al1;
        }

        // ---- O += P V  (3-pass split; B = V^T [d][t]) ----
        #pragma unroll
        for (int j = 0; j < 4; j++) {
            #pragma unroll
            for (int nq = 0; nq < 8; nq++) {
                uint32_t vh4[4], vl4[4];
                const uint32_t vaddr = buf + OFF_VH + (nq * 16 + b_roff) * VPITCH + j * 32 + b_coff;
                ldsm4(vh4, vaddr);
                ldsm4(vl4, vaddr + (OFF_VL - OFF_VH));
                mma16816(vacc[nq * 2],     pah[j], vh4[0], vh4[1]);
                mma16816(vacc[nq * 2 + 1], pah[j], vh4[2], vh4[3]);
                mma16816(vacc[nq * 2],     pah[j], vl4[0], vl4[1]);
                mma16816(vacc[nq * 2 + 1], pah[j], vl4[2], vl4[3]);
                mma16816(vacc[nq * 2],     pal[j], vh4[0], vh4[1]);
                mma16816(vacc[nq * 2 + 1], pal[j], vh4[2], vh4[3]);
            }
        }

        if (kt + 1 < nkt) CP_WAIT(0);
        __syncthreads();
    }

    // ---- epilogue ----
    const float inv0 = 1.f / sl0, inv1 = 1.f / sl1;
    float* o0 = Og + (size_t)(qrow0 + r0l) * DIM_ + h * HDIM;
    float* o1 = Og + (size_t)(qrow0 + r1l) * DIM_ + h * HDIM;
    #pragma unroll
    for (int ni = 0; ni < 16; ni++) {
        const int col = ni * 8 + (lane & 3) * 2;
        *(float2*)(o0 + col) = make_float2(vacc[ni][0] * inv0, vacc[ni][1] * inv0);
        *(float2*)(o1 + col) = make_float2(vacc[ni][2] * inv1, vacc[ni][3] * inv1);
    }
}

// ================= launch ====================================================
extern "C" void kernel_launch(void* const* d_in, const int* in_sizes, int n_in,
                              void* d_out, int out_size)
{
    const float* x  = (const float*)d_in[0];
    const float* fc = (const float*)d_in[1];
    const float* fs = (const float*)d_in[2];
    const float* wq = (const float*)d_in[3];
    const float* wk = (const float*)d_in[4];
    const float* wv = (const float*)d_in[5];
    const float* wo = (const float*)d_in[6];
    float* out = (float*)d_out;

    float *q, *k, *v, *att;
    cudaGetSymbolAddress((void**)&q,   g_q);
    cudaGetSymbolAddress((void**)&k,   g_k);
    cudaGetSymbolAddress((void**)&v,   g_v);
    cudaGetSymbolAddress((void**)&att, g_att);
    __nv_bfloat16 *xh, *xl, *wqth, *wqtl, *wkth, *wktl, *wvth, *wvtl, *woth, *wotl, *ath, *atl;
    __nv_bfloat16 *qh, *ql, *kh, *kl, *vth, *vtl;
    cudaGetSymbolAddress((void**)&xh,   g_xh);   cudaGetSymbolAddress((void**)&xl,   g_xl);
    cudaGetSymbolAddress((void**)&wqth, g_wqth); cudaGetSymbolAddress((void**)&wqtl, g_wqtl);
    cudaGetSymbolAddress((void**)&wkth, g_wkth); cudaGetSymbolAddress((void**)&wktl, g_wktl);
    cudaGetSymbolAddress((void**)&wvth, g_wvth); cudaGetSymbolAddress((void**)&wvtl, g_wvtl);
    cudaGetSymbolAddress((void**)&woth, g_woth); cudaGetSymbolAddress((void**)&wotl, g_wotl);
    cudaGetSymbolAddress((void**)&ath,  g_ath);  cudaGetSymbolAddress((void**)&atl,  g_atl);
    cudaGetSymbolAddress((void**)&qh,   g_qh);   cudaGetSymbolAddress((void**)&ql,   g_ql);
    cudaGetSymbolAddress((void**)&kh,   g_kh);   cudaGetSymbolAddress((void**)&kl,   g_kl);
    cudaGetSymbolAddress((void**)&vth,  g_vth);  cudaGetSymbolAddress((void**)&vtl,  g_vtl);

    cudaFuncSetAttribute(mma_gemm_kernel<true>,  cudaFuncAttributeMaxDynamicSharedMemorySize,
                         GEMM_SMEM);
    cudaFuncSetAttribute(mma_gemm_kernel<false>, cudaFuncAttributeMaxDynamicSharedMemorySize,
                         GEMM_SMEM);
    cudaFuncSetAttribute(flash_mma_kernel, cudaFuncAttributeMaxDynamicSharedMemorySize,
                         FLASH2_SMEM);

    const int n4x = MROWS * DIM_ / 4;          // 2M
    const int n4k = MROWS * KVDIM / 4;         // 512K
    const float qscale = 0.08838834764831845f; // 1/sqrt(128)

    split_kernel<<<n4x / 256, 256>>>(x, xh, xl, n4x, 1.f);
    tsplit_kernel<<<dim3(DIM_  / 32, DIM_ / 32), 256>>>(wq, wqth, wqtl, DIM_, DIM_);
    tsplit_kernel<<<dim3(KVDIM / 32, DIM_ / 32), 256>>>(wk, wkth, wktl, DIM_, KVDIM);
    tsplit_kernel<<<dim3(KVDIM / 32, DIM_ / 32), 256>>>(wv, wvth, wvtl, DIM_, KVDIM);
    tsplit_kernel<<<dim3(DIM_  / 32, DIM_ / 32), 256>>>(wo, woth, wotl, DIM_, DIM_);

    mma_gemm_kernel<true ><<<dim3(DIM_  / 128, MROWS / 128), 256, GEMM_SMEM>>>(
        xh, xl, wqth, wqtl, q, DIM_,  fc, fs);
    mma_gemm_kernel<true ><<<dim3(KVDIM / 128, MROWS / 128), 256, GEMM_SMEM>>>(
        xh, xl, wkth, wktl, k, KVDIM, fc, fs);
    mma_gemm_kernel<false><<<dim3(KVDIM / 128, MROWS / 128), 256, GEMM_SMEM>>>(
        xh, xl, wvth, wvtl, v, KVDIM, nullptr, nullptr);

    // convert flash inputs: Q (scale folded), K, V^T
    split_kernel<<<n4x / 256, 256>>>(q, qh, ql, n4x, qscale);
    split_kernel<<<n4k / 256, 256>>>(k, kh, kl, n4k, 1.f);
    vtsplit_kernel<<<dim3(T_SZ / 32, KVDIM / 32, B_SZ), 256>>>(v, vth, vtl);

    flash_mma_kernel<<<dim3(T_SZ / 128, B_SZ * NHEAD), 256, FLASH2_SMEM>>>(
        qh, ql, kh, kl, vth, vtl, att);

    split_kernel<<<n4x / 256, 256>>>(att, ath, atl, n4x, 1.f);
    mma_gemm_kernel<false><<<dim3(DIM_ / 128, MROWS / 128), 256, GEMM_SMEM>>>(
        ath, atl, woth, wotl, out, DIM_, nullptr, nullptr);
}

// round 13
// speedup vs baseline: 1.2069x; 1.2061x over previous
#include <cuda_runtime.h>
#include <cuda_bf16.h>
#include <cuda_fp16.h>
#include <cstdint>

#define B_SZ   2
#define T_SZ   2048
#define DIM_   2048
#define NHEAD  16
#define KVHEAD 4
#define HDIM   128
#define MROWS  (B_SZ * T_SZ)        // 4096
#define KVDIM  (KVHEAD * HDIM)      // 512
#define GK     2048
#define NTOT   (DIM_ + 2 * KVDIM)   // 3072 concat q|k|v columns

// ================= scratch (device globals; no allocations allowed) =========
__device__ float g_v[(size_t)MROWS * KVDIM];                       // fp32 v

__device__ __align__(16) __nv_bfloat16 g_xh[(size_t)MROWS * DIM_];
__device__ __align__(16) __nv_bfloat16 g_xl[(size_t)MROWS * DIM_];
__device__ __align__(16) __nv_bfloat16 g_wth[(size_t)NTOT * GK];   // [3072,2048] concat wq|wk|wv ^T
__device__ __align__(16) __nv_bfloat16 g_wtl[(size_t)NTOT * GK];
__device__ __align__(16) __half        g_wotf[(size_t)DIM_ * GK];  // wo^T fp16 single
__device__ __align__(16) __nv_bfloat16 g_qh[(size_t)MROWS * DIM_];
__device__ __align__(16) __nv_bfloat16 g_ql[(size_t)MROWS * DIM_];
__device__ __align__(16) __nv_bfloat16 g_kh[(size_t)MROWS * KVDIM];
__device__ __align__(16) __nv_bfloat16 g_kl[(size_t)MROWS * KVDIM];
__device__ __align__(16) __half        g_vtf[(size_t)B_SZ * KVDIM * T_SZ]; // [b*512+c][t]
__device__ __align__(16) __half        g_ath[(size_t)MROWS * DIM_];  // att hi fp16
__device__ __align__(16) __half        g_atl[(size_t)MROWS * DIM_];  // att lo fp16

// ================= helpers ===================================================
__device__ __forceinline__ uint32_t smem_u32(const void* p) {
    uint32_t a;
    asm("{ .reg .u64 t; cvta.to.shared.u64 t, %1; cvt.u32.u64 %0, t; }" : "=r"(a) : "l"(p));
    return a;
}
__device__ __forceinline__ void ldsm4(uint32_t (&r)[4], uint32_t addr) {
    asm volatile("ldmatrix.sync.aligned.m8n8.x4.shared.b16 {%0,%1,%2,%3}, [%4];"
                 : "=r"(r[0]), "=r"(r[1]), "=r"(r[2]), "=r"(r[3]) : "r"(addr));
}
__device__ __forceinline__ void mma16816(float (&d)[4], const uint32_t (&a)[4],
                                         uint32_t b0, uint32_t b1) {
    asm volatile("mma.sync.aligned.m16n8k16.row.col.f32.bf16.bf16.f32 "
                 "{%0,%1,%2,%3}, {%4,%5,%6,%7}, {%8,%9}, {%0,%1,%2,%3};"
                 : "+f"(d[0]), "+f"(d[1]), "+f"(d[2]), "+f"(d[3])
                 : "r"(a[0]), "r"(a[1]), "r"(a[2]), "r"(a[3]), "r"(b0), "r"(b1));
}
__device__ __forceinline__ void mma16816h(float (&d)[4], const uint32_t (&a)[4],
                                          uint32_t b0, uint32_t b1) {
    asm volatile("mma.sync.aligned.m16n8k16.row.col.f32.f16.f16.f32 "
                 "{%0,%1,%2,%3}, {%4,%5,%6,%7}, {%8,%9}, {%0,%1,%2,%3};"
                 : "+f"(d[0]), "+f"(d[1]), "+f"(d[2]), "+f"(d[3])
                 : "r"(a[0]), "r"(a[1]), "r"(a[2]), "r"(a[3]), "r"(b0), "r"(b1));
}
#define CP_ASYNC16(sm, gm) \
    asm volatile("cp.async.cg.shared.global [%0], [%1], 16;" :: "r"(sm), "l"(gm) : "memory")
#define CP_COMMIT() asm volatile("cp.async.commit_group;" ::: "memory")
#define CP_WAIT(n)  asm volatile("cp.async.wait_group %0;" :: "n"(n) : "memory")

__device__ __forceinline__ void split2(float a, float b, uint32_t& h, uint32_t& l) {
    __nv_bfloat16 ha = __float2bfloat16(a), hb = __float2bfloat16(b);
    float ra = a - __bfloat162float(ha), rb = b - __bfloat162float(hb);
    __nv_bfloat162 hp; hp.x = ha; hp.y = hb;
    __nv_bfloat162 lp; lp.x = __float2bfloat16(ra); lp.y = __float2bfloat16(rb);
    h = *reinterpret_cast<uint32_t*>(&hp);
    l = *reinterpret_cast<uint32_t*>(&lp);
}
__device__ __forceinline__ uint32_t h2u(__half2 v) { return *reinterpret_cast<uint32_t*>(&v); }
__device__ __forceinline__ void hsplit2(float a, float b, uint32_t& h, uint32_t& l) {
    __half ha = __float2half_rn(a), hb = __float2half_rn(b);
    float ra = a - __half2float(ha), rb = b - __half2float(hb);
    h = h2u(__halves2half2(ha, hb));
    l = h2u(__halves2half2(__float2half_rn(ra), __float2half_rn(rb)));
}

// ================= conversion kernels ========================================
__global__ void split_kernel(const float* __restrict__ in, __nv_bfloat16* __restrict__ hi,
                             __nv_bfloat16* __restrict__ lo, int n4)
{
    int i = blockIdx.x * 256 + threadIdx.x;
    if (i >= n4) return;
    float4 v = ((const float4*)in)[i];
    uint32_t h0, l0, h1, l1;
    split2(v.x, v.y, h0, l0);
    split2(v.z, v.w, h1, l1);
    ((uint32_t*)hi)[2 * i]     = h0;
    ((uint32_t*)hi)[2 * i + 1] = h1;
    ((uint32_t*)lo)[2 * i]     = l0;
    ((uint32_t*)lo)[2 * i + 1] = l1;
}

// in: [R,C] fp32 row-major -> out hi/lo: [C,R] bf16 (transposed)
__global__ void tsplit_kernel(const float* __restrict__ in, __nv_bfloat16* __restrict__ hi,
                              __nv_bfloat16* __restrict__ lo, int R, int C)
{
    __shared__ float tile[32][33];
    const int bx = blockIdx.x << 5;
    const int by = blockIdx.y << 5;
    const int tx = threadIdx.x & 31, ty = threadIdx.x >> 5;
    #pragma unroll
    for (int r = ty; r < 32; r += 8)
        tile[r][tx] = in[(size_t)(by + r) * C + bx + tx];
    __syncthreads();
    #pragma unroll
    for (int r = ty; r < 32; r += 8) {
        float v = tile[tx][r];
        __nv_bfloat16 h = __float2bfloat16(v);
        __nv_bfloat16 l = __float2bfloat16(v - __bfloat162float(h));
        size_t o = (size_t)(bx + r) * R + by + tx;
        hi[o] = h; lo[o] = l;
    }
}

// in: [R,C] fp32 -> out: [C,R] fp16 single (transposed)
__global__ void thalf_kernel(const float* __restrict__ in, __half* __restrict__ out,
                             int R, int C)
{
    __shared__ float tile[32][33];
    const int bx = blockIdx.x << 5;
    const int by = blockIdx.y << 5;
    const int tx = threadIdx.x & 31, ty = threadIdx.x >> 5;
    #pragma unroll
    for (int r = ty; r < 32; r += 8)
        tile[r][tx] = in[(size_t)(by + r) * C + bx + tx];
    __syncthreads();
    #pragma unroll
    for (int r = ty; r < 32; r += 8)
        out[(size_t)(bx + r) * R + by + tx] = __float2half_rn(tile[tx][r]);
}

// g_v [b*T+t][c] fp32 -> g_vtf [(b*512+c)][t] fp16 single
__global__ void vthalf_kernel(const float* __restrict__ in, __half* __restrict__ out)
{
    __shared__ float tile[32][33];
    const int t0 = blockIdx.x << 5;
    const int c0 = blockIdx.y << 5;
    const int b  = blockIdx.z;
    const int tx = threadIdx.x & 31, ty = threadIdx.x >> 5;
    #pragma unroll
    for (int r = ty; r < 32; r += 8)
        tile[r][tx] = in[(size_t)(b * T_SZ + t0 + r) * KVDIM + c0 + tx];
    __syncthreads();
    #pragma unroll
    for (int r = ty; r < 32; r += 8)
        out[(size_t)(b * KVDIM + c0 + r) * T_SZ + t0 + tx] = __float2half_rn(tile[tx][r]);
}

// ================= fused QKV gemm (split-bf16, 3-pass) =======================
// C[M, 3072] = x[M,2048] @ [wq|wk|wv]^T ; epilogue: q/k rope + bf16 hi/lo, v fp32
#define BK        32
#define NKB       (GK / BK)
#define TPITCH    80
#define TILE_BY   (128 * TPITCH)
#define SOFF_AH   0
#define SOFF_AL   (1 * TILE_BY)
#define SOFF_BH   (2 * TILE_BY)
#define SOFF_BL   (3 * TILE_BY)
#define STAGE_BY  (4 * TILE_BY)
#define GEMM_SMEM (2 * STAGE_BY)

__device__ __forceinline__ void load_stage(
    const __nv_bfloat16* __restrict__ Abh, const __nv_bfloat16* __restrict__ Abl,
    const __nv_bfloat16* __restrict__ Bbh, const __nv_bfloat16* __restrict__ Bbl,
    int kof, uint32_t sbuf, int tid)
{
    #pragma unroll
    for (int i = 0; i < 2; i++) {
        const int c   = tid + (i << 8);
        const int row = c >> 2, q = c & 3;
        const size_t   go = (size_t)row * GK + kof + q * 8;
        const uint32_t so = row * TPITCH + q * 16;
        CP_ASYNC16(sbuf + SOFF_AH + so, Abh + go);
        CP_ASYNC16(sbuf + SOFF_AL + so, Abl + go);
        CP_ASYNC16(sbuf + SOFF_BH + so, Bbh + go);
        CP_ASYNC16(sbuf + SOFF_BL + so, Bbl + go);
    }
}

__global__ __launch_bounds__(256, 1)
void qkv_gemm_kernel(const __nv_bfloat16* __restrict__ Ah, const __nv_bfloat16* __restrict__ Al,
                     const __nv_bfloat16* __restrict__ Bh, const __nv_bfloat16* __restrict__ Bl,
                     __nv_bfloat16* __restrict__ Qh, __nv_bfloat16* __restrict__ Ql,
                     __nv_bfloat16* __restrict__ Kh, __nv_bfloat16* __restrict__ Kl,
                     float* __restrict__ V,
                     const float* __restrict__ fc, const float* __restrict__ fs)
{
    extern __shared__ char smem[];
    const uint32_t sbase = smem_u32(smem);
    const int tid  = threadIdx.x;
    const int lane = tid & 31, wid = tid >> 5;
    const int wm   = wid & 3,  wn  = wid >> 2;
    const int row0 = blockIdx.y << 7, col0 = blockIdx.x << 7;

    const __nv_bfloat16* Abh = Ah + (size_t)row0 * GK;
    const __nv_bfloat16* Abl = Al + (size_t)row0 * GK;
    const __nv_bfloat16* Bbh = Bh + (size_t)col0 * GK;
    const __nv_bfloat16* Bbl = Bl + (size_t)col0 * GK;

    float acc[2][8][4];
    #pragma unroll
    for (int mi = 0; mi < 2; mi++)
        #pragma unroll
        for (int ni = 0; ni < 8; ni++)
            #pragma unroll
            for (int e = 0; e < 4; e++) acc[mi][ni][e] = 0.f;

    const uint32_t a_row = wm * 32 + (lane & 15);
    const uint32_t a_col = (lane >> 4) << 4;
    const uint32_t b_rowb = wn * 64 + (lane & 7) + ((lane >> 4) << 3);
    const uint32_t b_col  = ((lane >> 3) & 1) << 4;

    load_stage(Abh, Abl, Bbh, Bbl, 0, sbase, tid);
    CP_COMMIT();

    for (int blk = 0; blk < NKB; blk++) {
        const uint32_t buf = sbase + (uint32_t)(blk & 1) * STAGE_BY;
        if (blk + 1 < NKB) {
            load_stage(Abh, Abl, Bbh, Bbl, (blk + 1) * BK,
                       sbase + (uint32_t)((blk + 1) & 1) * STAGE_BY, tid);
            CP_COMMIT();
            CP_WAIT(1);
        } else {
            CP_WAIT(0);
        }
        __syncthreads();

        #pragma unroll
        for (int ks = 0; ks < 2; ks++) {
            const uint32_t koff = ks * 32;
            uint32_t ah[2][4], al[2][4];
            #pragma unroll
            for (int mi = 0; mi < 2; mi++) {
                const uint32_t aaddr = buf + SOFF_AH + (a_row + mi * 16) * TPITCH + koff + a_col;
                ldsm4(ah[mi], aaddr);
                ldsm4(al[mi], aaddr + (SOFF_AL - SOFF_AH));
            }
            uint32_t bh[4][4], bl[4][4];
            #pragma unroll
            for (int nq = 0; nq < 4; nq++) {
                const uint32_t baddr = buf + SOFF_BH + (b_rowb + nq * 16) * TPITCH + koff + b_col;
                ldsm4(bh[nq], baddr);
                ldsm4(bl[nq], baddr + (SOFF_BL - SOFF_BH));
            }
            #pragma unroll
            for (int mi = 0; mi < 2; mi++)
                #pragma unroll
                for (int nq = 0; nq < 4; nq++)
                    #pragma unroll
                    for (int hf = 0; hf < 2; hf++) {
                        const int ni = nq * 2 + hf;
                        const uint32_t b0h = bh[nq][hf * 2], b1h = bh[nq][hf * 2 + 1];
                        const uint32_t b0l = bl[nq][hf * 2], b1l = bl[nq][hf * 2 + 1];
                        mma16816(acc[mi][ni], ah[mi], b0h, b1h);
                        mma16816(acc[mi][ni], ah[mi], b0l, b1l);
                        mma16816(acc[mi][ni], al[mi], b0h, b1h);
                    }
        }
        __syncthreads();
    }

    // ---- epilogue by region: q (rope+scale, bf16 hi/lo), k (rope, bf16 hi/lo), v (fp32)
    const int lr = lane >> 2;
    const int lc = (lane & 3) << 1;
    const int region = (col0 < DIM_) ? 0 : (col0 < DIM_ + KVDIM ? 1 : 2);
    const float qsc = 0.08838834764831845f;   // 1/sqrt(128)
    #pragma unroll
    for (int mi = 0; mi < 2; mi++) {
        #pragma unroll
        for (int ni = 0; ni < 8; ni++) {
            float* d = acc[mi][ni];
            const int r0  = row0 + wm * 32 + mi * 16 + lr;
            const int r1  = r0 + 8;
            const int col = col0 + wn * 64 + ni * 8 + lc;
            if (region != 2) {   // rope for q and k
                const int p = (col & (HDIM - 1)) >> 1;
                {
                    const int t = r0 & (T_SZ - 1);
                    const float cz = fc[t * (HDIM / 2) + p];
                    const float sz = fs[t * (HDIM / 2) + p];
                    const float xr = d[0], xi = d[1];
                    d[0] = xr * cz - xi * sz;
                    d[1] = xr * sz + xi * cz;
                }
                {
                    const int t = r1 & (T_SZ - 1);
                    const float cz = fc[t * (HDIM / 2) + p];
                    const float sz = fs[t * (HDIM / 2) + p];
                    const float xr = d[2], xi = d[3];
                    d[2] = xr * cz - xi * sz;
                    d[3] = xr * sz + xi * cz;
                }
            }
            if (region == 0) {
                uint32_t h0, l0, h1, l1;
                split2(d[0] * qsc, d[1] * qsc, h0, l0);
                split2(d[2] * qsc, d[3] * qsc, h1, l1);
                *(uint32_t*)&Qh[(size_t)r0 * DIM_ + col] = h0;
                *(uint32_t*)&Ql[(size_t)r0 * DIM_ + col] = l0;
                *(uint32_t*)&Qh[(size_t)r1 * DIM_ + col] = h1;
                *(uint32_t*)&Ql[(size_t)r1 * DIM_ + col] = l1;
            } else if (region == 1) {
                const int ck = col - DIM_;
                uint32_t h0, l0, h1, l1;
                split2(d[0], d[1], h0, l0);
                split2(d[2], d[3], h1, l1);
                *(uint32_t*)&Kh[(size_t)r0 * KVDIM + ck] = h0;
                *(uint32_t*)&Kl[(size_t)r0 * KVDIM + ck] = l0;
                *(uint32_t*)&Kh[(size_t)r1 * KVDIM + ck] = h1;
                *(uint32_t*)&Kl[(size_t)r1 * KVDIM + ck] = l1;
            } else {
                const int cv = col - DIM_ - KVDIM;
                *(float2*)(V + (size_t)r0 * KVDIM + cv) = make_float2(d[0], d[1]);
                *(float2*)(V + (size_t)r1 * KVDIM + cv) = make_float2(d[2], d[3]);
            }
        }
    }
}

// ================= O projection: 2-pass fp16 GEMM ============================
// out[M,2048] = (Ath + Atl)[M,2048] @ wo^T(fp16)[2048,2048]
#define OTILE     10240
#define OS_AH     0
#define OS_AL     OTILE
#define OS_BH     (2 * OTILE)
#define OSTAGE    (3 * OTILE)
#define OGEMM_SMEM (2 * OSTAGE)    // 61440

__device__ __forceinline__ void load_stage_o(
    const __half* __restrict__ Abh, const __half* __restrict__ Abl,
    const __half* __restrict__ Bbh, int kof, uint32_t sbuf, int tid)
{
    #pragma unroll
    for (int i = 0; i < 2; i++) {
        const int c   = tid + (i << 8);
        const int row = c >> 2, q = c & 3;
        const size_t   go = (size_t)row * GK + kof + q * 8;
        const uint32_t so = row * TPITCH + q * 16;
        CP_ASYNC16(sbuf + OS_AH + so, Abh + go);
        CP_ASYNC16(sbuf + OS_AL + so, Abl + go);
        CP_ASYNC16(sbuf + OS_BH + so, Bbh + go);
    }
}

__global__ __launch_bounds__(256, 1)
void o_gemm_kernel(const __half* __restrict__ Ah, const __half* __restrict__ Al,
                   const __half* __restrict__ Bh, float* __restrict__ C)
{
    extern __shared__ char smem[];
    const uint32_t sbase = smem_u32(smem);
    const int tid  = threadIdx.x;
    const int lane = tid & 31, wid = tid >> 5;
    const int wm   = wid & 3,  wn  = wid >> 2;
    const int row0 = blockIdx.y << 7, col0 = blockIdx.x << 7;

    const __half* Abh = Ah + (size_t)row0 * GK;
    const __half* Abl = Al + (size_t)row0 * GK;
    const __half* Bbh = Bh + (size_t)col0 * GK;

    float acc[2][8][4];
    #pragma unroll
    for (int mi = 0; mi < 2; mi++)
        #pragma unroll
        for (int ni = 0; ni < 8; ni++)
            #pragma unroll
            for (int e = 0; e < 4; e++) acc[mi][ni][e] = 0.f;

    const uint32_t a_row = wm * 32 + (lane & 15);
    const uint32_t a_col = (lane >> 4) << 4;
    const uint32_t b_rowb = wn * 64 + (lane & 7) + ((lane >> 4) << 3);
    const uint32_t b_col  = ((lane >> 3) & 1) << 4;

    load_stage_o(Abh, Abl, Bbh, 0, sbase, tid);
    CP_COMMIT();

    for (int blk = 0; blk < NKB; blk++) {
        const uint32_t buf = sbase + (uint32_t)(blk & 1) * OSTAGE;
        if (blk + 1 < NKB) {
            load_stage_o(Abh, Abl, Bbh, (blk + 1) * BK,
                         sbase + (uint32_t)((blk + 1) & 1) * OSTAGE, tid);
            CP_COMMIT();
            CP_WAIT(1);
        } else {
            CP_WAIT(0);
        }
        __syncthreads();

        #pragma unroll
        for (int ks = 0; ks < 2; ks++) {
            const uint32_t koff = ks * 32;
            uint32_t ah[2][4], al[2][4];
            #pragma unroll
            for (int mi = 0; mi < 2; mi++) {
                const uint32_t aaddr = buf + OS_AH + (a_row + mi * 16) * TPITCH + koff + a_col;
                ldsm4(ah[mi], aaddr);
                ldsm4(al[mi], aaddr + (OS_AL - OS_AH));
            }
            uint32_t bh[4][4];
            #pragma unroll
            for (int nq = 0; nq < 4; nq++) {
                const uint32_t baddr = buf + OS_BH + (b_rowb + nq * 16) * TPITCH + koff + b_col;
                ldsm4(bh[nq], baddr);
            }
            #pragma unroll
            for (int mi = 0; mi < 2; mi++)
                #pragma unroll
                for (int nq = 0; nq < 4; nq++)
                    #pragma unroll
                    for (int hf = 0; hf < 2; hf++) {
                        const int ni = nq * 2 + hf;
                        const uint32_t b0 = bh[nq][hf * 2], b1 = bh[nq][hf * 2 + 1];
                        mma16816h(acc[mi][ni], ah[mi], b0, b1);
                        mma16816h(acc[mi][ni], al[mi], b0, b1);
                    }
        }
        __syncthreads();
    }

    const int lr = lane >> 2;
    const int lc = (lane & 3) << 1;
    #pragma unroll
    for (int mi = 0; mi < 2; mi++) {
        #pragma unroll
        for (int ni = 0; ni < 8; ni++) {
            float* d = acc[mi][ni];
            const int r0  = row0 + wm * 32 + mi * 16 + lr;
            const int r1  = r0 + 8;
            const int col = col0 + wn * 64 + ni * 8 + lc;
            *(float2*)(C + (size_t)r0 * DIM_ + col) = make_float2(d[0], d[1]);
            *(float2*)(C + (size_t)r1 * DIM_ + col) = make_float2(d[2], d[3]);
        }
    }
}

// ================= tensor-core flash attention ===============================
// q-tile 128 (8 warps x 16 rows), k-tile 64. S: 3-pass bf16 hi/lo.
// PV: single-pass fp16 (P cvt to half2, V^T fp16). att out: fp16 hi/lo.
#define QPITCH 272
#define VPITCH 144
#define SM_QH  0
#define SM_QL  (128 * QPITCH)          // 34816
#define SM_KV  (2 * 128 * QPITCH)      // 69632
#define OFF_KH 0
#define OFF_KL (64 * QPITCH)           // 17408
#define OFF_V  (2 * 64 * QPITCH)       // 34816
#define KVBUF  (OFF_V + 128 * VPITCH)  // 53248
#define FLASH2_SMEM (SM_KV + 2 * KVBUF) // 176128

__device__ __forceinline__ void flash_load_kv(
    const __nv_bfloat16* __restrict__ Kh, const __nv_bfloat16* __restrict__ Kl,
    const __half* __restrict__ Vt,
    int b, int kvh, int kt, uint32_t buf, int tid)
{
    const char* gkh = (const char*)(Kh + (size_t)(b * T_SZ + kt * 64) * KVDIM + kvh * HDIM);
    const char* gkl = (const char*)(Kl + (size_t)(b * T_SZ + kt * 64) * KVDIM + kvh * HDIM);
    #pragma unroll
    for (int s = 0; s < 4; s++) {
        const int u = tid + s * 256;           // 0..1023
        const int r = u >> 4, c = (u & 15) << 4;
        CP_ASYNC16(buf + OFF_KH + r * QPITCH + c, gkh + (size_t)r * (KVDIM * 2) + c);
        CP_ASYNC16(buf + OFF_KL + r * QPITCH + c, gkl + (size_t)r * (KVDIM * 2) + c);
    }
    const char* gv = (const char*)(Vt + ((size_t)(b * KVHEAD + kvh) * HDIM) * T_SZ + kt * 64);
    #pragma unroll
    for (int s = 0; s < 4; s++) {
        const int u = tid + s * 256;           // 0..1023 (128 rows x 8 chunks)
        const int r = u >> 3, c = (u & 7) << 4;
        CP_ASYNC16(buf + OFF_V + r * VPITCH + c, gv + (size_t)r * (T_SZ * 2) + c);
    }
}

__global__ __launch_bounds__(256, 1)
void flash_mma_kernel(const __nv_bfloat16* __restrict__ Qh, const __nv_bfloat16* __restrict__ Ql,
                      const __nv_bfloat16* __restrict__ Kh, const __nv_bfloat16* __restrict__ Kl,
                      const __half* __restrict__ Vt,
                      __half* __restrict__ Ath, __half* __restrict__ Atl)
{
    extern __shared__ char smem[];
    const uint32_t sbase = smem_u32(smem);
    const int tid = threadIdx.x, lane = tid & 31, w = tid >> 5;
    const int qt = (int)gridDim.x - 1 - (int)blockIdx.x;   // heavy tiles first
    const int bh = blockIdx.y, b = bh >> 4, h = bh & 15, kvh = h >> 2;
    const int qrow0 = b * T_SZ + qt * 128;
    const int nkt = 2 * qt + 2;

    {
        const char* gqh = (const char*)(Qh + (size_t)qrow0 * DIM_ + h * HDIM);
        const char* gql = (const char*)(Ql + (size_t)qrow0 * DIM_ + h * HDIM);
        #pragma unroll
        for (int s = 0; s < 8; s++) {
            const int u = tid + s * 256;
            const int r = u >> 4, c = (u & 15) << 4;
            CP_ASYNC16(sbase + SM_QH + r * QPITCH + c, gqh + (size_t)r * (DIM_ * 2) + c);
            CP_ASYNC16(sbase + SM_QL + r * QPITCH + c, gql + (size_t)r * (DIM_ * 2) + c);
        }
    }
    flash_load_kv(Kh, Kl, Vt, b, kvh, 0, sbase + SM_KV, tid);
    CP_COMMIT();

    float sm0 = -1e30f, sm1 = -1e30f, sl0 = 0.f, sl1 = 0.f;
    float vacc[16][4];
    #pragma unroll
    for (int ni = 0; ni < 16; ni++)
        #pragma unroll
        for (int e = 0; e < 4; e++) vacc[ni][e] = 0.f;

    const int r0l = w * 16 + (lane >> 2);
    const int r1l = r0l + 8;
    const uint32_t a_addr0 = sbase + SM_QH + (w * 16 + (lane & 15)) * QPITCH + ((lane >> 4) << 4);
    const uint32_t b_roff  = ((lane & 7) + ((lane >> 4) << 3));
    const uint32_t b_coff  = ((lane >> 3) & 1) << 4;

    CP_WAIT(0);
    __syncthreads();

    for (int kt = 0; kt < nkt; kt++) {
        const uint32_t buf = sbase + SM_KV + (uint32_t)(kt & 1) * KVBUF;
        if (kt + 1 < nkt) {
            flash_load_kv(Kh, Kl, Vt, b, kvh, kt + 1,
                          sbase + SM_KV + (uint32_t)((kt + 1) & 1) * KVBUF, tid);
            CP_COMMIT();
        }

        // ---- S = Q K^T (3-pass bf16 split) ----
        float sacc[8][4];
        #pragma unroll
        for (int nj = 0; nj < 8; nj++)
            #pragma unroll
            for (int e = 0; e < 4; e++) sacc[nj][e] = 0.f;

        #pragma unroll
        for (int ks = 0; ks < 8; ks++) {
            uint32_t qh4[4], ql4[4];
            const uint32_t aaddr = a_addr0 + ks * 32;
            ldsm4(qh4, aaddr);
            ldsm4(ql4, aaddr + (SM_QL - SM_QH));
            #pragma unroll
            for (int nq = 0; nq < 4; nq++) {
                uint32_t kh4[4], kl4[4];
                const uint32_t baddr = buf + OFF_KH + (nq * 16 + b_roff) * QPITCH + ks * 32 + b_coff;
                ldsm4(kh4, baddr);
                ldsm4(kl4, baddr + (OFF_KL - OFF_KH));
                mma16816(sacc[nq * 2],     qh4, kh4[0], kh4[1]);
                mma16816(sacc[nq * 2 + 1], qh4, kh4[2], kh4[3]);
                mma16816(sacc[nq * 2],     qh4, kl4[0], kl4[1]);
                mma16816(sacc[nq * 2 + 1], qh4, kl4[2], kl4[3]);
                mma16816(sacc[nq * 2],     ql4, kh4[0], kh4[1]);
                mma16816(sacc[nq * 2 + 1], ql4, kh4[2], kh4[3]);
            }
        }

        // ---- causal mask (diagonal k-tiles) ----
        if (kt >= 2 * qt) {
            const int coff = kt * 64 - qt * 128;
            #pragma unroll
            for (int nj = 0; nj < 8; nj++) {
                const int c0 = coff + nj * 8 + (lane & 3) * 2;
                if (c0     > r0l) sacc[nj][0] = -1e30f;
                if (c0 + 1 > r0l) sacc[nj][1] = -1e30f;
                if (c0     > r1l) sacc[nj][2] = -1e30f;
                if (c0 + 1 > r1l) sacc[nj][3] = -1e30f;
            }
        }

        // ---- online softmax (register stats, bfly over lane&3) ----
        float mx0 = -1e30f, mx1 = -1e30f;
        #pragma unroll
        for (int nj = 0; nj < 8; nj++) {
            mx0 = fmaxf(mx0, fmaxf(sacc[nj][0], sacc[nj][1]));
            mx1 = fmaxf(mx1, fmaxf(sacc[nj][2], sacc[nj][3]));
        }
        mx0 = fmaxf(mx0, __shfl_xor_sync(0xFFFFFFFFu, mx0, 1));
        mx0 = fmaxf(mx0, __shfl_xor_sync(0xFFFFFFFFu, mx0, 2));
        mx1 = fmaxf(mx1, __shfl_xor_sync(0xFFFFFFFFu, mx1, 1));
        mx1 = fmaxf(mx1, __shfl_xor_sync(0xFFFFFFFFu, mx1, 2));
        const float mn0 = fmaxf(sm0, mx0), mn1 = fmaxf(sm1, mx1);
        const float al0 = __expf(sm0 - mn0), al1 = __expf(sm1 - mn1);
        sm0 = mn0; sm1 = mn1;

        // P = exp(S - m) as half2 A-fragments (single precision level)
        uint32_t pa[4][4];
        float ls0 = 0.f, ls1 = 0.f;
        #pragma unroll
        for (int j = 0; j < 4; j++) {
            #pragma unroll
            for (int t = 0; t < 2; t++) {
                const int nj = 2 * j + t;
                const float p0 = __expf(sacc[nj][0] - mn0);
                const float p1 = __expf(sacc[nj][1] - mn0);
                const float p2 = __expf(sacc[nj][2] - mn1);
                const float p3 = __expf(sacc[nj][3] - mn1);
                ls0 += p0 + p1;
                ls1 += p2 + p3;
                pa[j][t * 2]     = h2u(__floats2half2_rn(p0, p1));
                pa[j][t * 2 + 1] = h2u(__floats2half2_rn(p2, p3));
            }
        }
        ls0 += __shfl_xor_sync(0xFFFFFFFFu, ls0, 1);
        ls0 += __shfl_xor_sync(0xFFFFFFFFu, ls0, 2);
        ls1 += __shfl_xor_sync(0xFFFFFFFFu, ls1, 1);
        ls1 += __shfl_xor_sync(0xFFFFFFFFu, ls1, 2);
        sl0 = sl0 * al0 + ls0;
        sl1 = sl1 * al1 + ls1;

        #pragma unroll
        for (int ni = 0; ni < 16; ni++) {
            vacc[ni][0] *= al0; vacc[ni][1] *= al0;
            vacc[ni][2] *= al1; vacc[ni][3] *= al1;
        }

        // ---- O += P V (single-pass fp16; B = V^T fp16 [d][t]) ----
        #pragma unroll
        for (int j = 0; j < 4; j++) {
            #pragma unroll
            for (int nq = 0; nq < 8; nq++) {
                uint32_t v4[4];
                const uint32_t vaddr = buf + OFF_V + (nq * 16 + b_roff) * VPITCH + j * 32 + b_coff;
                ldsm4(v4, vaddr);
                mma16816h(vacc[nq * 2],     pa[j], v4[0], v4[1]);
                mma16816h(vacc[nq * 2 + 1], pa[j], v4[2], v4[3]);
            }
        }

        if (kt + 1 < nkt) CP_WAIT(0);
        __syncthreads();
    }

    // ---- epilogue: write att as fp16 hi/lo ----
    const float inv0 = 1.f / sl0, inv1 = 1.f / sl1;
    __half* a0h = Ath + (size_t)(qrow0 + r0l) * DIM_ + h * HDIM;
    __half* a0l = Atl + (size_t)(qrow0 + r0l) * DIM_ + h * HDIM;
    __half* a1h = Ath + (size_t)(qrow0 + r1l) * DIM_ + h * HDIM;
    __half* a1l = Atl + (size_t)(qrow0 + r1l) * DIM_ + h * HDIM;
    #pragma unroll
    for (int ni = 0; ni < 16; ni++) {
        const int col = ni * 8 + (lane & 3) * 2;
        uint32_t h0, l0, h1, l1;
        hsplit2(vacc[ni][0] * inv0, vacc[ni][1] * inv0, h0, l0);
        hsplit2(vacc[ni][2] * inv1, vacc[ni][3] * inv1, h1, l1);
        *(uint32_t*)(a0h + col) = h0;
        *(uint32_t*)(a0l + col) = l0;
        *(uint32_t*)(a1h + col) = h1;
        *(uint32_t*)(a1l + col) = l1;
    }
}

// ================= launch ====================================================
extern "C" void kernel_launch(void* const* d_in, const int* in_sizes, int n_in,
                              void* d_out, int out_size)
{
    const float* x  = (const float*)d_in[0];
    const float* fc = (const float*)d_in[1];
    const float* fs = (const float*)d_in[2];
    const float* wq = (const float*)d_in[3];
    const float* wk = (const float*)d_in[4];
    const float* wv = (const float*)d_in[5];
    const float* wo = (const float*)d_in[6];
    float* out = (float*)d_out;

    float* v;
    cudaGetSymbolAddress((void**)&v, g_v);
    __nv_bfloat16 *xh, *xl, *wth, *wtl, *qh, *ql, *kh, *kl;
    __half *wotf, *vtf, *ath, *atl;
    cudaGetSymbolAddress((void**)&xh,   g_xh);   cudaGetSymbolAddress((void**)&xl,   g_xl);
    cudaGetSymbolAddress((void**)&wth,  g_wth);  cudaGetSymbolAddress((void**)&wtl,  g_wtl);
    cudaGetSymbolAddress((void**)&wotf, g_wotf);
    cudaGetSymbolAddress((void**)&qh,   g_qh);   cudaGetSymbolAddress((void**)&ql,   g_ql);
    cudaGetSymbolAddress((void**)&kh,   g_kh);   cudaGetSymbolAddress((void**)&kl,   g_kl);
    cudaGetSymbolAddress((void**)&vtf,  g_vtf);
    cudaGetSymbolAddress((void**)&ath,  g_ath);  cudaGetSymbolAddress((void**)&atl,  g_atl);

    cudaFuncSetAttribute(qkv_gemm_kernel, cudaFuncAttributeMaxDynamicSharedMemorySize, GEMM_SMEM);
    cudaFuncSetAttribute(o_gemm_kernel,   cudaFuncAttributeMaxDynamicSharedMemorySize, OGEMM_SMEM);
    cudaFuncSetAttribute(flash_mma_kernel, cudaFuncAttributeMaxDynamicSharedMemorySize, FLASH2_SMEM);

    const int n4x = MROWS * DIM_ / 4;

    // input conversions
    split_kernel<<<n4x / 256, 256>>>(x, xh, xl, n4x);
    tsplit_kernel<<<dim3(DIM_  / 32, DIM_ / 32), 256>>>(wq, wth, wtl, GK, DIM_);
    tsplit_kernel<<<dim3(KVDIM / 32, DIM_ / 32), 256>>>(
        wk, wth + (size_t)DIM_ * GK, wtl + (size_t)DIM_ * GK, GK, KVDIM);
    tsplit_kernel<<<dim3(KVDIM / 32, DIM_ / 32), 256>>>(
        wv, wth + (size_t)(DIM_ + KVDIM) * GK, wtl + (size_t)(DIM_ + KVDIM) * GK, GK, KVDIM);
    thalf_kernel<<<dim3(DIM_ / 32, DIM_ / 32), 256>>>(wo, wotf, GK, DIM_);

    // fused q|k|v projection (rope + hi/lo epilogues)
    qkv_gemm_kernel<<<dim3(NTOT / 128, MROWS / 128), 256, GEMM_SMEM>>>(
        xh, xl, wth, wtl, qh, ql, kh, kl, v, fc, fs);

    // v -> V^T fp16
    vthalf_kernel<<<dim3(T_SZ / 32, KVDIM / 32, B_SZ), 256>>>(v, vtf);

    // attention (writes att fp16 hi/lo)
    flash_mma_kernel<<<dim3(T_SZ / 128, B_SZ * NHEAD), 256, FLASH2_SMEM>>>(
        qh, ql, kh, kl, vtf, ath, atl);

    // output projection (2-pass fp16)
    o_gemm_kernel<<<dim3(DIM_ / 128, MROWS / 128), 256, OGEMM_SMEM>>>(ath, atl, wotf, out);
}

// round 14
// speedup vs baseline: 1.5598x; 1.2924x over previous
#include <cuda_runtime.h>
#include <cuda_bf16.h>
#include <cuda_fp16.h>
#include <cstdint>

#define B_SZ   2
#define T_SZ   2048
#define DIM_   2048
#define NHEAD  16
#define KVHEAD 4
#define HDIM   128
#define MROWS  (B_SZ * T_SZ)        // 4096
#define KVDIM  (KVHEAD * HDIM)      // 512
#define GK     2048
#define NTOT   (DIM_ + 2 * KVDIM)   // 3072 concat q|k|v columns

// ================= scratch (device globals; no allocations allowed) =========
__device__ float g_v[(size_t)MROWS * KVDIM];                       // fp32 v

__device__ __align__(16) __half g_xh[(size_t)MROWS * DIM_];        // x hi fp16
__device__ __align__(16) __half g_xl[(size_t)MROWS * DIM_];        // x lo fp16
__device__ __align__(16) __half g_wtf[(size_t)NTOT * GK];          // [3072,2048] wq|wk|wv ^T fp16
__device__ __align__(16) __half g_wotf[(size_t)DIM_ * GK];         // wo^T fp16
__device__ __align__(16) __half g_qh[(size_t)MROWS * DIM_];        // q hi/lo fp16 (unscaled)
__device__ __align__(16) __half g_ql[(size_t)MROWS * DIM_];
__device__ __align__(16) __half g_kh[(size_t)MROWS * KVDIM];
__device__ __align__(16) __half g_kl[(size_t)MROWS * KVDIM];
__device__ __align__(16) __half g_vtf[(size_t)B_SZ * KVDIM * T_SZ]; // [b*512+c][t]
__device__ __align__(16) __half g_ath[(size_t)MROWS * DIM_];       // att fp16 single

// ================= helpers ===================================================
__device__ __forceinline__ uint32_t smem_u32(const void* p) {
    uint32_t a;
    asm("{ .reg .u64 t; cvta.to.shared.u64 t, %1; cvt.u32.u64 %0, t; }" : "=r"(a) : "l"(p));
    return a;
}
__device__ __forceinline__ void ldsm4(uint32_t (&r)[4], uint32_t addr) {
    asm volatile("ldmatrix.sync.aligned.m8n8.x4.shared.b16 {%0,%1,%2,%3}, [%4];"
                 : "=r"(r[0]), "=r"(r[1]), "=r"(r[2]), "=r"(r[3]) : "r"(addr));
}
__device__ __forceinline__ void mma16816h(float (&d)[4], const uint32_t (&a)[4],
                                          uint32_t b0, uint32_t b1) {
    asm volatile("mma.sync.aligned.m16n8k16.row.col.f32.f16.f16.f32 "
                 "{%0,%1,%2,%3}, {%4,%5,%6,%7}, {%8,%9}, {%0,%1,%2,%3};"
                 : "+f"(d[0]), "+f"(d[1]), "+f"(d[2]), "+f"(d[3])
                 : "r"(a[0]), "r"(a[1]), "r"(a[2]), "r"(a[3]), "r"(b0), "r"(b1));
}
#define CP_ASYNC16(sm, gm) \
    asm volatile("cp.async.cg.shared.global [%0], [%1], 16;" :: "r"(sm), "l"(gm) : "memory")
#define CP_COMMIT() asm volatile("cp.async.commit_group;" ::: "memory")
#define CP_WAIT(n)  asm volatile("cp.async.wait_group %0;" :: "n"(n) : "memory")

__device__ __forceinline__ uint32_t h2u(__half2 v) { return *reinterpret_cast<uint32_t*>(&v); }
__device__ __forceinline__ void hsplit2(float a, float b, uint32_t& h, uint32_t& l) {
    __half ha = __float2half_rn(a), hb = __float2half_rn(b);
    float ra = a - __half2float(ha), rb = b - __half2float(hb);
    h = h2u(__halves2half2(ha, hb));
    l = h2u(__halves2half2(__float2half_rn(ra), __float2half_rn(rb)));
}

// ================= conversion kernels ========================================
// x fp32 -> fp16 hi/lo
__global__ void hsplit_kernel(const float* __restrict__ in, __half* __restrict__ hi,
                              __half* __restrict__ lo, int n4)
{
    int i = blockIdx.x * 256 + threadIdx.x;
    if (i >= n4) return;
    float4 v = ((const float4*)in)[i];
    uint32_t h0, l0, h1, l1;
    hsplit2(v.x, v.y, h0, l0);
    hsplit2(v.z, v.w, h1, l1);
    ((uint32_t*)hi)[2 * i]     = h0;
    ((uint32_t*)hi)[2 * i + 1] = h1;
    ((uint32_t*)lo)[2 * i]     = l0;
    ((uint32_t*)lo)[2 * i + 1] = l1;
}

// in: [R,C] fp32 -> out: [C,R] fp16 single (transposed)
__global__ void thalf_kernel(const float* __restrict__ in, __half* __restrict__ out,
                             int R, int C)
{
    __shared__ float tile[32][33];
    const int bx = blockIdx.x << 5;
    const int by = blockIdx.y << 5;
    const int tx = threadIdx.x & 31, ty = threadIdx.x >> 5;
    #pragma unroll
    for (int r = ty; r < 32; r += 8)
        tile[r][tx] = in[(size_t)(by + r) * C + bx + tx];
    __syncthreads();
    #pragma unroll
    for (int r = ty; r < 32; r += 8)
        out[(size_t)(bx + r) * R + by + tx] = __float2half_rn(tile[tx][r]);
}

// g_v [b*T+t][c] fp32 -> g_vtf [(b*512+c)][t] fp16 single
__global__ void vthalf_kernel(const float* __restrict__ in, __half* __restrict__ out)
{
    __shared__ float tile[32][33];
    const int t0 = blockIdx.x << 5;
    const int c0 = blockIdx.y << 5;
    const int b  = blockIdx.z;
    const int tx = threadIdx.x & 31, ty = threadIdx.x >> 5;
    #pragma unroll
    for (int r = ty; r < 32; r += 8)
        tile[r][tx] = in[(size_t)(b * T_SZ + t0 + r) * KVDIM + c0 + tx];
    __syncthreads();
    #pragma unroll
    for (int r = ty; r < 32; r += 8)
        out[(size_t)(b * KVDIM + c0 + r) * T_SZ + t0 + tx] = __float2half_rn(tile[tx][r]);
}

// ================= fused QKV gemm (2-pass fp16: (Xh+Xl)·Wf) ==================
// C[M, 3072] = x[M,2048] @ [wq|wk|wv]^T ; epilogue: q/k rope + fp16 hi/lo, v fp32
#define BK        32
#define NKB       (GK / BK)
#define TPITCH    80
#define TILE_BY   (128 * TPITCH)
#define QS_AH     0
#define QS_AL     TILE_BY
#define QS_B      (2 * TILE_BY)
#define QSTAGE    (3 * TILE_BY)
#define QGEMM_SMEM (2 * QSTAGE)      // 61440

__device__ __forceinline__ void load_stage_qkv(
    const __half* __restrict__ Abh, const __half* __restrict__ Abl,
    const __half* __restrict__ Bb, int kof, uint32_t sbuf, int tid)
{
    #pragma unroll
    for (int i = 0; i < 2; i++) {
        const int c   = tid + (i << 8);
        const int row = c >> 2, q = c & 3;
        const size_t   go = (size_t)row * GK + kof + q * 8;
        const uint32_t so = row * TPITCH + q * 16;
        CP_ASYNC16(sbuf + QS_AH + so, Abh + go);
        CP_ASYNC16(sbuf + QS_AL + so, Abl + go);
        CP_ASYNC16(sbuf + QS_B  + so, Bb  + go);
    }
}

__global__ __launch_bounds__(256, 1)
void qkv_gemm_kernel(const __half* __restrict__ Ah, const __half* __restrict__ Al,
                     const __half* __restrict__ B,
                     __half* __restrict__ Qh, __half* __restrict__ Ql,
                     __half* __restrict__ Kh, __half* __restrict__ Kl,
                     float* __restrict__ V,
                     const float* __restrict__ fc, const float* __restrict__ fs)
{
    extern __shared__ char smem[];
    const uint32_t sbase = smem_u32(smem);
    const int tid  = threadIdx.x;
    const int lane = tid & 31, wid = tid >> 5;
    const int wm   = wid & 3,  wn  = wid >> 2;
    const int row0 = blockIdx.y << 7, col0 = blockIdx.x << 7;

    const __half* Abh = Ah + (size_t)row0 * GK;
    const __half* Abl = Al + (size_t)row0 * GK;
    const __half* Bb  = B  + (size_t)col0 * GK;

    float acc[2][8][4];
    #pragma unroll
    for (int mi = 0; mi < 2; mi++)
        #pragma unroll
        for (int ni = 0; ni < 8; ni++)
            #pragma unroll
            for (int e = 0; e < 4; e++) acc[mi][ni][e] = 0.f;

    const uint32_t a_row = wm * 32 + (lane & 15);
    const uint32_t a_col = (lane >> 4) << 4;
    const uint32_t b_rowb = wn * 64 + (lane & 7) + ((lane >> 4) << 3);
    const uint32_t b_col  = ((lane >> 3) & 1) << 4;

    load_stage_qkv(Abh, Abl, Bb, 0, sbase, tid);
    CP_COMMIT();

    for (int blk = 0; blk < NKB; blk++) {
        const uint32_t buf = sbase + (uint32_t)(blk & 1) * QSTAGE;
        if (blk + 1 < NKB) {
            load_stage_qkv(Abh, Abl, Bb, (blk + 1) * BK,
                           sbase + (uint32_t)((blk + 1) & 1) * QSTAGE, tid);
            CP_COMMIT();
            CP_WAIT(1);
        } else {
            CP_WAIT(0);
        }
        __syncthreads();

        #pragma unroll
        for (int ks = 0; ks < 2; ks++) {
            const uint32_t koff = ks * 32;
            uint32_t ah[2][4], al[2][4];
            #pragma unroll
            for (int mi = 0; mi < 2; mi++) {
                const uint32_t aaddr = buf + QS_AH + (a_row + mi * 16) * TPITCH + koff + a_col;
                ldsm4(ah[mi], aaddr);
                ldsm4(al[mi], aaddr + (QS_AL - QS_AH));
            }
            uint32_t bf[4][4];
            #pragma unroll
            for (int nq = 0; nq < 4; nq++) {
                const uint32_t baddr = buf + QS_B + (b_rowb + nq * 16) * TPITCH + koff + b_col;
                ldsm4(bf[nq], baddr);
            }
            #pragma unroll
            for (int mi = 0; mi < 2; mi++)
                #pragma unroll
                for (int nq = 0; nq < 4; nq++)
                    #pragma unroll
                    for (int hf = 0; hf < 2; hf++) {
                        const int ni = nq * 2 + hf;
                        const uint32_t b0 = bf[nq][hf * 2], b1 = bf[nq][hf * 2 + 1];
                        mma16816h(acc[mi][ni], ah[mi], b0, b1);
                        mma16816h(acc[mi][ni], al[mi], b0, b1);
                    }
        }
        __syncthreads();
    }

    // ---- epilogue by region: q/k rope + fp16 hi/lo (unscaled), v fp32 ----
    const int lr = lane >> 2;
    const int lc = (lane & 3) << 1;
    const int region = (col0 < DIM_) ? 0 : (col0 < DIM_ + KVDIM ? 1 : 2);
    #pragma unroll
    for (int mi = 0; mi < 2; mi++) {
        #pragma unroll
        for (int ni = 0; ni < 8; ni++) {
            float* d = acc[mi][ni];
            const int r0  = row0 + wm * 32 + mi * 16 + lr;
            const int r1  = r0 + 8;
            const int col = col0 + wn * 64 + ni * 8 + lc;
            if (region != 2) {
                const int p = (col & (HDIM - 1)) >> 1;
                {
                    const int t = r0 & (T_SZ - 1);
                    const float cz = fc[t * (HDIM / 2) + p];
                    const float sz = fs[t * (HDIM / 2) + p];
                    const float xr = d[0], xi = d[1];
                    d[0] = xr * cz - xi * sz;
                    d[1] = xr * sz + xi * cz;
                }
                {
                    const int t = r1 & (T_SZ - 1);
                    const float cz = fc[t * (HDIM / 2) + p];
                    const float sz = fs[t * (HDIM / 2) + p];
                    const float xr = d[2], xi = d[3];
                    d[2] = xr * cz - xi * sz;
                    d[3] = xr * sz + xi * cz;
                }
            }
            if (region == 0) {
                uint32_t h0, l0, h1, l1;
                hsplit2(d[0], d[1], h0, l0);
                hsplit2(d[2], d[3], h1, l1);
                *(uint32_t*)&Qh[(size_t)r0 * DIM_ + col] = h0;
                *(uint32_t*)&Ql[(size_t)r0 * DIM_ + col] = l0;
                *(uint32_t*)&Qh[(size_t)r1 * DIM_ + col] = h1;
                *(uint32_t*)&Ql[(size_t)r1 * DIM_ + col] = l1;
            } else if (region == 1) {
                const int ck = col - DIM_;
                uint32_t h0, l0, h1, l1;
                hsplit2(d[0], d[1], h0, l0);
                hsplit2(d[2], d[3], h1, l1);
                *(uint32_t*)&Kh[(size_t)r0 * KVDIM + ck] = h0;
                *(uint32_t*)&Kl[(size_t)r0 * KVDIM + ck] = l0;
                *(uint32_t*)&Kh[(size_t)r1 * KVDIM + ck] = h1;
                *(uint32_t*)&Kl[(size_t)r1 * KVDIM + ck] = l1;
            } else {
                const int cv = col - DIM_ - KVDIM;
                *(float2*)(V + (size_t)r0 * KVDIM + cv) = make_float2(d[0], d[1]);
                *(float2*)(V + (size_t)r1 * KVDIM + cv) = make_float2(d[2], d[3]);
            }
        }
    }
}

// ================= O projection: 1-pass fp16 GEMM ============================
// out[M,2048] = att(fp16)[M,2048] @ wo^T(fp16)[2048,2048]
#define OS_A      0
#define OS_B      TILE_BY
#define OSTAGE    (2 * TILE_BY)
#define OGEMM_SMEM (2 * OSTAGE)      // 40960

__device__ __forceinline__ void load_stage_o(
    const __half* __restrict__ Ab, const __half* __restrict__ Bb,
    int kof, uint32_t sbuf, int tid)
{
    #pragma unroll
    for (int i = 0; i < 2; i++) {
        const int c   = tid + (i << 8);
        const int row = c >> 2, q = c & 3;
        const size_t   go = (size_t)row * GK + kof + q * 8;
        const uint32_t so = row * TPITCH + q * 16;
        CP_ASYNC16(sbuf + OS_A + so, Ab + go);
        CP_ASYNC16(sbuf + OS_B + so, Bb + go);
    }
}

__global__ __launch_bounds__(256, 1)
void o_gemm_kernel(const __half* __restrict__ A, const __half* __restrict__ B,
                   float* __restrict__ C)
{
    extern __shared__ char smem[];
    const uint32_t sbase = smem_u32(smem);
    const int tid  = threadIdx.x;
    const int lane = tid & 31, wid = tid >> 5;
    const int wm   = wid & 3,  wn  = wid >> 2;
    const int row0 = blockIdx.y << 7, col0 = blockIdx.x << 7;

    const __half* Ab = A + (size_t)row0 * GK;
    const __half* Bb = B + (size_t)col0 * GK;

    float acc[2][8][4];
    #pragma unroll
    for (int mi = 0; mi < 2; mi++)
        #pragma unroll
        for (int ni = 0; ni < 8; ni++)
            #pragma unroll
            for (int e = 0; e < 4; e++) acc[mi][ni][e] = 0.f;

    const uint32_t a_row = wm * 32 + (lane & 15);
    const uint32_t a_col = (lane >> 4) << 4;
    const uint32_t b_rowb = wn * 64 + (lane & 7) + ((lane >> 4) << 3);
    const uint32_t b_col  = ((lane >> 3) & 1) << 4;

    load_stage_o(Ab, Bb, 0, sbase, tid);
    CP_COMMIT();

    for (int blk = 0; blk < NKB; blk++) {
        const uint32_t buf = sbase + (uint32_t)(blk & 1) * OSTAGE;
        if (blk + 1 < NKB) {
            load_stage_o(Ab, Bb, (blk + 1) * BK,
                         sbase + (uint32_t)((blk + 1) & 1) * OSTAGE, tid);
            CP_COMMIT();
            CP_WAIT(1);
        } else {
            CP_WAIT(0);
        }
        __syncthreads();

        #pragma unroll
        for (int ks = 0; ks < 2; ks++) {
            const uint32_t koff = ks * 32;
            uint32_t af[2][4];
            #pragma unroll
            for (int mi = 0; mi < 2; mi++) {
                const uint32_t aaddr = buf + OS_A + (a_row + mi * 16) * TPITCH + koff + a_col;
                ldsm4(af[mi], aaddr);
            }
            uint32_t bf[4][4];
            #pragma unroll
            for (int nq = 0; nq < 4; nq++) {
                const uint32_t baddr = buf + OS_B + (b_rowb + nq * 16) * TPITCH + koff + b_col;
                ldsm4(bf[nq], baddr);
            }
            #pragma unroll
            for (int mi = 0; mi < 2; mi++)
                #pragma unroll
                for (int nq = 0; nq < 4; nq++)
                    #pragma unroll
                    for (int hf = 0; hf < 2; hf++) {
                        const int ni = nq * 2 + hf;
                        mma16816h(acc[mi][ni], af[mi], bf[nq][hf * 2], bf[nq][hf * 2 + 1]);
                    }
        }
        __syncthreads();
    }

    const int lr = lane >> 2;
    const int lc = (lane & 3) << 1;
    #pragma unroll
    for (int mi = 0; mi < 2; mi++) {
        #pragma unroll
        for (int ni = 0; ni < 8; ni++) {
            float* d = acc[mi][ni];
            const int r0  = row0 + wm * 32 + mi * 16 + lr;
            const int r1  = r0 + 8;
            const int col = col0 + wn * 64 + ni * 8 + lc;
            *(float2*)(C + (size_t)r0 * DIM_ + col) = make_float2(d[0], d[1]);
            *(float2*)(C + (size_t)r1 * DIM_ + col) = make_float2(d[2], d[3]);
        }
    }
}

// ================= tensor-core flash attention ===============================
// q-tile 128 (8 warps x 16 rows), k-tile 64. S: 3-pass fp16 hi/lo (Q unscaled,
// 1/sqrt(128) applied to logits post-mma). PV: single fp16. att out: fp16.
#define QPITCH 272
#define VPITCH 144
#define SM_QH  0
#define SM_QL  (128 * QPITCH)          // 34816
#define SM_KV  (2 * 128 * QPITCH)      // 69632
#define OFF_KH 0
#define OFF_KL (64 * QPITCH)           // 17408
#define OFF_V  (2 * 64 * QPITCH)       // 34816
#define KVBUF  (OFF_V + 128 * VPITCH)  // 53248
#define FLASH2_SMEM (SM_KV + 2 * KVBUF) // 176128

__device__ __forceinline__ void flash_load_kv(
    const __half* __restrict__ Kh, const __half* __restrict__ Kl,
    const __half* __restrict__ Vt,
    int b, int kvh, int kt, uint32_t buf, int tid)
{
    const char* gkh = (const char*)(Kh + (size_t)(b * T_SZ + kt * 64) * KVDIM + kvh * HDIM);
    const char* gkl = (const char*)(Kl + (size_t)(b * T_SZ + kt * 64) * KVDIM + kvh * HDIM);
    #pragma unroll
    for (int s = 0; s < 4; s++) {
        const int u = tid + s * 256;           // 0..1023
        const int r = u >> 4, c = (u & 15) << 4;
        CP_ASYNC16(buf + OFF_KH + r * QPITCH + c, gkh + (size_t)r * (KVDIM * 2) + c);
        CP_ASYNC16(buf + OFF_KL + r * QPITCH + c, gkl + (size_t)r * (KVDIM * 2) + c);
    }
    const char* gv = (const char*)(Vt + ((size_t)(b * KVHEAD + kvh) * HDIM) * T_SZ + kt * 64);
    #pragma unroll
    for (int s = 0; s < 4; s++) {
        const int u = tid + s * 256;           // 128 rows x 8 chunks
        const int r = u >> 3, c = (u & 7) << 4;
        CP_ASYNC16(buf + OFF_V + r * VPITCH + c, gv + (size_t)r * (T_SZ * 2) + c);
    }
}

__global__ __launch_bounds__(256, 1)
void flash_mma_kernel(const __half* __restrict__ Qh, const __half* __restrict__ Ql,
                      const __half* __restrict__ Kh, const __half* __restrict__ Kl,
                      const __half* __restrict__ Vt, __half* __restrict__ At)
{
    extern __shared__ char smem[];
    const uint32_t sbase = smem_u32(smem);
    const int tid = threadIdx.x, lane = tid & 31, w = tid >> 5;
    const int qt = (int)gridDim.x - 1 - (int)blockIdx.x;   // heavy tiles first
    const int bh = blockIdx.y, b = bh >> 4, h = bh & 15, kvh = h >> 2;
    const int qrow0 = b * T_SZ + qt * 128;
    const int nkt = 2 * qt + 2;
    const float qsc = 0.08838834764831845f;   // 1/sqrt(128)

    {
        const char* gqh = (const char*)(Qh + (size_t)qrow0 * DIM_ + h * HDIM);
        const char* gql = (const char*)(Ql + (size_t)qrow0 * DIM_ + h * HDIM);
        #pragma unroll
        for (int s = 0; s < 8; s++) {
            const int u = tid + s * 256;
            const int r = u >> 4, c = (u & 15) << 4;
            CP_ASYNC16(sbase + SM_QH + r * QPITCH + c, gqh + (size_t)r * (DIM_ * 2) + c);
            CP_ASYNC16(sbase + SM_QL + r * QPITCH + c, gql + (size_t)r * (DIM_ * 2) + c);
        }
    }
    flash_load_kv(Kh, Kl, Vt, b, kvh, 0, sbase + SM_KV, tid);
    CP_COMMIT();

    float sm0 = -1e30f, sm1 = -1e30f, sl0 = 0.f, sl1 = 0.f;
    float vacc[16][4];
    #pragma unroll
    for (int ni = 0; ni < 16; ni++)
        #pragma unroll
        for (int e = 0; e < 4; e++) vacc[ni][e] = 0.f;

    const int r0l = w * 16 + (lane >> 2);
    const int r1l = r0l + 8;
    const uint32_t a_addr0 = sbase + SM_QH + (w * 16 + (lane & 15)) * QPITCH + ((lane >> 4) << 4);
    const uint32_t b_roff  = ((lane & 7) + ((lane >> 4) << 3));
    const uint32_t b_coff  = ((lane >> 3) & 1) << 4;

    CP_WAIT(0);
    __syncthreads();

    for (int kt = 0; kt < nkt; kt++) {
        const uint32_t buf = sbase + SM_KV + (uint32_t)(kt & 1) * KVBUF;
        if (kt + 1 < nkt) {
            flash_load_kv(Kh, Kl, Vt, b, kvh, kt + 1,
                          sbase + SM_KV + (uint32_t)((kt + 1) & 1) * KVBUF, tid);
            CP_COMMIT();
        }

        // ---- S = Q K^T (3-pass fp16 split) ----
        float sacc[8][4];
        #pragma unroll
        for (int nj = 0; nj < 8; nj++)
            #pragma unroll
            for (int e = 0; e < 4; e++) sacc[nj][e] = 0.f;

        #pragma unroll
        for (int ks = 0; ks < 8; ks++) {
            uint32_t qh4[4], ql4[4];
            const uint32_t aaddr = a_addr0 + ks * 32;
            ldsm4(qh4, aaddr);
            ldsm4(ql4, aaddr + (SM_QL - SM_QH));
            #pragma unroll
            for (int nq = 0; nq < 4; nq++) {
                uint32_t kh4[4], kl4[4];
                const uint32_t baddr = buf + OFF_KH + (nq * 16 + b_roff) * QPITCH + ks * 32 + b_coff;
                ldsm4(kh4, baddr);
                ldsm4(kl4, baddr + (OFF_KL - OFF_KH));
                mma16816h(sacc[nq * 2],     qh4, kh4[0], kh4[1]);
                mma16816h(sacc[nq * 2 + 1], qh4, kh4[2], kh4[3]);
                mma16816h(sacc[nq * 2],     qh4, kl4[0], kl4[1]);
                mma16816h(sacc[nq * 2 + 1], qh4, kl4[2], kl4[3]);
                mma16816h(sacc[nq * 2],     ql4, kh4[0], kh4[1]);
                mma16816h(sacc[nq * 2 + 1], ql4, kh4[2], kh4[3]);
            }
        }

        // scale logits, then causal mask (diagonal k-tiles)
        #pragma unroll
        for (int nj = 0; nj < 8; nj++)
            #pragma unroll
            for (int e = 0; e < 4; e++) sacc[nj][e] *= qsc;

        if (kt >= 2 * qt) {
            const int coff = kt * 64 - qt * 128;
            #pragma unroll
            for (int nj = 0; nj < 8; nj++) {
                const int c0 = coff + nj * 8 + (lane & 3) * 2;
                if (c0     > r0l) sacc[nj][0] = -1e30f;
                if (c0 + 1 > r0l) sacc[nj][1] = -1e30f;
                if (c0     > r1l) sacc[nj][2] = -1e30f;
                if (c0 + 1 > r1l) sacc[nj][3] = -1e30f;
            }
        }

        // ---- online softmax (register stats, bfly over lane&3) ----
        float mx0 = -1e30f, mx1 = -1e30f;
        #pragma unroll
        for (int nj = 0; nj < 8; nj++) {
            mx0 = fmaxf(mx0, fmaxf(sacc[nj][0], sacc[nj][1]));
            mx1 = fmaxf(mx1, fmaxf(sacc[nj][2], sacc[nj][3]));
        }
        mx0 = fmaxf(mx0, __shfl_xor_sync(0xFFFFFFFFu, mx0, 1));
        mx0 = fmaxf(mx0, __shfl_xor_sync(0xFFFFFFFFu, mx0, 2));
        mx1 = fmaxf(mx1, __shfl_xor_sync(0xFFFFFFFFu, mx1, 1));
        mx1 = fmaxf(mx1, __shfl_xor_sync(0xFFFFFFFFu, mx1, 2));
        const float mn0 = fmaxf(sm0, mx0), mn1 = fmaxf(sm1, mx1);
        const float al0 = __expf(sm0 - mn0), al1 = __expf(sm1 - mn1);
        sm0 = mn0; sm1 = mn1;

        // P = exp(S - m) as half2 A-fragments
        uint32_t pa[4][4];
        float ls0 = 0.f, ls1 = 0.f;
        #pragma unroll
        for (int j = 0; j < 4; j++) {
            #pragma unroll
            for (int t = 0; t < 2; t++) {
                const int nj = 2 * j + t;
                const float p0 = __expf(sacc[nj][0] - mn0);
                const float p1 = __expf(sacc[nj][1] - mn0);
                const float p2 = __expf(sacc[nj][2] - mn1);
                const float p3 = __expf(sacc[nj][3] - mn1);
                ls0 += p0 + p1;
                ls1 += p2 + p3;
                pa[j][t * 2]     = h2u(__floats2half2_rn(p0, p1));
                pa[j][t * 2 + 1] = h2u(__floats2half2_rn(p2, p3));
            }
        }
        ls0 += __shfl_xor_sync(0xFFFFFFFFu, ls0, 1);
        ls0 += __shfl_xor_sync(0xFFFFFFFFu, ls0, 2);
        ls1 += __shfl_xor_sync(0xFFFFFFFFu, ls1, 1);
        ls1 += __shfl_xor_sync(0xFFFFFFFFu, ls1, 2);
        sl0 = sl0 * al0 + ls0;
        sl1 = sl1 * al1 + ls1;

        #pragma unroll
        for (int ni = 0; ni < 16; ni++) {
            vacc[ni][0] *= al0; vacc[ni][1] *= al0;
            vacc[ni][2] *= al1; vacc[ni][3] *= al1;
        }

        // ---- O += P V (single fp16; B = V^T fp16 [d][t]) ----
        #pragma unroll
        for (int j = 0; j < 4; j++) {
            #pragma unroll
            for (int nq = 0; nq < 8; nq++) {
                uint32_t v4[4];
                const uint32_t vaddr = buf + OFF_V + (nq * 16 + b_roff) * VPITCH + j * 32 + b_coff;
                ldsm4(v4, vaddr);
                mma16816h(vacc[nq * 2],     pa[j], v4[0], v4[1]);
                mma16816h(vacc[nq * 2 + 1], pa[j], v4[2], v4[3]);
            }
        }

        if (kt + 1 < nkt) CP_WAIT(0);
        __syncthreads();
    }

    // ---- epilogue: write att as fp16 single ----
    const float inv0 = 1.f / sl0, inv1 = 1.f / sl1;
    __half* a0 = At + (size_t)(qrow0 + r0l) * DIM_ + h * HDIM;
    __half* a1 = At + (size_t)(qrow0 + r1l) * DIM_ + h * HDIM;
    #pragma unroll
    for (int ni = 0; ni < 16; ni++) {
        const int col = ni * 8 + (lane & 3) * 2;
        *(uint32_t*)(a0 + col) = h2u(__floats2half2_rn(vacc[ni][0] * inv0, vacc[ni][1] * inv0));
        *(uint32_t*)(a1 + col) = h2u(__floats2half2_rn(vacc[ni][2] * inv1, vacc[ni][3] * inv1));
    }
}

// ================= launch ====================================================
extern "C" void kernel_launch(void* const* d_in, const int* in_sizes, int n_in,
                              void* d_out, int out_size)
{
    const float* x  = (const float*)d_in[0];
    const float* fc = (const float*)d_in[1];
    const float* fs = (const float*)d_in[2];
    const float* wq = (const float*)d_in[3];
    const float* wk = (const float*)d_in[4];
    const float* wv = (const float*)d_in[5];
    const float* wo = (const float*)d_in[6];
    float* out = (float*)d_out;

    float* v;
    cudaGetSymbolAddress((void**)&v, g_v);
    __half *xh, *xl, *wtf, *wotf, *qh, *ql, *kh, *kl, *vtf, *ath;
    cudaGetSymbolAddress((void**)&xh,   g_xh);   cudaGetSymbolAddress((void**)&xl,   g_xl);
    cudaGetSymbolAddress((void**)&wtf,  g_wtf);  cudaGetSymbolAddress((void**)&wotf, g_wotf);
    cudaGetSymbolAddress((void**)&qh,   g_qh);   cudaGetSymbolAddress((void**)&ql,   g_ql);
    cudaGetSymbolAddress((void**)&kh,   g_kh);   cudaGetSymbolAddress((void**)&kl,   g_kl);
    cudaGetSymbolAddress((void**)&vtf,  g_vtf);  cudaGetSymbolAddress((void**)&ath,  g_ath);

    cudaFuncSetAttribute(qkv_gemm_kernel, cudaFuncAttributeMaxDynamicSharedMemorySize, QGEMM_SMEM);
    cudaFuncSetAttribute(o_gemm_kernel,   cudaFuncAttributeMaxDynamicSharedMemorySize, OGEMM_SMEM);
    cudaFuncSetAttribute(flash_mma_kernel, cudaFuncAttributeMaxDynamicSharedMemorySize, FLASH2_SMEM);

    const int n4x = MROWS * DIM_ / 4;

    // input conversions (x hi/lo fp16; weights single fp16, transposed)
    hsplit_kernel<<<n4x / 256, 256>>>(x, xh, xl, n4x);
    thalf_kernel<<<dim3(DIM_  / 32, DIM_ / 32), 256>>>(wq, wtf, GK, DIM_);
    thalf_kernel<<<dim3(KVDIM / 32, DIM_ / 32), 256>>>(wk, wtf + (size_t)DIM_ * GK, GK, KVDIM);
    thalf_kernel<<<dim3(KVDIM / 32, DIM_ / 32), 256>>>(
        wv, wtf + (size_t)(DIM_ + KVDIM) * GK, GK, KVDIM);
    thalf_kernel<<<dim3(DIM_ / 32, DIM_ / 32), 256>>>(wo, wotf, GK, DIM_);

    // fused q|k|v projection (2-pass fp16; rope + hi/lo epilogues)
    qkv_gemm_kernel<<<dim3(NTOT / 128, MROWS / 128), 256, QGEMM_SMEM>>>(
        xh, xl, wtf, qh, ql, kh, kl, v, fc, fs);

    // v -> V^T fp16
    vthalf_kernel<<<dim3(T_SZ / 32, KVDIM / 32, B_SZ), 256>>>(v, vtf);

    // attention (S 3-pass fp16, PV single fp16; att fp16)
    flash_mma_kernel<<<dim3(T_SZ / 128, B_SZ * NHEAD), 256, FLASH2_SMEM>>>(
        qh, ql, kh, kl, vtf, ath);

    // output projection (1-pass fp16)
    o_gemm_kernel<<<dim3(DIM_ / 128, MROWS / 128), 256, OGEMM_SMEM>>>(ath, wotf, out);
}

// round 15
// speedup vs baseline: 1.7365x; 1.1133x over previous
#include <cuda_runtime.h>
#include <cuda_bf16.h>
#include <cuda_fp16.h>
#include <cstdint>

#define B_SZ   2
#define T_SZ   2048
#define DIM_   2048
#define NHEAD  16
#define KVHEAD 4
#define HDIM   128
#define MROWS  (B_SZ * T_SZ)        // 4096
#define KVDIM  (KVHEAD * HDIM)      // 512
#define GK     2048
#define NTOT   (DIM_ + 2 * KVDIM)   // 3072 concat q|k|v columns

// ================= scratch (device globals; no allocations allowed) =========
__device__ float g_v[(size_t)MROWS * KVDIM];                       // fp32 v

__device__ __align__(16) __half g_xh[(size_t)MROWS * DIM_];        // x hi fp16
__device__ __align__(16) __half g_xl[(size_t)MROWS * DIM_];        // x lo fp16
__device__ __align__(16) __half g_wtf[(size_t)NTOT * GK];          // [3072,2048] wq|wk|wv ^T fp16
__device__ __align__(16) __half g_wotf[(size_t)DIM_ * GK];         // wo^T fp16
__device__ __align__(16) __half g_qf[(size_t)MROWS * DIM_];        // q fp16 (scaled by 1/sqrt(128))
__device__ __align__(16) __half g_kf[(size_t)MROWS * KVDIM];       // k fp16
__device__ __align__(16) __half g_vtf[(size_t)B_SZ * KVDIM * T_SZ]; // [b*512+c][t]
__device__ __align__(16) __half g_ath[(size_t)MROWS * DIM_];       // att fp16 single

// ================= helpers ===================================================
__device__ __forceinline__ uint32_t smem_u32(const void* p) {
    uint32_t a;
    asm("{ .reg .u64 t; cvta.to.shared.u64 t, %1; cvt.u32.u64 %0, t; }" : "=r"(a) : "l"(p));
    return a;
}
__device__ __forceinline__ void ldsm4(uint32_t (&r)[4], uint32_t addr) {
    asm volatile("ldmatrix.sync.aligned.m8n8.x4.shared.b16 {%0,%1,%2,%3}, [%4];"
                 : "=r"(r[0]), "=r"(r[1]), "=r"(r[2]), "=r"(r[3]) : "r"(addr));
}
__device__ __forceinline__ void mma16816h(float (&d)[4], const uint32_t (&a)[4],
                                          uint32_t b0, uint32_t b1) {
    asm volatile("mma.sync.aligned.m16n8k16.row.col.f32.f16.f16.f32 "
                 "{%0,%1,%2,%3}, {%4,%5,%6,%7}, {%8,%9}, {%0,%1,%2,%3};"
                 : "+f"(d[0]), "+f"(d[1]), "+f"(d[2]), "+f"(d[3])
                 : "r"(a[0]), "r"(a[1]), "r"(a[2]), "r"(a[3]), "r"(b0), "r"(b1));
}
#define CP_ASYNC16(sm, gm) \
    asm volatile("cp.async.cg.shared.global [%0], [%1], 16;" :: "r"(sm), "l"(gm) : "memory")
#define CP_COMMIT() asm volatile("cp.async.commit_group;" ::: "memory")
#define CP_WAIT(n)  asm volatile("cp.async.wait_group %0;" :: "n"(n) : "memory")

__device__ __forceinline__ uint32_t h2u(__half2 v) { return *reinterpret_cast<uint32_t*>(&v); }
__device__ __forceinline__ void hsplit2(float a, float b, uint32_t& h, uint32_t& l) {
    __half ha = __float2half_rn(a), hb = __float2half_rn(b);
    float ra = a - __half2float(ha), rb = b - __half2float(hb);
    h = h2u(__halves2half2(ha, hb));
    l = h2u(__halves2half2(__float2half_rn(ra), __float2half_rn(rb)));
}

// ================= conversion kernels ========================================
// x fp32 -> fp16 hi/lo
__global__ void hsplit_kernel(const float* __restrict__ in, __half* __restrict__ hi,
                              __half* __restrict__ lo, int n4)
{
    int i = blockIdx.x * 256 + threadIdx.x;
    if (i >= n4) return;
    float4 v = ((const float4*)in)[i];
    uint32_t h0, l0, h1, l1;
    hsplit2(v.x, v.y, h0, l0);
    hsplit2(v.z, v.w, h1, l1);
    ((uint32_t*)hi)[2 * i]     = h0;
    ((uint32_t*)hi)[2 * i + 1] = h1;
    ((uint32_t*)lo)[2 * i]     = l0;
    ((uint32_t*)lo)[2 * i + 1] = l1;
}

// in: [R,C] fp32 -> out: [C,R] fp16 single (transposed)
__global__ void thalf_kernel(const float* __restrict__ in, __half* __restrict__ out,
                             int R, int C)
{
    __shared__ float tile[32][33];
    const int bx = blockIdx.x << 5;
    const int by = blockIdx.y << 5;
    const int tx = threadIdx.x & 31, ty = threadIdx.x >> 5;
    #pragma unroll
    for (int r = ty; r < 32; r += 8)
        tile[r][tx] = in[(size_t)(by + r) * C + bx + tx];
    __syncthreads();
    #pragma unroll
    for (int r = ty; r < 32; r += 8)
        out[(size_t)(bx + r) * R + by + tx] = __float2half_rn(tile[tx][r]);
}

// g_v [b*T+t][c] fp32 -> g_vtf [(b*512+c)][t] fp16 single
__global__ void vthalf_kernel(const float* __restrict__ in, __half* __restrict__ out)
{
    __shared__ float tile[32][33];
    const int t0 = blockIdx.x << 5;
    const int c0 = blockIdx.y << 5;
    const int b  = blockIdx.z;
    const int tx = threadIdx.x & 31, ty = threadIdx.x >> 5;
    #pragma unroll
    for (int r = ty; r < 32; r += 8)
        tile[r][tx] = in[(size_t)(b * T_SZ + t0 + r) * KVDIM + c0 + tx];
    __syncthreads();
    #pragma unroll
    for (int r = ty; r < 32; r += 8)
        out[(size_t)(b * KVDIM + c0 + r) * T_SZ + t0 + tx] = __float2half_rn(tile[tx][r]);
}

// ================= fused QKV gemm (2-pass fp16: (Xh+Xl)·Wf) ==================
// C[M, 3072] = x[M,2048] @ [wq|wk|wv]^T ; epilogue: q(rope*scale)/k(rope) fp16, v fp32
#define BK        32
#define NKB       (GK / BK)
#define TPITCH    80
#define TILE_BY   (128 * TPITCH)
#define QS_AH     0
#define QS_AL     TILE_BY
#define QS_B      (2 * TILE_BY)
#define QSTAGE    (3 * TILE_BY)
#define QGEMM_SMEM (2 * QSTAGE)      // 61440

__device__ __forceinline__ void load_stage_qkv(
    const __half* __restrict__ Abh, const __half* __restrict__ Abl,
    const __half* __restrict__ Bb, int kof, uint32_t sbuf, int tid)
{
    #pragma unroll
    for (int i = 0; i < 2; i++) {
        const int c   = tid + (i << 8);
        const int row = c >> 2, q = c & 3;
        const size_t   go = (size_t)row * GK + kof + q * 8;
        const uint32_t so = row * TPITCH + q * 16;
        CP_ASYNC16(sbuf + QS_AH + so, Abh + go);
        CP_ASYNC16(sbuf + QS_AL + so, Abl + go);
        CP_ASYNC16(sbuf + QS_B  + so, Bb  + go);
    }
}

__global__ __launch_bounds__(256, 1)
void qkv_gemm_kernel(const __half* __restrict__ Ah, const __half* __restrict__ Al,
                     const __half* __restrict__ B,
                     __half* __restrict__ Qf, __half* __restrict__ Kf,
                     float* __restrict__ V,
                     const float* __restrict__ fc, const float* __restrict__ fs)
{
    extern __shared__ char smem[];
    const uint32_t sbase = smem_u32(smem);
    const int tid  = threadIdx.x;
    const int lane = tid & 31, wid = tid >> 5;
    const int wm   = wid & 3,  wn  = wid >> 2;
    const int row0 = blockIdx.y << 7, col0 = blockIdx.x << 7;

    const __half* Abh = Ah + (size_t)row0 * GK;
    const __half* Abl = Al + (size_t)row0 * GK;
    const __half* Bb  = B  + (size_t)col0 * GK;

    float acc[2][8][4];
    #pragma unroll
    for (int mi = 0; mi < 2; mi++)
        #pragma unroll
        for (int ni = 0; ni < 8; ni++)
            #pragma unroll
            for (int e = 0; e < 4; e++) acc[mi][ni][e] = 0.f;

    const uint32_t a_row = wm * 32 + (lane & 15);
    const uint32_t a_col = (lane >> 4) << 4;
    const uint32_t b_rowb = wn * 64 + (lane & 7) + ((lane >> 4) << 3);
    const uint32_t b_col  = ((lane >> 3) & 1) << 4;

    load_stage_qkv(Abh, Abl, Bb, 0, sbase, tid);
    CP_COMMIT();

    for (int blk = 0; blk < NKB; blk++) {
        const uint32_t buf = sbase + (uint32_t)(blk & 1) * QSTAGE;
        if (blk + 1 < NKB) {
            load_stage_qkv(Abh, Abl, Bb, (blk + 1) * BK,
                           sbase + (uint32_t)((blk + 1) & 1) * QSTAGE, tid);
            CP_COMMIT();
            CP_WAIT(1);
        } else {
            CP_WAIT(0);
        }
        __syncthreads();

        #pragma unroll
        for (int ks = 0; ks < 2; ks++) {
            const uint32_t koff = ks * 32;
            uint32_t ah[2][4], al[2][4];
            #pragma unroll
            for (int mi = 0; mi < 2; mi++) {
                const uint32_t aaddr = buf + QS_AH + (a_row + mi * 16) * TPITCH + koff + a_col;
                ldsm4(ah[mi], aaddr);
                ldsm4(al[mi], aaddr + (QS_AL - QS_AH));
            }
            uint32_t bf[4][4];
            #pragma unroll
            for (int nq = 0; nq < 4; nq++) {
                const uint32_t baddr = buf + QS_B + (b_rowb + nq * 16) * TPITCH + koff + b_col;
                ldsm4(bf[nq], baddr);
            }
            #pragma unroll
            for (int mi = 0; mi < 2; mi++)
                #pragma unroll
                for (int nq = 0; nq < 4; nq++)
                    #pragma unroll
                    for (int hf = 0; hf < 2; hf++) {
                        const int ni = nq * 2 + hf;
                        const uint32_t b0 = bf[nq][hf * 2], b1 = bf[nq][hf * 2 + 1];
                        mma16816h(acc[mi][ni], ah[mi], b0, b1);
                        mma16816h(acc[mi][ni], al[mi], b0, b1);
                    }
        }
        __syncthreads();
    }

    // ---- epilogue by region: q (rope, *1/sqrt(128), fp16), k (rope, fp16), v fp32
    const int lr = lane >> 2;
    const int lc = (lane & 3) << 1;
    const int region = (col0 < DIM_) ? 0 : (col0 < DIM_ + KVDIM ? 1 : 2);
    const float qsc = 0.08838834764831845f;   // 1/sqrt(128)
    #pragma unroll
    for (int mi = 0; mi < 2; mi++) {
        #pragma unroll
        for (int ni = 0; ni < 8; ni++) {
            float* d = acc[mi][ni];
            const int r0  = row0 + wm * 32 + mi * 16 + lr;
            const int r1  = r0 + 8;
            const int col = col0 + wn * 64 + ni * 8 + lc;
            if (region != 2) {
                const int p = (col & (HDIM - 1)) >> 1;
                {
                    const int t = r0 & (T_SZ - 1);
                    const float cz = fc[t * (HDIM / 2) + p];
                    const float sz = fs[t * (HDIM / 2) + p];
                    const float xr = d[0], xi = d[1];
                    d[0] = xr * cz - xi * sz;
                    d[1] = xr * sz + xi * cz;
                }
                {
                    const int t = r1 & (T_SZ - 1);
                    const float cz = fc[t * (HDIM / 2) + p];
                    const float sz = fs[t * (HDIM / 2) + p];
                    const float xr = d[2], xi = d[3];
                    d[2] = xr * cz - xi * sz;
                    d[3] = xr * sz + xi * cz;
                }
            }
            if (region == 0) {
                *(uint32_t*)&Qf[(size_t)r0 * DIM_ + col] =
                    h2u(__floats2half2_rn(d[0] * qsc, d[1] * qsc));
                *(uint32_t*)&Qf[(size_t)r1 * DIM_ + col] =
                    h2u(__floats2half2_rn(d[2] * qsc, d[3] * qsc));
            } else if (region == 1) {
                const int ck = col - DIM_;
                *(uint32_t*)&Kf[(size_t)r0 * KVDIM + ck] = h2u(__floats2half2_rn(d[0], d[1]));
                *(uint32_t*)&Kf[(size_t)r1 * KVDIM + ck] = h2u(__floats2half2_rn(d[2], d[3]));
            } else {
                const int cv = col - DIM_ - KVDIM;
                *(float2*)(V + (size_t)r0 * KVDIM + cv) = make_float2(d[0], d[1]);
                *(float2*)(V + (size_t)r1 * KVDIM + cv) = make_float2(d[2], d[3]);
            }
        }
    }
}

// ================= O projection: 1-pass fp16 GEMM ============================
// out[M,2048] = att(fp16)[M,2048] @ wo^T(fp16)[2048,2048]
#define OS_A      0
#define OS_B      TILE_BY
#define OSTAGE    (2 * TILE_BY)
#define OGEMM_SMEM (2 * OSTAGE)      // 40960

__device__ __forceinline__ void load_stage_o(
    const __half* __restrict__ Ab, const __half* __restrict__ Bb,
    int kof, uint32_t sbuf, int tid)
{
    #pragma unroll
    for (int i = 0; i < 2; i++) {
        const int c   = tid + (i << 8);
        const int row = c >> 2, q = c & 3;
        const size_t   go = (size_t)row * GK + kof + q * 8;
        const uint32_t so = row * TPITCH + q * 16;
        CP_ASYNC16(sbuf + OS_A + so, Ab + go);
        CP_ASYNC16(sbuf + OS_B + so, Bb + go);
    }
}

__global__ __launch_bounds__(256, 1)
void o_gemm_kernel(const __half* __restrict__ A, const __half* __restrict__ B,
                   float* __restrict__ C)
{
    extern __shared__ char smem[];
    const uint32_t sbase = smem_u32(smem);
    const int tid  = threadIdx.x;
    const int lane = tid & 31, wid = tid >> 5;
    const int wm   = wid & 3,  wn  = wid >> 2;
    const int row0 = blockIdx.y << 7, col0 = blockIdx.x << 7;

    const __half* Ab = A + (size_t)row0 * GK;
    const __half* Bb = B + (size_t)col0 * GK;

    float acc[2][8][4];
    #pragma unroll
    for (int mi = 0; mi < 2; mi++)
        #pragma unroll
        for (int ni = 0; ni < 8; ni++)
            #pragma unroll
            for (int e = 0; e < 4; e++) acc[mi][ni][e] = 0.f;

    const uint32_t a_row = wm * 32 + (lane & 15);
    const uint32_t a_col = (lane >> 4) << 4;
    const uint32_t b_rowb = wn * 64 + (lane & 7) + ((lane >> 4) << 3);
    const uint32_t b_col  = ((lane >> 3) & 1) << 4;

    load_stage_o(Ab, Bb, 0, sbase, tid);
    CP_COMMIT();

    for (int blk = 0; blk < NKB; blk++) {
        const uint32_t buf = sbase + (uint32_t)(blk & 1) * OSTAGE;
        if (blk + 1 < NKB) {
            load_stage_o(Ab, Bb, (blk + 1) * BK,
                         sbase + (uint32_t)((blk + 1) & 1) * OSTAGE, tid);
            CP_COMMIT();
            CP_WAIT(1);
        } else {
            CP_WAIT(0);
        }
        __syncthreads();

        #pragma unroll
        for (int ks = 0; ks < 2; ks++) {
            const uint32_t koff = ks * 32;
            uint32_t af[2][4];
            #pragma unroll
            for (int mi = 0; mi < 2; mi++) {
                const uint32_t aaddr = buf + OS_A + (a_row + mi * 16) * TPITCH + koff + a_col;
                ldsm4(af[mi], aaddr);
            }
            uint32_t bf[4][4];
            #pragma unroll
            for (int nq = 0; nq < 4; nq++) {
                const uint32_t baddr = buf + OS_B + (b_rowb + nq * 16) * TPITCH + koff + b_col;
                ldsm4(bf[nq], baddr);
            }
            #pragma unroll
            for (int mi = 0; mi < 2; mi++)
                #pragma unroll
                for (int nq = 0; nq < 4; nq++)
                    #pragma unroll
                    for (int hf = 0; hf < 2; hf++) {
                        const int ni = nq * 2 + hf;
                        mma16816h(acc[mi][ni], af[mi], bf[nq][hf * 2], bf[nq][hf * 2 + 1]);
                    }
        }
        __syncthreads();
    }

    const int lr = lane >> 2;
    const int lc = (lane & 3) << 1;
    #pragma unroll
    for (int mi = 0; mi < 2; mi++) {
        #pragma unroll
        for (int ni = 0; ni < 8; ni++) {
            float* d = acc[mi][ni];
            const int r0  = row0 + wm * 32 + mi * 16 + lr;
            const int r1  = r0 + 8;
            const int col = col0 + wn * 64 + ni * 8 + lc;
            *(float2*)(C + (size_t)r0 * DIM_ + col) = make_float2(d[0], d[1]);
            *(float2*)(C + (size_t)r1 * DIM_ + col) = make_float2(d[2], d[3]);
        }
    }
}

// ================= tensor-core flash attention ===============================
// q-tile 128 (8 warps x 16 rows), k-tile 64. S: single fp16 (scale pre-folded
// into Q). PV: single fp16. att out: fp16.
#define QPITCH 272
#define VPITCH 144
#define SM_Q   0
#define SM_KV  (128 * QPITCH)          // 34816
#define OFF_K  0
#define OFF_V  (64 * QPITCH)           // 17408
#define KVBUF  (OFF_V + 128 * VPITCH)  // 35840
#define FLASH2_SMEM (SM_KV + 2 * KVBUF) // 106496

__device__ __forceinline__ void flash_load_kv(
    const __half* __restrict__ Kf, const __half* __restrict__ Vt,
    int b, int kvh, int kt, uint32_t buf, int tid)
{
    const char* gk = (const char*)(Kf + (size_t)(b * T_SZ + kt * 64) * KVDIM + kvh * HDIM);
    #pragma unroll
    for (int s = 0; s < 4; s++) {
        const int u = tid + s * 256;           // 0..1023 (64 rows x 16 chunks)
        const int r = u >> 4, c = (u & 15) << 4;
        CP_ASYNC16(buf + OFF_K + r * QPITCH + c, gk + (size_t)r * (KVDIM * 2) + c);
    }
    const char* gv = (const char*)(Vt + ((size_t)(b * KVHEAD + kvh) * HDIM) * T_SZ + kt * 64);
    #pragma unroll
    for (int s = 0; s < 4; s++) {
        const int u = tid + s * 256;           // 128 rows x 8 chunks
        const int r = u >> 3, c = (u & 7) << 4;
        CP_ASYNC16(buf + OFF_V + r * VPITCH + c, gv + (size_t)r * (T_SZ * 2) + c);
    }
}

__global__ __launch_bounds__(256, 1)
void flash_mma_kernel(const __half* __restrict__ Qf, const __half* __restrict__ Kf,
                      const __half* __restrict__ Vt, __half* __restrict__ At)
{
    extern __shared__ char smem[];
    const uint32_t sbase = smem_u32(smem);
    const int tid = threadIdx.x, lane = tid & 31, w = tid >> 5;
    const int qt = (int)gridDim.x - 1 - (int)blockIdx.x;   // heavy tiles first
    const int bh = blockIdx.y, b = bh >> 4, h = bh & 15, kvh = h >> 2;
    const int qrow0 = b * T_SZ + qt * 128;
    const int nkt = 2 * qt + 2;

    {
        const char* gq = (const char*)(Qf + (size_t)qrow0 * DIM_ + h * HDIM);
        #pragma unroll
        for (int s = 0; s < 8; s++) {
            const int u = tid + s * 256;       // 0..2047 (128 rows x 16 chunks)
            const int r = u >> 4, c = (u & 15) << 4;
            CP_ASYNC16(sbase + SM_Q + r * QPITCH + c, gq + (size_t)r * (DIM_ * 2) + c);
        }
    }
    flash_load_kv(Kf, Vt, b, kvh, 0, sbase + SM_KV, tid);
    CP_COMMIT();

    float sm0 = -1e30f, sm1 = -1e30f, sl0 = 0.f, sl1 = 0.f;
    float vacc[16][4];
    #pragma unroll
    for (int ni = 0; ni < 16; ni++)
        #pragma unroll
        for (int e = 0; e < 4; e++) vacc[ni][e] = 0.f;

    const int r0l = w * 16 + (lane >> 2);
    const int r1l = r0l + 8;
    const uint32_t a_addr0 = sbase + SM_Q + (w * 16 + (lane & 15)) * QPITCH + ((lane >> 4) << 4);
    const uint32_t b_roff  = ((lane & 7) + ((lane >> 4) << 3));
    const uint32_t b_coff  = ((lane >> 3) & 1) << 4;

    CP_WAIT(0);
    __syncthreads();

    for (int kt = 0; kt < nkt; kt++) {
        const uint32_t buf = sbase + SM_KV + (uint32_t)(kt & 1) * KVBUF;
        if (kt + 1 < nkt) {
            flash_load_kv(Kf, Vt, b, kvh, kt + 1,
                          sbase + SM_KV + (uint32_t)((kt + 1) & 1) * KVBUF, tid);
            CP_COMMIT();
        }

        // ---- S = Q K^T (single fp16; scale folded into Q) ----
        float sacc[8][4];
        #pragma unroll
        for (int nj = 0; nj < 8; nj++)
            #pragma unroll
            for (int e = 0; e < 4; e++) sacc[nj][e] = 0.f;

        #pragma unroll
        for (int ks = 0; ks < 8; ks++) {
            uint32_t q4[4];
            ldsm4(q4, a_addr0 + ks * 32);
            #pragma unroll
            for (int nq = 0; nq < 4; nq++) {
                uint32_t k4[4];
                ldsm4(k4, buf + OFF_K + (nq * 16 + b_roff) * QPITCH + ks * 32 + b_coff);
                mma16816h(sacc[nq * 2],     q4, k4[0], k4[1]);
                mma16816h(sacc[nq * 2 + 1], q4, k4[2], k4[3]);
            }
        }

        // ---- causal mask (diagonal k-tiles) ----
        if (kt >= 2 * qt) {
            const int coff = kt * 64 - qt * 128;
            #pragma unroll
            for (int nj = 0; nj < 8; nj++) {
                const int c0 = coff + nj * 8 + (lane & 3) * 2;
                if (c0     > r0l) sacc[nj][0] = -1e30f;
                if (c0 + 1 > r0l) sacc[nj][1] = -1e30f;
                if (c0     > r1l) sacc[nj][2] = -1e30f;
                if (c0 + 1 > r1l) sacc[nj][3] = -1e30f;
            }
        }

        // ---- online softmax (register stats, bfly over lane&3) ----
        float mx0 = -1e30f, mx1 = -1e30f;
        #pragma unroll
        for (int nj = 0; nj < 8; nj++) {
            mx0 = fmaxf(mx0, fmaxf(sacc[nj][0], sacc[nj][1]));
            mx1 = fmaxf(mx1, fmaxf(sacc[nj][2], sacc[nj][3]));
        }
        mx0 = fmaxf(mx0, __shfl_xor_sync(0xFFFFFFFFu, mx0, 1));
        mx0 = fmaxf(mx0, __shfl_xor_sync(0xFFFFFFFFu, mx0, 2));
        mx1 = fmaxf(mx1, __shfl_xor_sync(0xFFFFFFFFu, mx1, 1));
        mx1 = fmaxf(mx1, __shfl_xor_sync(0xFFFFFFFFu, mx1, 2));
        const float mn0 = fmaxf(sm0, mx0), mn1 = fmaxf(sm1, mx1);
        const float al0 = __expf(sm0 - mn0), al1 = __expf(sm1 - mn1);
        sm0 = mn0; sm1 = mn1;

        // P = exp(S - m) as half2 A-fragments
        uint32_t pa[4][4];
        float ls0 = 0.f, ls1 = 0.f;
        #pragma unroll
        for (int j = 0; j < 4; j++) {
            #pragma unroll
            for (int t = 0; t < 2; t++) {
                const int nj = 2 * j + t;
                const float p0 = __expf(sacc[nj][0] - mn0);
                const float p1 = __expf(sacc[nj][1] - mn0);
                const float p2 = __expf(sacc[nj][2] - mn1);
                const float p3 = __expf(sacc[nj][3] - mn1);
                ls0 += p0 + p1;
                ls1 += p2 + p3;
                pa[j][t * 2]     = h2u(__floats2half2_rn(p0, p1));
                pa[j][t * 2 + 1] = h2u(__floats2half2_rn(p2, p3));
            }
        }
        ls0 += __shfl_xor_sync(0xFFFFFFFFu, ls0, 1);
        ls0 += __shfl_xor_sync(0xFFFFFFFFu, ls0, 2);
        ls1 += __shfl_xor_sync(0xFFFFFFFFu, ls1, 1);
        ls1 += __shfl_xor_sync(0xFFFFFFFFu, ls1, 2);
        sl0 = sl0 * al0 + ls0;
        sl1 = sl1 * al1 + ls1;

        #pragma unroll
        for (int ni = 0; ni < 16; ni++) {
            vacc[ni][0] *= al0; vacc[ni][1] *= al0;
            vacc[ni][2] *= al1; vacc[ni][3] *= al1;
        }

        // ---- O += P V (single fp16; B = V^T fp16 [d][t]) ----
        #pragma unroll
        for (int j = 0; j < 4; j++) {
            #pragma unroll
            for (int nq = 0; nq < 8; nq++) {
                uint32_t v4[4];
                const uint32_t vaddr = buf + OFF_V + (nq * 16 + b_roff) * VPITCH + j * 32 + b_coff;
                ldsm4(v4, vaddr);
                mma16816h(vacc[nq * 2],     pa[j], v4[0], v4[1]);
                mma16816h(vacc[nq * 2 + 1], pa[j], v4[2], v4[3]);
            }
        }

        if (kt + 1 < nkt) CP_WAIT(0);
        __syncthreads();
    }

    // ---- epilogue: write att as fp16 single ----
    const float inv0 = 1.f / sl0, inv1 = 1.f / sl1;
    __half* a0 = At + (size_t)(qrow0 + r0l) * DIM_ + h * HDIM;
    __half* a1 = At + (size_t)(qrow0 + r1l) * DIM_ + h * HDIM;
    #pragma unroll
    for (int ni = 0; ni < 16; ni++) {
        const int col = ni * 8 + (lane & 3) * 2;
        *(uint32_t*)(a0 + col) = h2u(__floats2half2_rn(vacc[ni][0] * inv0, vacc[ni][1] * inv0));
        *(uint32_t*)(a1 + col) = h2u(__floats2half2_rn(vacc[ni][2] * inv1, vacc[ni][3] * inv1));
    }
}

// ================= launch ====================================================
extern "C" void kernel_launch(void* const* d_in, const int* in_sizes, int n_in,
                              void* d_out, int out_size)
{
    const float* x  = (const float*)d_in[0];
    const float* fc = (const float*)d_in[1];
    const float* fs = (const float*)d_in[2];
    const float* wq = (const float*)d_in[3];
    const float* wk = (const float*)d_in[4];
    const float* wv = (const float*)d_in[5];
    const float* wo = (const float*)d_in[6];
    float* out = (float*)d_out;

    float* v;
    cudaGetSymbolAddress((void**)&v, g_v);
    __half *xh, *xl, *wtf, *wotf, *qf, *kf, *vtf, *ath;
    cudaGetSymbolAddress((void**)&xh,   g_xh);   cudaGetSymbolAddress((void**)&xl,   g_xl);
    cudaGetSymbolAddress((void**)&wtf,  g_wtf);  cudaGetSymbolAddress((void**)&wotf, g_wotf);
    cudaGetSymbolAddress((void**)&qf,   g_qf);   cudaGetSymbolAddress((void**)&kf,   g_kf);
    cudaGetSymbolAddress((void**)&vtf,  g_vtf);  cudaGetSymbolAddress((void**)&ath,  g_ath);

    cudaFuncSetAttribute(qkv_gemm_kernel, cudaFuncAttributeMaxDynamicSharedMemorySize, QGEMM_SMEM);
    cudaFuncSetAttribute(o_gemm_kernel,   cudaFuncAttributeMaxDynamicSharedMemorySize, OGEMM_SMEM);
    cudaFuncSetAttribute(flash_mma_kernel, cudaFuncAttributeMaxDynamicSharedMemorySize, FLASH2_SMEM);

    const int n4x = MROWS * DIM_ / 4;

    // input conversions (x hi/lo fp16; weights single fp16, transposed)
    hsplit_kernel<<<n4x / 256, 256>>>(x, xh, xl, n4x);
    thalf_kernel<<<dim3(DIM_  / 32, DIM_ / 32), 256>>>(wq, wtf, GK, DIM_);
    thalf_kernel<<<dim3(KVDIM / 32, DIM_ / 32), 256>>>(wk, wtf + (size_t)DIM_ * GK, GK, KVDIM);
    thalf_kernel<<<dim3(KVDIM / 32, DIM_ / 32), 256>>>(
        wv, wtf + (size_t)(DIM_ + KVDIM) * GK, GK, KVDIM);
    thalf_kernel<<<dim3(DIM_ / 32, DIM_ / 32), 256>>>(wo, wotf, GK, DIM_);

    // fused q|k|v projection (2-pass fp16; rope + fp16 epilogues, q pre-scaled)
    qkv_gemm_kernel<<<dim3(NTOT / 128, MROWS / 128), 256, QGEMM_SMEM>>>(
        xh, xl, wtf, qf, kf, v, fc, fs);

    // v -> V^T fp16
    vthalf_kernel<<<dim3(T_SZ / 32, KVDIM / 32, B_SZ), 256>>>(v, vtf);

    // attention (S single fp16, PV single fp16; att fp16)
    flash_mma_kernel<<<dim3(T_SZ / 128, B_SZ * NHEAD), 256, FLASH2_SMEM>>>(qf, kf, vtf, ath);

    // output projection (1-pass fp16)
    o_gemm_kernel<<<dim3(DIM_ / 128, MROWS / 128), 256, OGEMM_SMEM>>>(ath, wotf, out);
}

// round 16
// speedup vs baseline: 2.0798x; 1.1976x over previous
#include <cuda_runtime.h>
#include <cuda_fp16.h>
#include <cstdint>

#define B_SZ   2
#define T_SZ   2048
#define DIM_   2048
#define NHEAD  16
#define KVHEAD 4
#define HDIM   128
#define MROWS  (B_SZ * T_SZ)        // 4096
#define KVDIM  (KVHEAD * HDIM)      // 512
#define GK     2048
#define NTOT   (DIM_ + 2 * KVDIM)   // 3072 concat q|k|v columns

// ================= scratch (device globals; no allocations allowed) =========
__device__ float g_v[(size_t)MROWS * KVDIM];                       // fp32 v

__device__ __align__(16) __half g_xf[(size_t)MROWS * DIM_];        // x fp16 single
__device__ __align__(16) __half g_wtf[(size_t)NTOT * GK];          // [3072,2048] wq|wk|wv ^T fp16
__device__ __align__(16) __half g_wotf[(size_t)DIM_ * GK];         // wo^T fp16
__device__ __align__(16) __half g_qf[(size_t)MROWS * DIM_];        // q fp16 (scaled 1/sqrt(128))
__device__ __align__(16) __half g_kf[(size_t)MROWS * KVDIM];       // k fp16
__device__ __align__(16) __half g_vtf[(size_t)B_SZ * KVDIM * T_SZ]; // [b*512+c][t]
__device__ __align__(16) __half g_ath[(size_t)MROWS * DIM_];       // att fp16 single

// ================= helpers ===================================================
__device__ __forceinline__ uint32_t smem_u32(const void* p) {
    uint32_t a;
    asm("{ .reg .u64 t; cvta.to.shared.u64 t, %1; cvt.u32.u64 %0, t; }" : "=r"(a) : "l"(p));
    return a;
}
__device__ __forceinline__ void ldsm4(uint32_t (&r)[4], uint32_t addr) {
    asm volatile("ldmatrix.sync.aligned.m8n8.x4.shared.b16 {%0,%1,%2,%3}, [%4];"
                 : "=r"(r[0]), "=r"(r[1]), "=r"(r[2]), "=r"(r[3]) : "r"(addr));
}
__device__ __forceinline__ void mma16816h(float (&d)[4], const uint32_t (&a)[4],
                                          uint32_t b0, uint32_t b1) {
    asm volatile("mma.sync.aligned.m16n8k16.row.col.f32.f16.f16.f32 "
                 "{%0,%1,%2,%3}, {%4,%5,%6,%7}, {%8,%9}, {%0,%1,%2,%3};"
                 : "+f"(d[0]), "+f"(d[1]), "+f"(d[2]), "+f"(d[3])
                 : "r"(a[0]), "r"(a[1]), "r"(a[2]), "r"(a[3]), "r"(b0), "r"(b1));
}
#define CP_ASYNC16(sm, gm) \
    asm volatile("cp.async.cg.shared.global [%0], [%1], 16;" :: "r"(sm), "l"(gm) : "memory")
#define CP_COMMIT() asm volatile("cp.async.commit_group;" ::: "memory")
#define CP_WAIT(n)  asm volatile("cp.async.wait_group %0;" :: "n"(n) : "memory")

__device__ __forceinline__ uint32_t h2u(__half2 v) { return *reinterpret_cast<uint32_t*>(&v); }

// ================= conversion kernels ========================================
// fp32 -> fp16 single (flat)
__global__ void xhalf_kernel(const float* __restrict__ in, __half* __restrict__ out, int n4)
{
    int i = blockIdx.x * 256 + threadIdx.x;
    if (i >= n4) return;
    float4 v = ((const float4*)in)[i];
    ((uint32_t*)out)[2 * i]     = h2u(__floats2half2_rn(v.x, v.y));
    ((uint32_t*)out)[2 * i + 1] = h2u(__floats2half2_rn(v.z, v.w));
}

// in: [R,C] fp32 -> out: [C,R] fp16 single (transposed)
__global__ void thalf_kernel(const float* __restrict__ in, __half* __restrict__ out,
                             int R, int C)
{
    __shared__ float tile[32][33];
    const int bx = blockIdx.x << 5;
    const int by = blockIdx.y << 5;
    const int tx = threadIdx.x & 31, ty = threadIdx.x >> 5;
    #pragma unroll
    for (int r = ty; r < 32; r += 8)
        tile[r][tx] = in[(size_t)(by + r) * C + bx + tx];
    __syncthreads();
    #pragma unroll
    for (int r = ty; r < 32; r += 8)
        out[(size_t)(bx + r) * R + by + tx] = __float2half_rn(tile[tx][r]);
}

// g_v [b*T+t][c] fp32 -> g_vtf [(b*512+c)][t] fp16 single
__global__ void vthalf_kernel(const float* __restrict__ in, __half* __restrict__ out)
{
    __shared__ float tile[32][33];
    const int t0 = blockIdx.x << 5;
    const int c0 = blockIdx.y << 5;
    const int b  = blockIdx.z;
    const int tx = threadIdx.x & 31, ty = threadIdx.x >> 5;
    #pragma unroll
    for (int r = ty; r < 32; r += 8)
        tile[r][tx] = in[(size_t)(b * T_SZ + t0 + r) * KVDIM + c0 + tx];
    __syncthreads();
    #pragma unroll
    for (int r = ty; r < 32; r += 8)
        out[(size_t)(b * KVDIM + c0 + r) * T_SZ + t0 + tx] = __float2half_rn(tile[tx][r]);
}

// ================= 1-pass fp16 GEMM core (3-stage cp.async) ==================
#define BK        32
#define NKB       (GK / BK)          // 64
#define TPITCH    80
#define TILE_BY   (128 * TPITCH)
#define GS_A      0
#define GS_B      TILE_BY
#define GSTAGE    (2 * TILE_BY)      // 20480
#define GEMM_SMEM (3 * GSTAGE)       // 61440

__device__ __forceinline__ void load_stage_g(
    const __half* __restrict__ Ab, const __half* __restrict__ Bb,
    int kof, uint32_t sbuf, int tid)
{
    #pragma unroll
    for (int i = 0; i < 2; i++) {
        const int c   = tid + (i << 8);
        const int row = c >> 2, q = c & 3;
        const size_t   go = (size_t)row * GK + kof + q * 8;
        const uint32_t so = row * TPITCH + q * 16;
        CP_ASYNC16(sbuf + GS_A + so, Ab + go);
        CP_ASYNC16(sbuf + GS_B + so, Bb + go);
    }
}

// Mainloop shared by qkv and o gemms; leaves fp32 accumulators in acc.
__device__ __forceinline__ void gemm_mainloop(
    const __half* __restrict__ Ab, const __half* __restrict__ Bb,
    uint32_t sbase, int tid, int lane, int wm, int wn, float (&acc)[2][8][4])
{
    const uint32_t a_row = wm * 32 + (lane & 15);
    const uint32_t a_col = (lane >> 4) << 4;
    const uint32_t b_rowb = wn * 64 + (lane & 7) + ((lane >> 4) << 3);
    const uint32_t b_col  = ((lane >> 3) & 1) << 4;

    load_stage_g(Ab, Bb, 0, sbase, tid);
    CP_COMMIT();
    load_stage_g(Ab, Bb, BK, sbase + GSTAGE, tid);
    CP_COMMIT();

    for (int blk = 0; blk < NKB; blk++) {
        const uint32_t buf = sbase + (uint32_t)(blk % 3) * GSTAGE;
        if (blk + 2 < NKB) {
            load_stage_g(Ab, Bb, (blk + 2) * BK, sbase + (uint32_t)((blk + 2) % 3) * GSTAGE, tid);
            CP_COMMIT();
            CP_WAIT(2);
        } else if (blk + 2 == NKB) {
            CP_WAIT(1);
        } else {
            CP_WAIT(0);
        }
        __syncthreads();

        #pragma unroll
        for (int ks = 0; ks < 2; ks++) {
            const uint32_t koff = ks * 32;
            uint32_t af[2][4];
            #pragma unroll
            for (int mi = 0; mi < 2; mi++)
                ldsm4(af[mi], buf + GS_A + (a_row + mi * 16) * TPITCH + koff + a_col);
            uint32_t bf[4][4];
            #pragma unroll
            for (int nq = 0; nq < 4; nq++)
                ldsm4(bf[nq], buf + GS_B + (b_rowb + nq * 16) * TPITCH + koff + b_col);
            #pragma unroll
            for (int mi = 0; mi < 2; mi++)
                #pragma unroll
                for (int nq = 0; nq < 4; nq++)
                    #pragma unroll
                    for (int hf = 0; hf < 2; hf++)
                        mma16816h(acc[mi][nq * 2 + hf], af[mi],
                                  bf[nq][hf * 2], bf[nq][hf * 2 + 1]);
        }
        __syncthreads();
    }
}

// ================= fused QKV gemm ============================================
// C[M, 3072] = x(fp16)[M,2048] @ [wq|wk|wv]^T(fp16) ;
// epilogue: q (rope * 1/sqrt(128)) fp16, k (rope) fp16, v fp32
__global__ __launch_bounds__(256, 1)
void qkv_gemm_kernel(const __half* __restrict__ A, const __half* __restrict__ B,
                     __half* __restrict__ Qf, __half* __restrict__ Kf,
                     float* __restrict__ V,
                     const float* __restrict__ fc, const float* __restrict__ fs)
{
    extern __shared__ char smem[];
    const uint32_t sbase = smem_u32(smem);
    const int tid  = threadIdx.x;
    const int lane = tid & 31, wid = tid >> 5;
    const int wm   = wid & 3,  wn  = wid >> 2;
    const int row0 = blockIdx.y << 7, col0 = blockIdx.x << 7;

    float acc[2][8][4];
    #pragma unroll
    for (int mi = 0; mi < 2; mi++)
        #pragma unroll
        for (int ni = 0; ni < 8; ni++)
            #pragma unroll
            for (int e = 0; e < 4; e++) acc[mi][ni][e] = 0.f;

    gemm_mainloop(A + (size_t)row0 * GK, B + (size_t)col0 * GK,
                  sbase, tid, lane, wm, wn, acc);

    // ---- epilogue by region ----
    const int lr = lane >> 2;
    const int lc = (lane & 3) << 1;
    const int region = (col0 < DIM_) ? 0 : (col0 < DIM_ + KVDIM ? 1 : 2);
    const float qsc = 0.08838834764831845f;   // 1/sqrt(128)
    #pragma unroll
    for (int mi = 0; mi < 2; mi++) {
        #pragma unroll
        for (int ni = 0; ni < 8; ni++) {
            float* d = acc[mi][ni];
            const int r0  = row0 + wm * 32 + mi * 16 + lr;
            const int r1  = r0 + 8;
            const int col = col0 + wn * 64 + ni * 8 + lc;
            if (region != 2) {
                const int p = (col & (HDIM - 1)) >> 1;
                {
                    const int t = r0 & (T_SZ - 1);
                    const float cz = fc[t * (HDIM / 2) + p];
                    const float sz = fs[t * (HDIM / 2) + p];
                    const float xr = d[0], xi = d[1];
                    d[0] = xr * cz - xi * sz;
                    d[1] = xr * sz + xi * cz;
                }
                {
                    const int t = r1 & (T_SZ - 1);
                    const float cz = fc[t * (HDIM / 2) + p];
                    const float sz = fs[t * (HDIM / 2) + p];
                    const float xr = d[2], xi = d[3];
                    d[2] = xr * cz - xi * sz;
                    d[3] = xr * sz + xi * cz;
                }
            }
            if (region == 0) {
                *(uint32_t*)&Qf[(size_t)r0 * DIM_ + col] =
                    h2u(__floats2half2_rn(d[0] * qsc, d[1] * qsc));
                *(uint32_t*)&Qf[(size_t)r1 * DIM_ + col] =
                    h2u(__floats2half2_rn(d[2] * qsc, d[3] * qsc));
            } else if (region == 1) {
                const int ck = col - DIM_;
                *(uint32_t*)&Kf[(size_t)r0 * KVDIM + ck] = h2u(__floats2half2_rn(d[0], d[1]));
                *(uint32_t*)&Kf[(size_t)r1 * KVDIM + ck] = h2u(__floats2half2_rn(d[2], d[3]));
            } else {
                const int cv = col - DIM_ - KVDIM;
                *(float2*)(V + (size_t)r0 * KVDIM + cv) = make_float2(d[0], d[1]);
                *(float2*)(V + (size_t)r1 * KVDIM + cv) = make_float2(d[2], d[3]);
            }
        }
    }
}

// ================= O projection: 1-pass fp16 GEMM ============================
__global__ __launch_bounds__(256, 1)
void o_gemm_kernel(const __half* __restrict__ A, const __half* __restrict__ B,
                   float* __restrict__ C)
{
    extern __shared__ char smem[];
    const uint32_t sbase = smem_u32(smem);
    const int tid  = threadIdx.x;
    const int lane = tid & 31, wid = tid >> 5;
    const int wm   = wid & 3,  wn  = wid >> 2;
    const int row0 = blockIdx.y << 7, col0 = blockIdx.x << 7;

    float acc[2][8][4];
    #pragma unroll
    for (int mi = 0; mi < 2; mi++)
        #pragma unroll
        for (int ni = 0; ni < 8; ni++)
            #pragma unroll
            for (int e = 0; e < 4; e++) acc[mi][ni][e] = 0.f;

    gemm_mainloop(A + (size_t)row0 * GK, B + (size_t)col0 * GK,
                  sbase, tid, lane, wm, wn, acc);

    const int lr = lane >> 2;
    const int lc = (lane & 3) << 1;
    #pragma unroll
    for (int mi = 0; mi < 2; mi++) {
        #pragma unroll
        for (int ni = 0; ni < 8; ni++) {
            float* d = acc[mi][ni];
            const int r0  = row0 + wm * 32 + mi * 16 + lr;
            const int r1  = r0 + 8;
            const int col = col0 + wn * 64 + ni * 8 + lc;
            *(float2*)(C + (size_t)r0 * DIM_ + col) = make_float2(d[0], d[1]);
            *(float2*)(C + (size_t)r1 * DIM_ + col) = make_float2(d[2], d[3]);
        }
    }
}

// ================= tensor-core flash attention (unchanged R15-passing) =======
// q-tile 128 (8 warps x 16 rows), k-tile 64. S single fp16 (scale in Q),
// PV single fp16, att out fp16.
#define QPITCH 272
#define VPITCH 144
#define SM_Q   0
#define SM_KV  (128 * QPITCH)          // 34816
#define OFF_K  0
#define OFF_V  (64 * QPITCH)           // 17408
#define KVBUF  (OFF_V + 128 * VPITCH)  // 35840
#define FLASH2_SMEM (SM_KV + 2 * KVBUF) // 106496

__device__ __forceinline__ void flash_load_kv(
    const __half* __restrict__ Kf, const __half* __restrict__ Vt,
    int b, int kvh, int kt, uint32_t buf, int tid)
{
    const char* gk = (const char*)(Kf + (size_t)(b * T_SZ + kt * 64) * KVDIM + kvh * HDIM);
    #pragma unroll
    for (int s = 0; s < 4; s++) {
        const int u = tid + s * 256;           // 64 rows x 16 chunks
        const int r = u >> 4, c = (u & 15) << 4;
        CP_ASYNC16(buf + OFF_K + r * QPITCH + c, gk + (size_t)r * (KVDIM * 2) + c);
    }
    const char* gv = (const char*)(Vt + ((size_t)(b * KVHEAD + kvh) * HDIM) * T_SZ + kt * 64);
    #pragma unroll
    for (int s = 0; s < 4; s++) {
        const int u = tid + s * 256;           // 128 rows x 8 chunks
        const int r = u >> 3, c = (u & 7) << 4;
        CP_ASYNC16(buf + OFF_V + r * VPITCH + c, gv + (size_t)r * (T_SZ * 2) + c);
    }
}

__global__ __launch_bounds__(256, 1)
void flash_mma_kernel(const __half* __restrict__ Qf, const __half* __restrict__ Kf,
                      const __half* __restrict__ Vt, __half* __restrict__ At)
{
    extern __shared__ char smem[];
    const uint32_t sbase = smem_u32(smem);
    const int tid = threadIdx.x, lane = tid & 31, w = tid >> 5;
    const int qt = (int)gridDim.x - 1 - (int)blockIdx.x;   // heavy tiles first
    const int bh = blockIdx.y, b = bh >> 4, h = bh & 15, kvh = h >> 2;
    const int qrow0 = b * T_SZ + qt * 128;
    const int nkt = 2 * qt + 2;

    {
        const char* gq = (const char*)(Qf + (size_t)qrow0 * DIM_ + h * HDIM);
        #pragma unroll
        for (int s = 0; s < 8; s++) {
            const int u = tid + s * 256;       // 128 rows x 16 chunks
            const int r = u >> 4, c = (u & 15) << 4;
            CP_ASYNC16(sbase + SM_Q + r * QPITCH + c, gq + (size_t)r * (DIM_ * 2) + c);
        }
    }
    flash_load_kv(Kf, Vt, b, kvh, 0, sbase + SM_KV, tid);
    CP_COMMIT();

    float sm0 = -1e30f, sm1 = -1e30f, sl0 = 0.f, sl1 = 0.f;
    float vacc[16][4];
    #pragma unroll
    for (int ni = 0; ni < 16; ni++)
        #pragma unroll
        for (int e = 0; e < 4; e++) vacc[ni][e] = 0.f;

    const int r0l = w * 16 + (lane >> 2);
    const int r1l = r0l + 8;
    const uint32_t a_addr0 = sbase + SM_Q + (w * 16 + (lane & 15)) * QPITCH + ((lane >> 4) << 4);
    const uint32_t b_roff  = ((lane & 7) + ((lane >> 4) << 3));
    const uint32_t b_coff  = ((lane >> 3) & 1) << 4;

    CP_WAIT(0);
    __syncthreads();

    for (int kt = 0; kt < nkt; kt++) {
        const uint32_t buf = sbase + SM_KV + (uint32_t)(kt & 1) * KVBUF;
        if (kt + 1 < nkt) {
            flash_load_kv(Kf, Vt, b, kvh, kt + 1,
                          sbase + SM_KV + (uint32_t)((kt + 1) & 1) * KVBUF, tid);
            CP_COMMIT();
        }

        // ---- S = Q K^T (single fp16) ----
        float sacc[8][4];
        #pragma unroll
        for (int nj = 0; nj < 8; nj++)
            #pragma unroll
            for (int e = 0; e < 4; e++) sacc[nj][e] = 0.f;

        #pragma unroll
        for (int ks = 0; ks < 8; ks++) {
            uint32_t q4[4];
            ldsm4(q4, a_addr0 + ks * 32);
            #pragma unroll
            for (int nq = 0; nq < 4; nq++) {
                uint32_t k4[4];
                ldsm4(k4, buf + OFF_K + (nq * 16 + b_roff) * QPITCH + ks * 32 + b_coff);
                mma16816h(sacc[nq * 2],     q4, k4[0], k4[1]);
                mma16816h(sacc[nq * 2 + 1], q4, k4[2], k4[3]);
            }
        }

        // ---- causal mask (diagonal k-tiles) ----
        if (kt >= 2 * qt) {
            const int coff = kt * 64 - qt * 128;
            #pragma unroll
            for (int nj = 0; nj < 8; nj++) {
                const int c0 = coff + nj * 8 + (lane & 3) * 2;
                if (c0     > r0l) sacc[nj][0] = -1e30f;
                if (c0 + 1 > r0l) sacc[nj][1] = -1e30f;
                if (c0     > r1l) sacc[nj][2] = -1e30f;
                if (c0 + 1 > r1l) sacc[nj][3] = -1e30f;
            }
        }

        // ---- online softmax (register stats, bfly over lane&3) ----
        float mx0 = -1e30f, mx1 = -1e30f;
        #pragma unroll
        for (int nj = 0; nj < 8; nj++) {
            mx0 = fmaxf(mx0, fmaxf(sacc[nj][0], sacc[nj][1]));
            mx1 = fmaxf(mx1, fmaxf(sacc[nj][2], sacc[nj][3]));
        }
        mx0 = fmaxf(mx0, __shfl_xor_sync(0xFFFFFFFFu, mx0, 1));
        mx0 = fmaxf(mx0, __shfl_xor_sync(0xFFFFFFFFu, mx0, 2));
        mx1 = fmaxf(mx1, __shfl_xor_sync(0xFFFFFFFFu, mx1, 1));
        mx1 = fmaxf(mx1, __shfl_xor_sync(0xFFFFFFFFu, mx1, 2));
        const float mn0 = fmaxf(sm0, mx0), mn1 = fmaxf(sm1, mx1);
        const float al0 = __expf(sm0 - mn0), al1 = __expf(sm1 - mn1);
        sm0 = mn0; sm1 = mn1;

        // P = exp(S - m) as half2 A-fragments
        uint32_t pa[4][4];
        float ls0 = 0.f, ls1 = 0.f;
        #pragma unroll
        for (int j = 0; j < 4; j++) {
            #pragma unroll
            for (int t = 0; t < 2; t++) {
                const int nj = 2 * j + t;
                const float p0 = __expf(sacc[nj][0] - mn0);
                const float p1 = __expf(sacc[nj][1] - mn0);
                const float p2 = __expf(sacc[nj][2] - mn1);
                const float p3 = __expf(sacc[nj][3] - mn1);
                ls0 += p0 + p1;
                ls1 += p2 + p3;
                pa[j][t * 2]     = h2u(__floats2half2_rn(p0, p1));
                pa[j][t * 2 + 1] = h2u(__floats2half2_rn(p2, p3));
            }
        }
        ls0 += __shfl_xor_sync(0xFFFFFFFFu, ls0, 1);
        ls0 += __shfl_xor_sync(0xFFFFFFFFu, ls0, 2);
        ls1 += __shfl_xor_sync(0xFFFFFFFFu, ls1, 1);
        ls1 += __shfl_xor_sync(0xFFFFFFFFu, ls1, 2);
        sl0 = sl0 * al0 + ls0;
        sl1 = sl1 * al1 + ls1;

        #pragma unroll
        for (int ni = 0; ni < 16; ni++) {
            vacc[ni][0] *= al0; vacc[ni][1] *= al0;
            vacc[ni][2] *= al1; vacc[ni][3] *= al1;
        }

        // ---- O += P V (single fp16; B = V^T fp16 [d][t]) ----
        #pragma unroll
        for (int j = 0; j < 4; j++) {
            #pragma unroll
            for (int nq = 0; nq < 8; nq++) {
                uint32_t v4[4];
                const uint32_t vaddr = buf + OFF_V + (nq * 16 + b_roff) * VPITCH + j * 32 + b_coff;
                ldsm4(v4, vaddr);
                mma16816h(vacc[nq * 2],     pa[j], v4[0], v4[1]);
                mma16816h(vacc[nq * 2 + 1], pa[j], v4[2], v4[3]);
            }
        }

        if (kt + 1 < nkt) CP_WAIT(0);
        __syncthreads();
    }

    // ---- epilogue: write att as fp16 single ----
    const float inv0 = 1.f / sl0, inv1 = 1.f / sl1;
    __half* a0 = At + (size_t)(qrow0 + r0l) * DIM_ + h * HDIM;
    __half* a1 = At + (size_t)(qrow0 + r1l) * DIM_ + h * HDIM;
    #pragma unroll
    for (int ni = 0; ni < 16; ni++) {
        const int col = ni * 8 + (lane & 3) * 2;
        *(uint32_t*)(a0 + col) = h2u(__floats2half2_rn(vacc[ni][0] * inv0, vacc[ni][1] * inv0));
        *(uint32_t*)(a1 + col) = h2u(__floats2half2_rn(vacc[ni][2] * inv1, vacc[ni][3] * inv1));
    }
}

// ================= launch ====================================================
extern "C" void kernel_launch(void* const* d_in, const int* in_sizes, int n_in,
                              void* d_out, int out_size)
{
    const float* x  = (const float*)d_in[0];
    const float* fc = (const float*)d_in[1];
    const float* fs = (const float*)d_in[2];
    const float* wq = (const float*)d_in[3];
    const float* wk = (const float*)d_in[4];
    const float* wv = (const float*)d_in[5];
    const float* wo = (const float*)d_in[6];
    float* out = (float*)d_out;

    float* v;
    cudaGetSymbolAddress((void**)&v, g_v);
    __half *xf, *wtf, *wotf, *qf, *kf, *vtf, *ath;
    cudaGetSymbolAddress((void**)&xf,   g_xf);
    cudaGetSymbolAddress((void**)&wtf,  g_wtf);  cudaGetSymbolAddress((void**)&wotf, g_wotf);
    cudaGetSymbolAddress((void**)&qf,   g_qf);   cudaGetSymbolAddress((void**)&kf,   g_kf);
    cudaGetSymbolAddress((void**)&vtf,  g_vtf);  cudaGetSymbolAddress((void**)&ath,  g_ath);

    cudaFuncSetAttribute(qkv_gemm_kernel, cudaFuncAttributeMaxDynamicSharedMemorySize, GEMM_SMEM);
    cudaFuncSetAttribute(o_gemm_kernel,   cudaFuncAttributeMaxDynamicSharedMemorySize, GEMM_SMEM);
    cudaFuncSetAttribute(flash_mma_kernel, cudaFuncAttributeMaxDynamicSharedMemorySize, FLASH2_SMEM);

    const int n4x = MROWS * DIM_ / 4;

    // input conversions (x single fp16; weights single fp16, transposed)
    xhalf_kernel<<<n4x / 256, 256>>>(x, xf, n4x);
    thalf_kernel<<<dim3(DIM_  / 32, DIM_ / 32), 256>>>(wq, wtf, GK, DIM_);
    thalf_kernel<<<dim3(KVDIM / 32, DIM_ / 32), 256>>>(wk, wtf + (size_t)DIM_ * GK, GK, KVDIM);
    thalf_kernel<<<dim3(KVDIM / 32, DIM_ / 32), 256>>>(
        wv, wtf + (size_t)(DIM_ + KVDIM) * GK, GK, KVDIM);
    thalf_kernel<<<dim3(DIM_ / 32, DIM_ / 32), 256>>>(wo, wotf, GK, DIM_);

    // fused q|k|v projection (1-pass fp16; rope + fp16 epilogues, q pre-scaled)
    qkv_gemm_kernel<<<dim3(NTOT / 128, MROWS / 128), 256, GEMM_SMEM>>>(
        xf, wtf, qf, kf, v, fc, fs);

    // v -> V^T fp16
    vthalf_kernel<<<dim3(T_SZ / 32, KVDIM / 32, B_SZ), 256>>>(v, vtf);

    // attention (S single fp16, PV single fp16; att fp16)
    flash_mma_kernel<<<dim3(T_SZ / 128, B_SZ * NHEAD), 256, FLASH2_SMEM>>>(qf, kf, vtf, ath);

    // output projection (1-pass fp16)
    o_gemm_kernel<<<dim3(DIM_ / 128, MROWS / 128), 256, GEMM_SMEM>>>(ath, wotf, out);
}

// round 17
// speedup vs baseline: 2.4969x; 1.2006x over previous
#include <cuda_runtime.h>
#include <cuda_fp16.h>
#include <cstdint>

#define B_SZ   2
#define T_SZ   2048
#define DIM_   2048
#define NHEAD  16
#define KVHEAD 4
#define HDIM   128
#define MROWS  (B_SZ * T_SZ)        // 4096
#define KVDIM  (KVHEAD * HDIM)      // 512
#define GK     2048
#define NTOT   (DIM_ + 2 * KVDIM)   // 3072 concat q|k|v columns

// ================= scratch (device globals; no allocations allowed) =========
__device__ __align__(16) __half g_xf[(size_t)MROWS * DIM_];        // x fp16 single
__device__ __align__(16) __half g_wtf[(size_t)NTOT * GK];          // [3072,2048] wq|wk|wv ^T fp16
__device__ __align__(16) __half g_wotf[(size_t)DIM_ * GK];         // wo^T fp16
__device__ __align__(16) __half g_qf[(size_t)MROWS * DIM_];        // q fp16 (scaled 1/sqrt(128))
__device__ __align__(16) __half g_kf[(size_t)MROWS * KVDIM];       // k fp16
__device__ __align__(16) __half g_vtf[(size_t)B_SZ * KVDIM * T_SZ]; // [b*512+c][t] fp16
__device__ __align__(16) __half g_ath[(size_t)MROWS * DIM_];       // att fp16 single

// ================= helpers ===================================================
__device__ __forceinline__ uint32_t smem_u32(const void* p) {
    uint32_t a;
    asm("{ .reg .u64 t; cvta.to.shared.u64 t, %1; cvt.u32.u64 %0, t; }" : "=r"(a) : "l"(p));
    return a;
}
__device__ __forceinline__ void ldsm4(uint32_t (&r)[4], uint32_t addr) {
    asm volatile("ldmatrix.sync.aligned.m8n8.x4.shared.b16 {%0,%1,%2,%3}, [%4];"
                 : "=r"(r[0]), "=r"(r[1]), "=r"(r[2]), "=r"(r[3]) : "r"(addr));
}
__device__ __forceinline__ void mma16816h(float (&d)[4], const uint32_t (&a)[4],
                                          uint32_t b0, uint32_t b1) {
    asm volatile("mma.sync.aligned.m16n8k16.row.col.f32.f16.f16.f32 "
                 "{%0,%1,%2,%3}, {%4,%5,%6,%7}, {%8,%9}, {%0,%1,%2,%3};"
                 : "+f"(d[0]), "+f"(d[1]), "+f"(d[2]), "+f"(d[3])
                 : "r"(a[0]), "r"(a[1]), "r"(a[2]), "r"(a[3]), "r"(b0), "r"(b1));
}
#define CP_ASYNC16(sm, gm) \
    asm volatile("cp.async.cg.shared.global [%0], [%1], 16;" :: "r"(sm), "l"(gm) : "memory")
#define CP_COMMIT() asm volatile("cp.async.commit_group;" ::: "memory")
#define CP_WAIT(n)  asm volatile("cp.async.wait_group %0;" :: "n"(n) : "memory")

__device__ __forceinline__ uint32_t h2u(__half2 v) { return *reinterpret_cast<uint32_t*>(&v); }

// ================= conversion kernels ========================================
// fp32 -> fp16 single (flat)
__global__ void xhalf_kernel(const float* __restrict__ in, __half* __restrict__ out, int n4)
{
    int i = blockIdx.x * 256 + threadIdx.x;
    if (i >= n4) return;
    float4 v = ((const float4*)in)[i];
    ((uint32_t*)out)[2 * i]     = h2u(__floats2half2_rn(v.x, v.y));
    ((uint32_t*)out)[2 * i + 1] = h2u(__floats2half2_rn(v.z, v.w));
}

// in: [R,C] fp32 -> out: [C,R] fp16 single (transposed)
__global__ void thalf_kernel(const float* __restrict__ in, __half* __restrict__ out,
                             int R, int C)
{
    __shared__ float tile[32][33];
    const int bx = blockIdx.x << 5;
    const int by = blockIdx.y << 5;
    const int tx = threadIdx.x & 31, ty = threadIdx.x >> 5;
    #pragma unroll
    for (int r = ty; r < 32; r += 8)
        tile[r][tx] = in[(size_t)(by + r) * C + bx + tx];
    __syncthreads();
    #pragma unroll
    for (int r = ty; r < 32; r += 8)
        out[(size_t)(bx + r) * R + by + tx] = __float2half_rn(tile[tx][r]);
}

// ================= 1-pass fp16 GEMM core (3-stage cp.async) ==================
#define BK        32
#define NKB       (GK / BK)          // 64
#define TPITCH    80
#define TILE_BY   (128 * TPITCH)
#define GS_A      0
#define GS_B      TILE_BY
#define GSTAGE    (2 * TILE_BY)      // 20480
#define GEMM_SMEM (3 * GSTAGE)       // 61440

__device__ __forceinline__ void load_stage_g(
    const __half* __restrict__ Ab, const __half* __restrict__ Bb,
    int kof, uint32_t sbuf, int tid)
{
    #pragma unroll
    for (int i = 0; i < 2; i++) {
        const int c   = tid + (i << 8);
        const int row = c >> 2, q = c & 3;
        const size_t   go = (size_t)row * GK + kof + q * 8;
        const uint32_t so = row * TPITCH + q * 16;
        CP_ASYNC16(sbuf + GS_A + so, Ab + go);
        CP_ASYNC16(sbuf + GS_B + so, Bb + go);
    }
}

// Mainloop shared by qkv and o gemms; leaves fp32 accumulators in acc.
__device__ __forceinline__ void gemm_mainloop(
    const __half* __restrict__ Ab, const __half* __restrict__ Bb,
    uint32_t sbase, int tid, int lane, int wm, int wn, float (&acc)[2][8][4])
{
    const uint32_t a_row = wm * 32 + (lane & 15);
    const uint32_t a_col = (lane >> 4) << 4;
    const uint32_t b_rowb = wn * 64 + (lane & 7) + ((lane >> 4) << 3);
    const uint32_t b_col  = ((lane >> 3) & 1) << 4;

    load_stage_g(Ab, Bb, 0, sbase, tid);
    CP_COMMIT();
    load_stage_g(Ab, Bb, BK, sbase + GSTAGE, tid);
    CP_COMMIT();

    for (int blk = 0; blk < NKB; blk++) {
        const uint32_t buf = sbase + (uint32_t)(blk % 3) * GSTAGE;
        if (blk + 2 < NKB) {
            load_stage_g(Ab, Bb, (blk + 2) * BK, sbase + (uint32_t)((blk + 2) % 3) * GSTAGE, tid);
            CP_COMMIT();
            CP_WAIT(2);
        } else if (blk + 2 == NKB) {
            CP_WAIT(1);
        } else {
            CP_WAIT(0);
        }
        __syncthreads();

        #pragma unroll
        for (int ks = 0; ks < 2; ks++) {
            const uint32_t koff = ks * 32;
            uint32_t af[2][4];
            #pragma unroll
            for (int mi = 0; mi < 2; mi++)
                ldsm4(af[mi], buf + GS_A + (a_row + mi * 16) * TPITCH + koff + a_col);
            uint32_t bf[4][4];
            #pragma unroll
            for (int nq = 0; nq < 4; nq++)
                ldsm4(bf[nq], buf + GS_B + (b_rowb + nq * 16) * TPITCH + koff + b_col);
            #pragma unroll
            for (int mi = 0; mi < 2; mi++)
                #pragma unroll
                for (int nq = 0; nq < 4; nq++)
                    #pragma unroll
                    for (int hf = 0; hf < 2; hf++)
                        mma16816h(acc[mi][nq * 2 + hf], af[mi],
                                  bf[nq][hf * 2], bf[nq][hf * 2 + 1]);
        }
        __syncthreads();
    }
}

// ================= fused QKV gemm ============================================
// C[M, 3072] = x(fp16)[M,2048] @ [wq|wk|wv]^T(fp16) ;
// epilogue: q (rope * 1/sqrt(128)) fp16, k (rope) fp16, v -> V^T fp16 direct
__global__ __launch_bounds__(256, 2)
void qkv_gemm_kernel(const __half* __restrict__ A, const __half* __restrict__ B,
                     __half* __restrict__ Qf, __half* __restrict__ Kf,
                     __half* __restrict__ Vt,
                     const float* __restrict__ fc, const float* __restrict__ fs)
{
    extern __shared__ char smem[];
    const uint32_t sbase = smem_u32(smem);
    const int tid  = threadIdx.x;
    const int lane = tid & 31, wid = tid >> 5;
    const int wm   = wid & 3,  wn  = wid >> 2;
    const int row0 = blockIdx.y << 7, col0 = blockIdx.x << 7;

    float acc[2][8][4];
    #pragma unroll
    for (int mi = 0; mi < 2; mi++)
        #pragma unroll
        for (int ni = 0; ni < 8; ni++)
            #pragma unroll
            for (int e = 0; e < 4; e++) acc[mi][ni][e] = 0.f;

    gemm_mainloop(A + (size_t)row0 * GK, B + (size_t)col0 * GK,
                  sbase, tid, lane, wm, wn, acc);

    // ---- epilogue by region ----
    const int lr = lane >> 2;
    const int lc = (lane & 3) << 1;
    const int region = (col0 < DIM_) ? 0 : (col0 < DIM_ + KVDIM ? 1 : 2);
    const float qsc = 0.08838834764831845f;   // 1/sqrt(128)
    #pragma unroll
    for (int mi = 0; mi < 2; mi++) {
        #pragma unroll
        for (int ni = 0; ni < 8; ni++) {
            float* d = acc[mi][ni];
            const int r0  = row0 + wm * 32 + mi * 16 + lr;
            const int r1  = r0 + 8;
            const int col = col0 + wn * 64 + ni * 8 + lc;
            if (region != 2) {
                const int p = (col & (HDIM - 1)) >> 1;
                {
                    const int t = r0 & (T_SZ - 1);
                    const float cz = fc[t * (HDIM / 2) + p];
                    const float sz = fs[t * (HDIM / 2) + p];
                    const float xr = d[0], xi = d[1];
                    d[0] = xr * cz - xi * sz;
                    d[1] = xr * sz + xi * cz;
                }
                {
                    const int t = r1 & (T_SZ - 1);
                    const float cz = fc[t * (HDIM / 2) + p];
                    const float sz = fs[t * (HDIM / 2) + p];
                    const float xr = d[2], xi = d[3];
                    d[2] = xr * cz - xi * sz;
                    d[3] = xr * sz + xi * cz;
                }
            }
            if (region == 0) {
                *(uint32_t*)&Qf[(size_t)r0 * DIM_ + col] =
                    h2u(__floats2half2_rn(d[0] * qsc, d[1] * qsc));
                *(uint32_t*)&Qf[(size_t)r1 * DIM_ + col] =
                    h2u(__floats2half2_rn(d[2] * qsc, d[3] * qsc));
            } else if (region == 1) {
                const int ck = col - DIM_;
                *(uint32_t*)&Kf[(size_t)r0 * KVDIM + ck] = h2u(__floats2half2_rn(d[0], d[1]));
                *(uint32_t*)&Kf[(size_t)r1 * KVDIM + ck] = h2u(__floats2half2_rn(d[2], d[3]));
            } else {
                // v region: write directly transposed fp16 -> Vt[(b*512+c)][t]
                const int cv = col - DIM_ - KVDIM;
                const int b0 = r0 >> 11, t0 = r0 & (T_SZ - 1);   // T_SZ = 2048
                const int b1 = r1 >> 11, t1 = r1 & (T_SZ - 1);
                Vt[((size_t)(b0 * KVDIM + cv)     ) * T_SZ + t0] = __float2half_rn(d[0]);
                Vt[((size_t)(b0 * KVDIM + cv + 1) ) * T_SZ + t0] = __float2half_rn(d[1]);
                Vt[((size_t)(b1 * KVDIM + cv)     ) * T_SZ + t1] = __float2half_rn(d[2]);
                Vt[((size_t)(b1 * KVDIM + cv + 1) ) * T_SZ + t1] = __float2half_rn(d[3]);
            }
        }
    }
}

// ================= O projection: 1-pass fp16 GEMM ============================
__global__ __launch_bounds__(256, 2)
void o_gemm_kernel(const __half* __restrict__ A, const __half* __restrict__ B,
                   float* __restrict__ C)
{
    extern __shared__ char smem[];
    const uint32_t sbase = smem_u32(smem);
    const int tid  = threadIdx.x;
    const int lane = tid & 31, wid = tid >> 5;
    const int wm   = wid & 3,  wn  = wid >> 2;
    const int row0 = blockIdx.y << 7, col0 = blockIdx.x << 7;

    float acc[2][8][4];
    #pragma unroll
    for (int mi = 0; mi < 2; mi++)
        #pragma unroll
        for (int ni = 0; ni < 8; ni++)
            #pragma unroll
            for (int e = 0; e < 4; e++) acc[mi][ni][e] = 0.f;

    gemm_mainloop(A + (size_t)row0 * GK, B + (size_t)col0 * GK,
                  sbase, tid, lane, wm, wn, acc);

    const int lr = lane >> 2;
    const int lc = (lane & 3) << 1;
    #pragma unroll
    for (int mi = 0; mi < 2; mi++) {
        #pragma unroll
        for (int ni = 0; ni < 8; ni++) {
            float* d = acc[mi][ni];
            const int r0  = row0 + wm * 32 + mi * 16 + lr;
            const int r1  = r0 + 8;
            const int col = col0 + wn * 64 + ni * 8 + lc;
            *(float2*)(C + (size_t)r0 * DIM_ + col) = make_float2(d[0], d[1]);
            *(float2*)(C + (size_t)r1 * DIM_ + col) = make_float2(d[2], d[3]);
        }
    }
}

// ================= tensor-core flash attention (unchanged R16-passing) =======
// q-tile 128 (8 warps x 16 rows), k-tile 64. S single fp16 (scale in Q),
// PV single fp16, att out fp16.
#define QPITCH 272
#define VPITCH 144
#define SM_Q   0
#define SM_KV  (128 * QPITCH)          // 34816
#define OFF_K  0
#define OFF_V  (64 * QPITCH)           // 17408
#define KVBUF  (OFF_V + 128 * VPITCH)  // 35840
#define FLASH2_SMEM (SM_KV + 2 * KVBUF) // 106496

__device__ __forceinline__ void flash_load_kv(
    const __half* __restrict__ Kf, const __half* __restrict__ Vt,
    int b, int kvh, int kt, uint32_t buf, int tid)
{
    const char* gk = (const char*)(Kf + (size_t)(b * T_SZ + kt * 64) * KVDIM + kvh * HDIM);
    #pragma unroll
    for (int s = 0; s < 4; s++) {
        const int u = tid + s * 256;           // 64 rows x 16 chunks
        const int r = u >> 4, c = (u & 15) << 4;
        CP_ASYNC16(buf + OFF_K + r * QPITCH + c, gk + (size_t)r * (KVDIM * 2) + c);
    }
    const char* gv = (const char*)(Vt + ((size_t)(b * KVHEAD + kvh) * HDIM) * T_SZ + kt * 64);
    #pragma unroll
    for (int s = 0; s < 4; s++) {
        const int u = tid + s * 256;           // 128 rows x 8 chunks
        const int r = u >> 3, c = (u & 7) << 4;
        CP_ASYNC16(buf + OFF_V + r * VPITCH + c, gv + (size_t)r * (T_SZ * 2) + c);
    }
}

__global__ __launch_bounds__(256, 1)
void flash_mma_kernel(const __half* __restrict__ Qf, const __half* __restrict__ Kf,
                      const __half* __restrict__ Vt, __half* __restrict__ At)
{
    extern __shared__ char smem[];
    const uint32_t sbase = smem_u32(smem);
    const int tid = threadIdx.x, lane = tid & 31, w = tid >> 5;
    const int qt = (int)gridDim.x - 1 - (int)blockIdx.x;   // heavy tiles first
    const int bh = blockIdx.y, b = bh >> 4, h = bh & 15, kvh = h >> 2;
    const int qrow0 = b * T_SZ + qt * 128;
    const int nkt = 2 * qt + 2;

    {
        const char* gq = (const char*)(Qf + (size_t)qrow0 * DIM_ + h * HDIM);
        #pragma unroll
        for (int s = 0; s < 8; s++) {
            const int u = tid + s * 256;       // 128 rows x 16 chunks
            const int r = u >> 4, c = (u & 15) << 4;
            CP_ASYNC16(sbase + SM_Q + r * QPITCH + c, gq + (size_t)r * (DIM_ * 2) + c);
        }
    }
    flash_load_kv(Kf, Vt, b, kvh, 0, sbase + SM_KV, tid);
    CP_COMMIT();

    float sm0 = -1e30f, sm1 = -1e30f, sl0 = 0.f, sl1 = 0.f;
    float vacc[16][4];
    #pragma unroll
    for (int ni = 0; ni < 16; ni++)
        #pragma unroll
        for (int e = 0; e < 4; e++) vacc[ni][e] = 0.f;

    const int r0l = w * 16 + (lane >> 2);
    const int r1l = r0l + 8;
    const uint32_t a_addr0 = sbase + SM_Q + (w * 16 + (lane & 15)) * QPITCH + ((lane >> 4) << 4);
    const uint32_t b_roff  = ((lane & 7) + ((lane >> 4) << 3));
    const uint32_t b_coff  = ((lane >> 3) & 1) << 4;

    CP_WAIT(0);
    __syncthreads();

    for (int kt = 0; kt < nkt; kt++) {
        const uint32_t buf = sbase + SM_KV + (uint32_t)(kt & 1) * KVBUF;
        if (kt + 1 < nkt) {
            flash_load_kv(Kf, Vt, b, kvh, kt + 1,
                          sbase + SM_KV + (uint32_t)((kt + 1) & 1) * KVBUF, tid);
            CP_COMMIT();
        }

        // ---- S = Q K^T (single fp16) ----
        float sacc[8][4];
        #pragma unroll
        for (int nj = 0; nj < 8; nj++)
            #pragma unroll
            for (int e = 0; e < 4; e++) sacc[nj][e] = 0.f;

        #pragma unroll
        for (int ks = 0; ks < 8; ks++) {
            uint32_t q4[4];
            ldsm4(q4, a_addr0 + ks * 32);
            #pragma unroll
            for (int nq = 0; nq < 4; nq++) {
                uint32_t k4[4];
                ldsm4(k4, buf + OFF_K + (nq * 16 + b_roff) * QPITCH + ks * 32 + b_coff);
                mma16816h(sacc[nq * 2],     q4, k4[0], k4[1]);
                mma16816h(sacc[nq * 2 + 1], q4, k4[2], k4[3]);
            }
        }

        // ---- causal mask (diagonal k-tiles) ----
        if (kt >= 2 * qt) {
            const int coff = kt * 64 - qt * 128;
            #pragma unroll
            for (int nj = 0; nj < 8; nj++) {
                const int c0 = coff + nj * 8 + (lane & 3) * 2;
                if (c0     > r0l) sacc[nj][0] = -1e30f;
                if (c0 + 1 > r0l) sacc[nj][1] = -1e30f;
                if (c0     > r1l) sacc[nj][2] = -1e30f;
                if (c0 + 1 > r1l) sacc[nj][3] = -1e30f;
            }
        }

        // ---- online softmax (register stats, bfly over lane&3) ----
        float mx0 = -1e30f, mx1 = -1e30f;
        #pragma unroll
        for (int nj = 0; nj < 8; nj++) {
            mx0 = fmaxf(mx0, fmaxf(sacc[nj][0], sacc[nj][1]));
            mx1 = fmaxf(mx1, fmaxf(sacc[nj][2], sacc[nj][3]));
        }
        mx0 = fmaxf(mx0, __shfl_xor_sync(0xFFFFFFFFu, mx0, 1));
        mx0 = fmaxf(mx0, __shfl_xor_sync(0xFFFFFFFFu, mx0, 2));
        mx1 = fmaxf(mx1, __shfl_xor_sync(0xFFFFFFFFu, mx1, 1));
        mx1 = fmaxf(mx1, __shfl_xor_sync(0xFFFFFFFFu, mx1, 2));
        const float mn0 = fmaxf(sm0, mx0), mn1 = fmaxf(sm1, mx1);
        const float al0 = __expf(sm0 - mn0), al1 = __expf(sm1 - mn1);
        sm0 = mn0; sm1 = mn1;

        // P = exp(S - m) as half2 A-fragments
        uint32_t pa[4][4];
        float ls0 = 0.f, ls1 = 0.f;
        #pragma unroll
        for (int j = 0; j < 4; j++) {
            #pragma unroll
            for (int t = 0; t < 2; t++) {
                const int nj = 2 * j + t;
                const float p0 = __expf(sacc[nj][0] - mn0);
                const float p1 = __expf(sacc[nj][1] - mn0);
                const float p2 = __expf(sacc[nj][2] - mn1);
                const float p3 = __expf(sacc[nj][3] - mn1);
                ls0 += p0 + p1;
                ls1 += p2 + p3;
                pa[j][t * 2]     = h2u(__floats2half2_rn(p0, p1));
                pa[j][t * 2 + 1] = h2u(__floats2half2_rn(p2, p3));
            }
        }
        ls0 += __shfl_xor_sync(0xFFFFFFFFu, ls0, 1);
        ls0 += __shfl_xor_sync(0xFFFFFFFFu, ls0, 2);
        ls1 += __shfl_xor_sync(0xFFFFFFFFu, ls1, 1);
        ls1 += __shfl_xor_sync(0xFFFFFFFFu, ls1, 2);
        sl0 = sl0 * al0 + ls0;
        sl1 = sl1 * al1 + ls1;

        #pragma unroll
        for (int ni = 0; ni < 16; ni++) {
            vacc[ni][0] *= al0; vacc[ni][1] *= al0;
            vacc[ni][2] *= al1; vacc[ni][3] *= al1;
        }

        // ---- O += P V (single fp16; B = V^T fp16 [d][t]) ----
        #pragma unroll
        for (int j = 0; j < 4; j++) {
            #pragma unroll
            for (int nq = 0; nq < 8; nq++) {
                uint32_t v4[4];
                const uint32_t vaddr = buf + OFF_V + (nq * 16 + b_roff) * VPITCH + j * 32 + b_coff;
                ldsm4(v4, vaddr);
                mma16816h(vacc[nq * 2],     pa[j], v4[0], v4[1]);
                mma16816h(vacc[nq * 2 + 1], pa[j], v4[2], v4[3]);
            }
        }

        if (kt + 1 < nkt) CP_WAIT(0);
        __syncthreads();
    }

    // ---- epilogue: write att as fp16 single ----
    const float inv0 = 1.f / sl0, inv1 = 1.f / sl1;
    __half* a0 = At + (size_t)(qrow0 + r0l) * DIM_ + h * HDIM;
    __half* a1 = At + (size_t)(qrow0 + r1l) * DIM_ + h * HDIM;
    #pragma unroll
    for (int ni = 0; ni < 16; ni++) {
        const int col = ni * 8 + (lane & 3) * 2;
        *(uint32_t*)(a0 + col) = h2u(__floats2half2_rn(vacc[ni][0] * inv0, vacc[ni][1] * inv0));
        *(uint32_t*)(a1 + col) = h2u(__floats2half2_rn(vacc[ni][2] * inv1, vacc[ni][3] * inv1));
    }
}

// ================= launch ====================================================
extern "C" void kernel_launch(void* const* d_in, const int* in_sizes, int n_in,
                              void* d_out, int out_size)
{
    const float* x  = (const float*)d_in[0];
    const float* fc = (const float*)d_in[1];
    const float* fs = (const float*)d_in[2];
    const float* wq = (const float*)d_in[3];
    const float* wk = (const float*)d_in[4];
    const float* wv = (const float*)d_in[5];
    const float* wo = (const float*)d_in[6];
    float* out = (float*)d_out;

    __half *xf, *wtf, *wotf, *qf, *kf, *vtf, *ath;
    cudaGetSymbolAddress((void**)&xf,   g_xf);
    cudaGetSymbolAddress((void**)&wtf,  g_wtf);  cudaGetSymbolAddress((void**)&wotf, g_wotf);
    cudaGetSymbolAddress((void**)&qf,   g_qf);   cudaGetSymbolAddress((void**)&kf,   g_kf);
    cudaGetSymbolAddress((void**)&vtf,  g_vtf);  cudaGetSymbolAddress((void**)&ath,  g_ath);

    cudaFuncSetAttribute(qkv_gemm_kernel, cudaFuncAttributeMaxDynamicSharedMemorySize, GEMM_SMEM);
    cudaFuncSetAttribute(o_gemm_kernel,   cudaFuncAttributeMaxDynamicSharedMemorySize, GEMM_SMEM);
    cudaFuncSetAttribute(flash_mma_kernel, cudaFuncAttributeMaxDynamicSharedMemorySize, FLASH2_SMEM);

    const int n4x = MROWS * DIM_ / 4;

    // input conversions (x single fp16; weights single fp16, transposed)
    xhalf_kernel<<<n4x / 256, 256>>>(x, xf, n4x);
    thalf_kernel<<<dim3(DIM_  / 32, DIM_ / 32), 256>>>(wq, wtf, GK, DIM_);
    thalf_kernel<<<dim3(KVDIM / 32, DIM_ / 32), 256>>>(wk, wtf + (size_t)DIM_ * GK, GK, KVDIM);
    thalf_kernel<<<dim3(KVDIM / 32, DIM_ / 32), 256>>>(
        wv, wtf + (size_t)(DIM_ + KVDIM) * GK, GK, KVDIM);
    thalf_kernel<<<dim3(DIM_ / 32, DIM_ / 32), 256>>>(wo, wotf, GK, DIM_);

    // fused q|k|v projection (1-pass fp16; rope + fp16 epilogues, V^T fused)
    qkv_gemm_kernel<<<dim3(NTOT / 128, MROWS / 128), 256, GEMM_SMEM>>>(
        xf, wtf, qf, kf, vtf, fc, fs);

    // attention (S single fp16, PV single fp16; att fp16)
    flash_mma_kernel<<<dim3(T_SZ / 128, B_SZ * NHEAD), 256, FLASH2_SMEM>>>(qf, kf, vtf, ath);

    // output projection (1-pass fp16)
    o_gemm_kernel<<<dim3(DIM_ / 128, MROWS / 128), 256, GEMM_SMEM>>>(ath, wotf, out);
}